// round 1
// baseline (speedup 1.0000x reference)
#include <cuda_runtime.h>
#include <cstddef>

// ---------------------------------------------------------------------------
// Encoder: 12 x (QKV GEMM -> MHA -> proj+res -> LN1 -> MLP1(relu) -> MLP2+res -> LN2)
// B=2, S=2048, D=512, H=8, DH=64, DHID=1024, fp32.
// scale = 1/sqrt(D_model) = 1/sqrt(512).
// QKV column layout per token: head h occupies cols [h*192, h*192+192) as [q64|k64|v64].
// ---------------------------------------------------------------------------

#define NB    12
#define DMODEL 512
#define NH    8
#define DHEAD 64
#define DHID  1024
#define BATCH 2
#define SEQ   2048
#define ROWS  (BATCH * SEQ)      // 4096
#define CTXW  (3 * DMODEL)       // 1536
#define LN_EPS 1e-5f
#define ATTN_SCALE 0.044194173824159216f  // 1/sqrt(512)

// ------------------------- scratch (no allocation allowed) -----------------
__device__ float g_ctx [ROWS * CTXW];    // qkv activations
__device__ float g_attn[ROWS * DMODEL];  // attention output (head-interleaved)
__device__ float g_x   [ROWS * DMODEL];  // block input carry
__device__ float g_x1  [ROWS * DMODEL];  // after attn residual
__device__ float g_xn  [ROWS * DMODEL];  // LN1 output
__device__ float g_h   [ROWS * DHID];    // MLP hidden
__device__ float g_x2  [ROWS * DMODEL];  // after MLP residual

// ---------------------------------------------------------------------------
// SGEMM: C[M,N] = A[M,K] @ W[K,N] + bias[N] (+ res[M,N]) (relu?)
// 128x128 tile, BK=8, 256 threads, 8x8 micro-tile split as (4 + 4) rows/cols
// for conflict-free LDS.128.  M,N,K all multiples of 128/8 here.
// ---------------------------------------------------------------------------
template <bool RELU, bool RES>
__global__ void __launch_bounds__(256)
gemm128(const float* __restrict__ A, const float* __restrict__ W,
        const float* __restrict__ bias, const float* __restrict__ res,
        float* __restrict__ C, int M, int N, int K)
{
    __shared__ float As[8][128];   // [k][m]
    __shared__ float Ws[8][128];   // [k][n]

    const int tid  = threadIdx.x;
    const int brow = blockIdx.y * 128;
    const int bcol = blockIdx.x * 128;

    // loaders
    const int lar = tid >> 1;            // A row 0..127
    const int lak = (tid & 1) * 4;       // A k-offset {0,4}
    const int lwr = tid >> 5;            // W row 0..7
    const int lwc = (tid & 31) * 4;      // W col 0..124

    const float* Ap = A + (size_t)(brow + lar) * K + lak;
    const float* Wp = W + (size_t)lwr * N + bcol + lwc;

    const int ty = tid >> 4;             // 0..15
    const int tx = tid & 15;             // 0..15

    float acc[8][8];
#pragma unroll
    for (int i = 0; i < 8; i++)
#pragma unroll
        for (int j = 0; j < 8; j++) acc[i][j] = 0.f;

    for (int k0 = 0; k0 < K; k0 += 8) {
        float4 av = *(const float4*)(Ap + k0);
        float4 wv = *(const float4*)(Wp + (size_t)k0 * N);
        __syncthreads();
        As[lak + 0][lar] = av.x; As[lak + 1][lar] = av.y;
        As[lak + 2][lar] = av.z; As[lak + 3][lar] = av.w;
        *(float4*)&Ws[lwr][lwc] = wv;
        __syncthreads();
#pragma unroll
        for (int kk = 0; kk < 8; kk++) {
            float4 a0 = *(const float4*)&As[kk][ty * 4];
            float4 a1 = *(const float4*)&As[kk][64 + ty * 4];
            float4 b0 = *(const float4*)&Ws[kk][tx * 4];
            float4 b1 = *(const float4*)&Ws[kk][64 + tx * 4];
            float a[8] = {a0.x, a0.y, a0.z, a0.w, a1.x, a1.y, a1.z, a1.w};
            float b[8] = {b0.x, b0.y, b0.z, b0.w, b1.x, b1.y, b1.z, b1.w};
#pragma unroll
            for (int i = 0; i < 8; i++)
#pragma unroll
                for (int j = 0; j < 8; j++) acc[i][j] += a[i] * b[j];
        }
    }

    // epilogue: rows {brow+ty*4+i, brow+64+ty*4+i}, cols {bcol+tx*4+j, bcol+64+tx*4+j}
#pragma unroll
    for (int ih = 0; ih < 2; ih++) {
#pragma unroll
        for (int i = 0; i < 4; i++) {
            int row = brow + ih * 64 + ty * 4 + i;
#pragma unroll
            for (int jh = 0; jh < 2; jh++) {
                int col = bcol + jh * 64 + tx * 4;
                float4 bv = *(const float4*)(bias + col);
                float v0 = acc[ih * 4 + i][jh * 4 + 0] + bv.x;
                float v1 = acc[ih * 4 + i][jh * 4 + 1] + bv.y;
                float v2 = acc[ih * 4 + i][jh * 4 + 2] + bv.z;
                float v3 = acc[ih * 4 + i][jh * 4 + 3] + bv.w;
                if (RES) {
                    float4 rv = *(const float4*)(res + (size_t)row * N + col);
                    v0 += rv.x; v1 += rv.y; v2 += rv.z; v3 += rv.w;
                }
                if (RELU) {
                    v0 = fmaxf(v0, 0.f); v1 = fmaxf(v1, 0.f);
                    v2 = fmaxf(v2, 0.f); v3 = fmaxf(v3, 0.f);
                }
                float4 ov = {v0, v1, v2, v3};
                *(float4*)(C + (size_t)row * N + col) = ov;
            }
        }
    }
}

// ---------------------------------------------------------------------------
// Attention: per (batch, head), 64-query tiles, online softmax over 32 KV tiles.
// ctx layout: row = b*SEQ + s, head h cols: q = h*192+[0,64), k = +64, v = +128.
// out[row, h*64 + d].
// ---------------------------------------------------------------------------
#define ATTN_SMEM_FLOATS (64 * 64 * 3 + 64 * 68 + 3 * 64)
#define ATTN_SMEM_BYTES  (ATTN_SMEM_FLOATS * 4)

__global__ void __launch_bounds__(256)
attn_kernel(const float* __restrict__ ctx, float* __restrict__ out)
{
    extern __shared__ float sm[];
    float* Qs   = sm;                 // [d][i]  64x64
    float* Ks   = sm + 4096;          // [d][j]  64x64
    float* Vs   = sm + 8192;          // [j][c]  64x64
    float* Ss   = sm + 12288;         // [j][i]  64x68 (padded)
    float* m_s  = Ss + 64 * 68;       // [64]
    float* l_s  = m_s + 64;           // [64]
    float* sc_s = l_s + 64;           // [64]

    const int tid = threadIdx.x;
    const int tx = tid & 15, ty = tid >> 4;
    const int b = blockIdx.y >> 3, h = blockIdx.y & 7;
    const int qrow0 = b * SEQ + blockIdx.x * 64;
    const int krowb = b * SEQ;
    const int qc = h * 192, kc = qc + 64, vc = qc + 128;

    // load Q tile transposed: Qs[d][i]
    {
        int r  = tid >> 2;
        int dq = (tid & 3) * 4;
        const float* qp = ctx + (size_t)(qrow0 + r) * CTXW + qc + dq;
#pragma unroll
        for (int t = 0; t < 4; t++) {
            float4 v = *(const float4*)(qp + t * 16);
            int d = dq + t * 16;
            Qs[(d + 0) * 64 + r] = v.x; Qs[(d + 1) * 64 + r] = v.y;
            Qs[(d + 2) * 64 + r] = v.z; Qs[(d + 3) * 64 + r] = v.w;
        }
    }
    if (tid < 64) { m_s[tid] = -1e30f; l_s[tid] = 0.f; }

    float o[4][4] = {};

    for (int kt = 0; kt < 32; kt++) {
        const int krow0 = krowb + kt * 64;
        const int r  = tid >> 2;
        const int dq = (tid & 3) * 4;
        const float* kp = ctx + (size_t)(krow0 + r) * CTXW + kc + dq;
        const float* vp = ctx + (size_t)(krow0 + r) * CTXW + vc + dq;
        float4 kv[4], vv[4];
#pragma unroll
        for (int t = 0; t < 4; t++) {
            kv[t] = *(const float4*)(kp + t * 16);
            vv[t] = *(const float4*)(vp + t * 16);
        }
        __syncthreads();   // previous tile's PV done; Q stores done (iter 0)
#pragma unroll
        for (int t = 0; t < 4; t++) {
            int d = dq + t * 16;
            Ks[(d + 0) * 64 + r] = kv[t].x; Ks[(d + 1) * 64 + r] = kv[t].y;
            Ks[(d + 2) * 64 + r] = kv[t].z; Ks[(d + 3) * 64 + r] = kv[t].w;
            *(float4*)&Vs[r * 64 + d] = vv[t];
        }
        __syncthreads();

        // S tile: s[i][j] = sum_d Q[i][d] * K[j][d]
        float s[4][4] = {};
#pragma unroll
        for (int kk = 0; kk < 64; kk++) {
            float4 av = *(const float4*)&Qs[kk * 64 + ty * 4];
            float4 bv = *(const float4*)&Ks[kk * 64 + tx * 4];
            float a[4] = {av.x, av.y, av.z, av.w};
            float bb[4] = {bv.x, bv.y, bv.z, bv.w};
#pragma unroll
            for (int i = 0; i < 4; i++)
#pragma unroll
                for (int j = 0; j < 4; j++) s[i][j] += a[i] * bb[j];
        }
#pragma unroll
        for (int i = 0; i < 4; i++)
#pragma unroll
            for (int j = 0; j < 4; j++)
                Ss[(tx * 4 + j) * 68 + ty * 4 + i] = s[i][j] * ATTN_SCALE;
        __syncthreads();

        // online softmax: threads 4r+q own row r, each 16 keys
        {
            int rr = tid >> 2, q = tid & 3;
            float mx = -1e30f;
#pragma unroll
            for (int e = 0; e < 16; e++)
                mx = fmaxf(mx, Ss[(q * 16 + e) * 68 + rr]);
            mx = fmaxf(mx, __shfl_xor_sync(0xffffffffu, mx, 1));
            mx = fmaxf(mx, __shfl_xor_sync(0xffffffffu, mx, 2));
            float m_old = m_s[rr];
            float m_new = fmaxf(m_old, mx);
            float sum = 0.f;
#pragma unroll
            for (int e = 0; e < 16; e++) {
                int j = q * 16 + e;
                float p = __expf(Ss[j * 68 + rr] - m_new);
                Ss[j * 68 + rr] = p;
                sum += p;
            }
            sum += __shfl_xor_sync(0xffffffffu, sum, 1);
            sum += __shfl_xor_sync(0xffffffffu, sum, 2);
            if (q == 0) {
                float cf = __expf(m_old - m_new);
                sc_s[rr] = cf;
                l_s[rr] = l_s[rr] * cf + sum;
                m_s[rr] = m_new;
            }
        }
        __syncthreads();

        // rescale O, accumulate P @ V
        {
            float cf[4];
#pragma unroll
            for (int i = 0; i < 4; i++) cf[i] = sc_s[ty * 4 + i];
#pragma unroll
            for (int i = 0; i < 4; i++)
#pragma unroll
                for (int j = 0; j < 4; j++) o[i][j] *= cf[i];
#pragma unroll
            for (int kk = 0; kk < 64; kk++) {
                float4 pv = *(const float4*)&Ss[kk * 68 + ty * 4];
                float4 vv2 = *(const float4*)&Vs[kk * 64 + tx * 4];
                float p[4] = {pv.x, pv.y, pv.z, pv.w};
                float v[4] = {vv2.x, vv2.y, vv2.z, vv2.w};
#pragma unroll
                for (int i = 0; i < 4; i++)
#pragma unroll
                    for (int j = 0; j < 4; j++) o[i][j] += p[i] * v[j];
            }
        }
    }

    // epilogue
#pragma unroll
    for (int i = 0; i < 4; i++) {
        int r = ty * 4 + i;
        float inv = 1.f / l_s[r];
        size_t row = (size_t)(qrow0 + r);
        float4 ov = {o[i][0] * inv, o[i][1] * inv, o[i][2] * inv, o[i][3] * inv};
        *(float4*)(out + row * DMODEL + h * 64 + tx * 4) = ov;
    }
}

// ---------------------------------------------------------------------------
// LayerNorm over rows of 512. One block (128 threads, 4 elems each) per row.
// Two-pass for accuracy.
// ---------------------------------------------------------------------------
__global__ void __launch_bounds__(128)
ln_kernel(const float* __restrict__ x, const float* __restrict__ g,
          const float* __restrict__ bta, float* __restrict__ y)
{
    __shared__ float sbuf[4];
    const int row = blockIdx.x;
    const int tid = threadIdx.x;
    const float* xr = x + (size_t)row * DMODEL;
    float4 v = *(const float4*)(xr + tid * 4);

    float s = v.x + v.y + v.z + v.w;
#pragma unroll
    for (int off = 16; off > 0; off >>= 1) s += __shfl_xor_sync(0xffffffffu, s, off);
    if ((tid & 31) == 0) sbuf[tid >> 5] = s;
    __syncthreads();
    float mean = (sbuf[0] + sbuf[1] + sbuf[2] + sbuf[3]) * (1.f / 512.f);

    float dx = v.x - mean, dy = v.y - mean, dz = v.z - mean, dw = v.w - mean;
    float s2 = dx * dx + dy * dy + dz * dz + dw * dw;
#pragma unroll
    for (int off = 16; off > 0; off >>= 1) s2 += __shfl_xor_sync(0xffffffffu, s2, off);
    __syncthreads();
    if ((tid & 31) == 0) sbuf[tid >> 5] = s2;
    __syncthreads();
    float var = (sbuf[0] + sbuf[1] + sbuf[2] + sbuf[3]) * (1.f / 512.f);
    float inv = rsqrtf(var + LN_EPS);

    float4 gg = *(const float4*)(g + tid * 4);
    float4 bb = *(const float4*)(bta + tid * 4);
    float4 o;
    o.x = dx * inv * gg.x + bb.x;
    o.y = dy * inv * gg.y + bb.y;
    o.z = dz * inv * gg.z + bb.z;
    o.w = dw * inv * gg.w + bb.w;
    *(float4*)(y + (size_t)row * DMODEL + tid * 4) = o;
}

// ---------------------------------------------------------------------------
extern "C" void kernel_launch(void* const* d_in, const int* in_sizes, int n_in,
                              void* d_out, int out_size)
{
    const float* X     = (const float*)d_in[0];
    const float* qkv_w = (const float*)d_in[1];
    const float* qkv_b = (const float*)d_in[2];
    const float* fc_w  = (const float*)d_in[3];
    const float* fc_b  = (const float*)d_in[4];
    const float* ln1_g = (const float*)d_in[5];
    const float* ln1_b = (const float*)d_in[6];
    const float* w1    = (const float*)d_in[7];
    const float* b1    = (const float*)d_in[8];
    const float* w2    = (const float*)d_in[9];
    const float* b2    = (const float*)d_in[10];
    const float* ln2_g = (const float*)d_in[11];
    const float* ln2_b = (const float*)d_in[12];
    float* out = (float*)d_out;

    float *ctx, *attn, *x, *x1, *xn, *hbuf, *x2;
    cudaGetSymbolAddress((void**)&ctx,  g_ctx);
    cudaGetSymbolAddress((void**)&attn, g_attn);
    cudaGetSymbolAddress((void**)&x,    g_x);
    cudaGetSymbolAddress((void**)&x1,   g_x1);
    cudaGetSymbolAddress((void**)&xn,   g_xn);
    cudaGetSymbolAddress((void**)&hbuf, g_h);
    cudaGetSymbolAddress((void**)&x2,   g_x2);

    cudaFuncSetAttribute(attn_kernel, cudaFuncAttributeMaxDynamicSharedMemorySize,
                         ATTN_SMEM_BYTES);

    const float* xcur = X;  // block input (read-only); first block reads harness input

    for (int i = 0; i < NB; i++) {
        // 1) ctx = xcur @ qkv_w[i] + qkv_b[i]        [4096,1536]
        gemm128<false, false><<<dim3(CTXW / 128, ROWS / 128), 256>>>(
            xcur, qkv_w + (size_t)i * DMODEL * CTXW, qkv_b + (size_t)i * CTXW,
            nullptr, ctx, ROWS, CTXW, DMODEL);

        // 2) attention
        attn_kernel<<<dim3(SEQ / 64, BATCH * NH), 256, ATTN_SMEM_BYTES>>>(ctx, attn);

        // 3) x1 = attn @ fc_w[i] + fc_b[i] + xcur
        gemm128<false, true><<<dim3(DMODEL / 128, ROWS / 128), 256>>>(
            attn, fc_w + (size_t)i * DMODEL * DMODEL, fc_b + (size_t)i * DMODEL,
            xcur, x1, ROWS, DMODEL, DMODEL);

        // 4) xn = LN1(x1)
        ln_kernel<<<ROWS, 128>>>(x1, ln1_g + (size_t)i * DMODEL,
                                 ln1_b + (size_t)i * DMODEL, xn);

        // 5) h = relu(xn @ w1[i] + b1[i])            [4096,1024]
        gemm128<true, false><<<dim3(DHID / 128, ROWS / 128), 256>>>(
            xn, w1 + (size_t)i * DMODEL * DHID, b1 + (size_t)i * DHID,
            nullptr, hbuf, ROWS, DHID, DMODEL);

        // 6) x2 = h @ w2[i] + b2[i] + x1
        gemm128<false, true><<<dim3(DMODEL / 128, ROWS / 128), 256>>>(
            hbuf, w2 + (size_t)i * DHID * DMODEL, b2 + (size_t)i * DMODEL,
            x1, x2, ROWS, DMODEL, DHID);

        // 7) next x = LN2(x2); last block writes d_out
        float* dst = (i == NB - 1) ? out : x;
        ln_kernel<<<ROWS, 128>>>(x2, ln2_g + (size_t)i * DMODEL,
                                 ln2_b + (size_t)i * DMODEL, dst);
        xcur = dst;
    }
}

// round 4
// speedup vs baseline: 2.2176x; 2.2176x over previous
#include <cuda_runtime.h>
#include <cuda_bf16.h>
#include <cstdint>
#include <cstddef>

// ---------------------------------------------------------------------------
// Encoder: 12 x (QKV -> MHA -> proj+res -> LN1 -> MLP(relu) -> +res -> LN2)
// B=2, S=2048, D=512, H=8, DH=64, DHID=1024, fp32 in/out.
// All matmuls on mma.sync bf16 (HMMA) with hi/lo split (3 MMAs) ~ fp32 acc.
// NOTE: harness compiles to compute_100 (non-'a') => no tcgen05/TMA allowed.
// ---------------------------------------------------------------------------

#define NB     12
#define DMODEL 512
#define NH     8
#define DHEAD  64
#define DHID   1024
#define BATCH  2
#define SEQ    2048
#define ROWS   (BATCH * SEQ)     // 4096
#define CTXW   (3 * DMODEL)      // 1536
#define LN_EPS 1e-5f
#define ATTN_SCALE 0.044194173824159216f  // 1/sqrt(512)

// ----------------------------- PTX helpers ---------------------------------
__device__ __forceinline__ uint32_t smem_u32(const void* p) {
    uint32_t a;
    asm("{ .reg .u64 t; cvta.to.shared.u64 t, %1; cvt.u32.u64 %0, t; }"
        : "=r"(a) : "l"(p));
    return a;
}
__device__ __forceinline__ void ldsm_x4(uint32_t* r, uint32_t a) {
    asm volatile("ldmatrix.sync.aligned.m8n8.x4.shared.b16 {%0,%1,%2,%3}, [%4];"
        : "=r"(r[0]), "=r"(r[1]), "=r"(r[2]), "=r"(r[3]) : "r"(a));
}
__device__ __forceinline__ void ldsm_x2t(uint32_t* r, uint32_t a) {
    asm volatile("ldmatrix.sync.aligned.m8n8.x2.trans.shared.b16 {%0,%1}, [%2];"
        : "=r"(r[0]), "=r"(r[1]) : "r"(a));
}
__device__ __forceinline__ void mma_bf16(float* c, const uint32_t* a, const uint32_t* b) {
    asm volatile("mma.sync.aligned.m16n8k16.row.col.f32.bf16.bf16.f32 "
        "{%0,%1,%2,%3}, {%4,%5,%6,%7}, {%8,%9}, {%0,%1,%2,%3};"
        : "+f"(c[0]), "+f"(c[1]), "+f"(c[2]), "+f"(c[3])
        : "r"(a[0]), "r"(a[1]), "r"(a[2]), "r"(a[3]), "r"(b[0]), "r"(b[1]));
}
__device__ __forceinline__ void split2(float v, __nv_bfloat16& h, __nv_bfloat16& l) {
    h = __float2bfloat16(v);
    l = __float2bfloat16(v - __bfloat162float(h));
}

// ------------------------- scratch (no allocation) -------------------------
__device__ __nv_bfloat16 g_ctx_hi[ROWS * CTXW];
__device__ __nv_bfloat16 g_ctx_lo[ROWS * CTXW];
__device__ __nv_bfloat16 g_attn_hi[ROWS * DMODEL];
__device__ __nv_bfloat16 g_attn_lo[ROWS * DMODEL];
__device__ float         g_x   [ROWS * DMODEL];        // fp32 carry
__device__ __nv_bfloat16 g_x_hi[ROWS * DMODEL];
__device__ __nv_bfloat16 g_x_lo[ROWS * DMODEL];
__device__ float         g_x1  [ROWS * DMODEL];
__device__ __nv_bfloat16 g_xn_hi[ROWS * DMODEL];
__device__ __nv_bfloat16 g_xn_lo[ROWS * DMODEL];
__device__ __nv_bfloat16 g_h_hi[ROWS * DHID];
__device__ __nv_bfloat16 g_h_lo[ROWS * DHID];
__device__ float         g_x2  [ROWS * DMODEL];
__device__ __nv_bfloat16 g_qkvT_hi[CTXW * DMODEL],  g_qkvT_lo[CTXW * DMODEL];
__device__ __nv_bfloat16 g_fcT_hi [DMODEL * DMODEL], g_fcT_lo[DMODEL * DMODEL];
__device__ __nv_bfloat16 g_w1T_hi [DHID * DMODEL],   g_w1T_lo[DHID * DMODEL];
__device__ __nv_bfloat16 g_w2T_hi [DMODEL * DHID],   g_w2T_lo[DMODEL * DHID];

// ---------------------------------------------------------------------------
// mma GEMM: C[M,N] = A[M,K] @ W[K,N] (+bias)(+res)(relu)
// A: bf16 hi/lo [M][K]; W transposed: bf16 hi/lo [N][K].
// 128x128 tile, BK=32, 8 warps (warp tile 32x64), smem row stride 40 b16.
// ---------------------------------------------------------------------------
#define GS 40   // smem row stride in bf16 (80 bytes -> conflict-free ldmatrix)

template <bool RELU, bool RES, bool WF32, bool WHILO>
__global__ void __launch_bounds__(256)
gemm_mma(const __nv_bfloat16* __restrict__ Ahi, const __nv_bfloat16* __restrict__ Alo,
         const __nv_bfloat16* __restrict__ Bhi, const __nv_bfloat16* __restrict__ Blo,
         const float* __restrict__ bias, const float* __restrict__ res,
         float* __restrict__ Cf, __nv_bfloat16* __restrict__ Chi,
         __nv_bfloat16* __restrict__ Clo, int N, int K)
{
    __shared__ __nv_bfloat16 sAh[128 * GS], sAl[128 * GS];
    __shared__ __nv_bfloat16 sBh[128 * GS], sBl[128 * GS];

    const int tid  = threadIdx.x;
    const int lane = tid & 31, wid = tid >> 5;
    const int g = lane >> 3, rq = lane & 7;
    const int brow = blockIdx.y * 128, bcol = blockIdx.x * 128;
    const int m0 = (wid & 3) * 32, n0 = (wid >> 2) * 64;

    const uint32_t bAh = smem_u32(sAh), bAl = smem_u32(sAl);
    const uint32_t bBh = smem_u32(sBh), bBl = smem_u32(sBl);

    float acc[2][8][4];
#pragma unroll
    for (int mt = 0; mt < 2; mt++)
#pragma unroll
        for (int nt = 0; nt < 8; nt++)
#pragma unroll
            for (int e = 0; e < 4; e++) acc[mt][nt][e] = 0.f;

    const int NC = K >> 5;
    for (int c = 0; c < NC; c++) {
        uint4 rAh[2], rAl[2], rBh[2], rBl[2];
#pragma unroll
        for (int t = 0; t < 2; t++) {
            int idx = tid + t * 256;
            int row = idx >> 2, seg = idx & 3;
            size_t ga = (size_t)(brow + row) * K + c * 32 + seg * 8;
            size_t gb = (size_t)(bcol + row) * K + c * 32 + seg * 8;
            rAh[t] = *(const uint4*)(Ahi + ga);
            rAl[t] = *(const uint4*)(Alo + ga);
            rBh[t] = *(const uint4*)(Bhi + gb);
            rBl[t] = *(const uint4*)(Blo + gb);
        }
        __syncthreads();
#pragma unroll
        for (int t = 0; t < 2; t++) {
            int idx = tid + t * 256;
            int row = idx >> 2, seg = idx & 3;
            int so = row * GS + seg * 8;
            *(uint4*)(sAh + so) = rAh[t];
            *(uint4*)(sAl + so) = rAl[t];
            *(uint4*)(sBh + so) = rBh[t];
            *(uint4*)(sBl + so) = rBl[t];
        }
        __syncthreads();
#pragma unroll
        for (int ks = 0; ks < 2; ks++) {
            const int k0 = ks * 16;
            uint32_t ah[2][4], al[2][4];
#pragma unroll
            for (int mt = 0; mt < 2; mt++) {
                uint32_t off = (uint32_t)(m0 + mt * 16 + (g & 1) * 8 + rq) * (GS * 2)
                             + (k0 + (g >> 1) * 8) * 2;
                ldsm_x4(ah[mt], bAh + off);
                ldsm_x4(al[mt], bAl + off);
            }
            uint32_t bh[8][2], bl[8][2];
#pragma unroll
            for (int np = 0; np < 4; np++) {
                uint32_t off = (uint32_t)(n0 + np * 16 + (g >> 1) * 8 + rq) * (GS * 2)
                             + (k0 + (g & 1) * 8) * 2;
                uint32_t tmp[4];
                ldsm_x4(tmp, bBh + off);
                bh[2 * np][0] = tmp[0]; bh[2 * np][1] = tmp[1];
                bh[2 * np + 1][0] = tmp[2]; bh[2 * np + 1][1] = tmp[3];
                ldsm_x4(tmp, bBl + off);
                bl[2 * np][0] = tmp[0]; bl[2 * np][1] = tmp[1];
                bl[2 * np + 1][0] = tmp[2]; bl[2 * np + 1][1] = tmp[3];
            }
#pragma unroll
            for (int mt = 0; mt < 2; mt++)
#pragma unroll
                for (int nt = 0; nt < 8; nt++) {
                    mma_bf16(acc[mt][nt], ah[mt], bh[nt]);
                    mma_bf16(acc[mt][nt], ah[mt], bl[nt]);
                    mma_bf16(acc[mt][nt], al[mt], bh[nt]);
                }
        }
    }

    // epilogue
#pragma unroll
    for (int mt = 0; mt < 2; mt++)
#pragma unroll
        for (int nt = 0; nt < 8; nt++) {
            const int row0 = brow + m0 + mt * 16 + (lane >> 2);
            const int col  = bcol + n0 + nt * 8 + (lane & 3) * 2;
            float2 bv = *(const float2*)(bias + col);
#pragma unroll
            for (int hh = 0; hh < 2; hh++) {
                const int row = row0 + hh * 8;
                float v0 = acc[mt][nt][2 * hh]     + bv.x;
                float v1 = acc[mt][nt][2 * hh + 1] + bv.y;
                if (RES) {
                    float2 rv = *(const float2*)(res + (size_t)row * N + col);
                    v0 += rv.x; v1 += rv.y;
                }
                if (RELU) { v0 = fmaxf(v0, 0.f); v1 = fmaxf(v1, 0.f); }
                if (WF32) {
                    float2 o = {v0, v1};
                    *(float2*)(Cf + (size_t)row * N + col) = o;
                }
                if (WHILO) {
                    __nv_bfloat162 hp, lp;
                    split2(v0, hp.x, lp.x);
                    split2(v1, hp.y, lp.y);
                    *(__nv_bfloat162*)(Chi + (size_t)row * N + col) = hp;
                    *(__nv_bfloat162*)(Clo + (size_t)row * N + col) = lp;
                }
            }
        }
}

// ---------------------------------------------------------------------------
// Weight transpose + bf16 hi/lo split: in[K][N] fp32 -> out_hi/lo [N][K] bf16
// ---------------------------------------------------------------------------
__global__ void __launch_bounds__(256)
transpose_split(const float* __restrict__ in, __nv_bfloat16* __restrict__ oh,
                __nv_bfloat16* __restrict__ ol, int K, int N)
{
    __shared__ float t[32][33];
    const int n0 = blockIdx.x * 32, k0 = blockIdx.y * 32;
    const int tx = threadIdx.x, ty = threadIdx.y;   // 32 x 8
#pragma unroll
    for (int i = 0; i < 32; i += 8)
        t[ty + i][tx] = in[(size_t)(k0 + ty + i) * N + n0 + tx];
    __syncthreads();
#pragma unroll
    for (int i = 0; i < 32; i += 8) {
        float v = t[tx][ty + i];
        size_t o = (size_t)(n0 + ty + i) * K + k0 + tx;
        __nv_bfloat16 h, l;
        split2(v, h, l);
        oh[o] = h; ol[o] = l;
    }
}

__global__ void __launch_bounds__(256)
split_hilo(const float* __restrict__ x, __nv_bfloat16* __restrict__ h,
           __nv_bfloat16* __restrict__ l, int n)
{
    int i = blockIdx.x * 256 + threadIdx.x;
    if (i < n) {
        __nv_bfloat16 hv, lv;
        split2(x[i], hv, lv);
        h[i] = hv; l[i] = lv;
    }
}

// ---------------------------------------------------------------------------
// Attention: per (batch, head), 64-query tile, 32 KV tiles, online softmax.
// QK^T and P.V via mma.sync bf16 hi/lo; softmax SIMT in smem (fp32).
// ctx hi/lo layout: row = b*SEQ + s; head h: q = h*192+[0,64), k = +64, v = +128.
// ---------------------------------------------------------------------------
#define AST 72                    // bf16 smem row stride (144B, conflict-free)
#define A_TILE (64 * AST)         // bf16 elems per matrix
#define ATTN_SMEM_BYTES (8 * A_TILE * 2 + (64 * 68 + 3 * 64) * 4)  // 91904

__global__ void __launch_bounds__(256)
attn_kernel(const __nv_bfloat16* __restrict__ cxh, const __nv_bfloat16* __restrict__ cxl,
            __nv_bfloat16* __restrict__ ohi, __nv_bfloat16* __restrict__ olo)
{
    extern __shared__ char smc[];
    __nv_bfloat16* Qh = (__nv_bfloat16*)smc;
    __nv_bfloat16* Ql = Qh + A_TILE;
    __nv_bfloat16* Kh = Ql + A_TILE;
    __nv_bfloat16* Kl = Kh + A_TILE;
    __nv_bfloat16* Vh = Kl + A_TILE;
    __nv_bfloat16* Vl = Vh + A_TILE;
    __nv_bfloat16* Ph = Vl + A_TILE;
    __nv_bfloat16* Pl = Ph + A_TILE;
    float* S    = (float*)(Pl + A_TILE);     // [64][68]
    float* m_s  = S + 64 * 68;
    float* l_s  = m_s + 64;
    float* sc_s = l_s + 64;

    const int tid  = threadIdx.x;
    const int lane = tid & 31, wid = tid >> 5;
    const int g = lane >> 3, rq = lane & 7;
    const int b = blockIdx.y >> 3, h = blockIdx.y & 7;
    const int qrow0 = b * SEQ + blockIdx.x * 64;
    const int krowb = b * SEQ;
    const int qc = h * 192, kc = qc + 64, vc = qc + 128;

    const uint32_t bQh = smem_u32(Qh), bQl = smem_u32(Ql);
    const uint32_t bKh = smem_u32(Kh), bKl = smem_u32(Kl);
    const uint32_t bVh = smem_u32(Vh), bVl = smem_u32(Vl);
    const uint32_t bPh = smem_u32(Ph), bPl = smem_u32(Pl);

    const int m0  = (wid & 3) * 16;       // warp's query rows
    const int n0h = (wid >> 2) * 32;      // warp's key/dh column half

    // load Q tile (64 x 64 bf16 hi/lo)
#pragma unroll
    for (int t = 0; t < 2; t++) {
        int idx = tid + t * 256;
        int row = idx >> 3, seg = idx & 7;
        size_t go = (size_t)(qrow0 + row) * CTXW + qc + seg * 8;
        int so = row * AST + seg * 8;
        *(uint4*)(Qh + so) = *(const uint4*)(cxh + go);
        *(uint4*)(Ql + so) = *(const uint4*)(cxl + go);
    }
    if (tid < 64) { m_s[tid] = -1e30f; l_s[tid] = 0.f; }

    float oacc[4][4];
#pragma unroll
    for (int nt = 0; nt < 4; nt++)
#pragma unroll
        for (int e = 0; e < 4; e++) oacc[nt][e] = 0.f;

    for (int kt = 0; kt < 32; kt++) {
        const int krow0 = krowb + kt * 64;
        // stage K/V loads in regs (overlap with prev PV)
        uint4 rkh[2], rkl[2], rvh[2], rvl[2];
#pragma unroll
        for (int t = 0; t < 2; t++) {
            int idx = tid + t * 256;
            int row = idx >> 3, seg = idx & 7;
            size_t gk = (size_t)(krow0 + row) * CTXW + kc + seg * 8;
            size_t gv = (size_t)(krow0 + row) * CTXW + vc + seg * 8;
            rkh[t] = *(const uint4*)(cxh + gk);
            rkl[t] = *(const uint4*)(cxl + gk);
            rvh[t] = *(const uint4*)(cxh + gv);
            rvl[t] = *(const uint4*)(cxl + gv);
        }
        __syncthreads();   // prev PV done reading Ph/Vh (and Q stores on kt=0)
#pragma unroll
        for (int t = 0; t < 2; t++) {
            int idx = tid + t * 256;
            int row = idx >> 3, seg = idx & 7;
            int so = row * AST + seg * 8;
            *(uint4*)(Kh + so) = rkh[t];
            *(uint4*)(Kl + so) = rkl[t];
            *(uint4*)(Vh + so) = rvh[t];
            *(uint4*)(Vl + so) = rvl[t];
        }
        __syncthreads();

        // ---- S = Q @ K^T (hi/lo, 3 mma) ----
        {
            float sacc[4][4];
#pragma unroll
            for (int nt = 0; nt < 4; nt++)
#pragma unroll
                for (int e = 0; e < 4; e++) sacc[nt][e] = 0.f;
#pragma unroll
            for (int ks = 0; ks < 4; ks++) {
                const int k0 = ks * 16;
                uint32_t aq_h[4], aq_l[4];
                uint32_t offA = (uint32_t)(m0 + (g & 1) * 8 + rq) * (AST * 2)
                              + (k0 + (g >> 1) * 8) * 2;
                ldsm_x4(aq_h, bQh + offA);
                ldsm_x4(aq_l, bQl + offA);
                uint32_t bk_h[4][2], bk_l[4][2];
#pragma unroll
                for (int np = 0; np < 2; np++) {
                    uint32_t offB = (uint32_t)(n0h + np * 16 + (g >> 1) * 8 + rq) * (AST * 2)
                                  + (k0 + (g & 1) * 8) * 2;
                    uint32_t tmp[4];
                    ldsm_x4(tmp, bKh + offB);
                    bk_h[2 * np][0] = tmp[0]; bk_h[2 * np][1] = tmp[1];
                    bk_h[2 * np + 1][0] = tmp[2]; bk_h[2 * np + 1][1] = tmp[3];
                    ldsm_x4(tmp, bKl + offB);
                    bk_l[2 * np][0] = tmp[0]; bk_l[2 * np][1] = tmp[1];
                    bk_l[2 * np + 1][0] = tmp[2]; bk_l[2 * np + 1][1] = tmp[3];
                }
#pragma unroll
                for (int nt = 0; nt < 4; nt++) {
                    mma_bf16(sacc[nt], aq_h, bk_h[nt]);
                    mma_bf16(sacc[nt], aq_h, bk_l[nt]);
                    mma_bf16(sacc[nt], aq_l, bk_h[nt]);
                }
            }
            // store scaled S
#pragma unroll
            for (int nt = 0; nt < 4; nt++) {
                const int row0 = m0 + (lane >> 2);
                const int col  = n0h + nt * 8 + (lane & 3) * 2;
                S[row0 * 68 + col]       = sacc[nt][0] * ATTN_SCALE;
                S[row0 * 68 + col + 1]   = sacc[nt][1] * ATTN_SCALE;
                S[(row0 + 8) * 68 + col]     = sacc[nt][2] * ATTN_SCALE;
                S[(row0 + 8) * 68 + col + 1] = sacc[nt][3] * ATTN_SCALE;
            }
        }
        __syncthreads();

        // ---- online softmax (SIMT), writes P hi/lo ----
        {
            const int rr = tid >> 2, q = tid & 3;
            const float* srow = S + rr * 68 + q * 16;
            float mx = -1e30f;
#pragma unroll
            for (int e = 0; e < 16; e++) mx = fmaxf(mx, srow[e]);
            mx = fmaxf(mx, __shfl_xor_sync(0xffffffffu, mx, 1));
            mx = fmaxf(mx, __shfl_xor_sync(0xffffffffu, mx, 2));
            float m_old = m_s[rr];
            float m_new = fmaxf(m_old, mx);
            float p[16];
            float sum = 0.f;
#pragma unroll
            for (int e = 0; e < 16; e++) { p[e] = __expf(srow[e] - m_new); sum += p[e]; }
            sum += __shfl_xor_sync(0xffffffffu, sum, 1);
            sum += __shfl_xor_sync(0xffffffffu, sum, 2);
            if (q == 0) {
                float cf = __expf(m_old - m_new);
                sc_s[rr] = cf;
                l_s[rr] = l_s[rr] * cf + sum;
                m_s[rr] = m_new;
            }
            __nv_bfloat16* ph = Ph + rr * AST + q * 16;
            __nv_bfloat16* pl = Pl + rr * AST + q * 16;
#pragma unroll
            for (int e = 0; e < 16; e++) {
                __nv_bfloat16 hv, lv;
                split2(p[e], hv, lv);
                ph[e] = hv; pl[e] = lv;
            }
        }
        __syncthreads();

        // ---- O = O*cf + P @ V (hi/lo, 3 mma; V via ldmatrix.trans) ----
        {
            const float cf0 = sc_s[m0 + (lane >> 2)];
            const float cf1 = sc_s[m0 + 8 + (lane >> 2)];
#pragma unroll
            for (int nt = 0; nt < 4; nt++) {
                oacc[nt][0] *= cf0; oacc[nt][1] *= cf0;
                oacc[nt][2] *= cf1; oacc[nt][3] *= cf1;
            }
#pragma unroll
            for (int ks = 0; ks < 4; ks++) {
                const int k0 = ks * 16;
                uint32_t ap_h[4], ap_l[4];
                uint32_t offA = (uint32_t)(m0 + (g & 1) * 8 + rq) * (AST * 2)
                              + (k0 + (g >> 1) * 8) * 2;
                ldsm_x4(ap_h, bPh + offA);
                ldsm_x4(ap_l, bPl + offA);
                const uint32_t rowv = (uint32_t)(k0 + (lane & 15)) * (AST * 2);
                uint32_t bv_h[4][2], bv_l[4][2];
#pragma unroll
                for (int nt = 0; nt < 4; nt++) {
                    uint32_t offB = rowv + (n0h + nt * 8) * 2;
                    ldsm_x2t(bv_h[nt], bVh + offB);
                    ldsm_x2t(bv_l[nt], bVl + offB);
                }
#pragma unroll
                for (int nt = 0; nt < 4; nt++) {
                    mma_bf16(oacc[nt], ap_h, bv_h[nt]);
                    mma_bf16(oacc[nt], ap_h, bv_l[nt]);
                    mma_bf16(oacc[nt], ap_l, bv_h[nt]);
                }
            }
        }
    }

    // epilogue: O /= l, write bf16 hi/lo
#pragma unroll
    for (int nt = 0; nt < 4; nt++) {
#pragma unroll
        for (int hh = 0; hh < 2; hh++) {
            const int rloc = m0 + hh * 8 + (lane >> 2);
            const float inv = 1.f / l_s[rloc];
            float v0 = oacc[nt][2 * hh] * inv;
            float v1 = oacc[nt][2 * hh + 1] * inv;
            size_t base = (size_t)(qrow0 + rloc) * DMODEL + h * 64
                        + n0h + nt * 8 + (lane & 3) * 2;
            __nv_bfloat162 hp, lp;
            split2(v0, hp.x, lp.x);
            split2(v1, hp.y, lp.y);
            *(__nv_bfloat162*)(ohi + base) = hp;
            *(__nv_bfloat162*)(olo + base) = lp;
        }
    }
}

// ---------------------------------------------------------------------------
// LayerNorm (rows of 512). Optional fp32 out, optional bf16 hi/lo out.
// ---------------------------------------------------------------------------
__global__ void __launch_bounds__(128)
ln_kernel(const float* __restrict__ x, const float* __restrict__ g,
          const float* __restrict__ bta, float* __restrict__ yf,
          __nv_bfloat16* __restrict__ yh, __nv_bfloat16* __restrict__ yl)
{
    __shared__ float sbuf[4];
    const int row = blockIdx.x;
    const int tid = threadIdx.x;
    const float* xr = x + (size_t)row * DMODEL;
    float4 v = *(const float4*)(xr + tid * 4);

    float s = v.x + v.y + v.z + v.w;
#pragma unroll
    for (int off = 16; off > 0; off >>= 1) s += __shfl_xor_sync(0xffffffffu, s, off);
    if ((tid & 31) == 0) sbuf[tid >> 5] = s;
    __syncthreads();
    float mean = (sbuf[0] + sbuf[1] + sbuf[2] + sbuf[3]) * (1.f / 512.f);

    float dx = v.x - mean, dy = v.y - mean, dz = v.z - mean, dw = v.w - mean;
    float s2 = dx * dx + dy * dy + dz * dz + dw * dw;
#pragma unroll
    for (int off = 16; off > 0; off >>= 1) s2 += __shfl_xor_sync(0xffffffffu, s2, off);
    __syncthreads();
    if ((tid & 31) == 0) sbuf[tid >> 5] = s2;
    __syncthreads();
    float var = (sbuf[0] + sbuf[1] + sbuf[2] + sbuf[3]) * (1.f / 512.f);
    float inv = rsqrtf(var + LN_EPS);

    float4 gg = *(const float4*)(g + tid * 4);
    float4 bb = *(const float4*)(bta + tid * 4);
    float o0 = dx * inv * gg.x + bb.x;
    float o1 = dy * inv * gg.y + bb.y;
    float o2 = dz * inv * gg.z + bb.z;
    float o3 = dw * inv * gg.w + bb.w;
    size_t base = (size_t)row * DMODEL + tid * 4;
    if (yf) {
        float4 o = {o0, o1, o2, o3};
        *(float4*)(yf + base) = o;
    }
    if (yh) {
        __nv_bfloat162 h01, h23, l01, l23;
        split2(o0, h01.x, l01.x); split2(o1, h01.y, l01.y);
        split2(o2, h23.x, l23.x); split2(o3, h23.y, l23.y);
        *(__nv_bfloat162*)(yh + base)     = h01;
        *(__nv_bfloat162*)(yh + base + 2) = h23;
        *(__nv_bfloat162*)(yl + base)     = l01;
        *(__nv_bfloat162*)(yl + base + 2) = l23;
    }
}

// ---------------------------------------------------------------------------
extern "C" void kernel_launch(void* const* d_in, const int* in_sizes, int n_in,
                              void* d_out, int out_size)
{
    const float* X     = (const float*)d_in[0];
    const float* qkv_w = (const float*)d_in[1];
    const float* qkv_b = (const float*)d_in[2];
    const float* fc_w  = (const float*)d_in[3];
    const float* fc_b  = (const float*)d_in[4];
    const float* ln1_g = (const float*)d_in[5];
    const float* ln1_b = (const float*)d_in[6];
    const float* w1    = (const float*)d_in[7];
    const float* b1    = (const float*)d_in[8];
    const float* w2    = (const float*)d_in[9];
    const float* b2    = (const float*)d_in[10];
    const float* ln2_g = (const float*)d_in[11];
    const float* ln2_b = (const float*)d_in[12];
    float* out = (float*)d_out;

    float *x, *x1, *x2;
    __nv_bfloat16 *ctx_hi, *ctx_lo, *attn_hi, *attn_lo, *x_hi, *x_lo;
    __nv_bfloat16 *xn_hi, *xn_lo, *h_hi, *h_lo;
    __nv_bfloat16 *qkvT_hi, *qkvT_lo, *fcT_hi, *fcT_lo, *w1T_hi, *w1T_lo, *w2T_hi, *w2T_lo;
    cudaGetSymbolAddress((void**)&ctx_hi,  g_ctx_hi);
    cudaGetSymbolAddress((void**)&ctx_lo,  g_ctx_lo);
    cudaGetSymbolAddress((void**)&attn_hi, g_attn_hi);
    cudaGetSymbolAddress((void**)&attn_lo, g_attn_lo);
    cudaGetSymbolAddress((void**)&x,       g_x);
    cudaGetSymbolAddress((void**)&x1,      g_x1);
    cudaGetSymbolAddress((void**)&x2,      g_x2);
    cudaGetSymbolAddress((void**)&x_hi,    g_x_hi);
    cudaGetSymbolAddress((void**)&x_lo,    g_x_lo);
    cudaGetSymbolAddress((void**)&xn_hi,   g_xn_hi);
    cudaGetSymbolAddress((void**)&xn_lo,   g_xn_lo);
    cudaGetSymbolAddress((void**)&h_hi,    g_h_hi);
    cudaGetSymbolAddress((void**)&h_lo,    g_h_lo);
    cudaGetSymbolAddress((void**)&qkvT_hi, g_qkvT_hi);
    cudaGetSymbolAddress((void**)&qkvT_lo, g_qkvT_lo);
    cudaGetSymbolAddress((void**)&fcT_hi,  g_fcT_hi);
    cudaGetSymbolAddress((void**)&fcT_lo,  g_fcT_lo);
    cudaGetSymbolAddress((void**)&w1T_hi,  g_w1T_hi);
    cudaGetSymbolAddress((void**)&w1T_lo,  g_w1T_lo);
    cudaGetSymbolAddress((void**)&w2T_hi,  g_w2T_hi);
    cudaGetSymbolAddress((void**)&w2T_lo,  g_w2T_lo);

    cudaFuncSetAttribute(attn_kernel, cudaFuncAttributeMaxDynamicSharedMemorySize,
                         ATTN_SMEM_BYTES);

    // X -> bf16 hi/lo
    split_hilo<<<(ROWS * DMODEL + 255) / 256, 256>>>(X, x_hi, x_lo, ROWS * DMODEL);

    const float* xcur_f = X;   // fp32 carry for the proj residual

    for (int i = 0; i < NB; i++) {
        transpose_split<<<dim3(CTXW / 32, DMODEL / 32), dim3(32, 8)>>>(
            qkv_w + (size_t)i * DMODEL * CTXW, qkvT_hi, qkvT_lo, DMODEL, CTXW);
        transpose_split<<<dim3(DMODEL / 32, DMODEL / 32), dim3(32, 8)>>>(
            fc_w + (size_t)i * DMODEL * DMODEL, fcT_hi, fcT_lo, DMODEL, DMODEL);
        transpose_split<<<dim3(DHID / 32, DMODEL / 32), dim3(32, 8)>>>(
            w1 + (size_t)i * DMODEL * DHID, w1T_hi, w1T_lo, DMODEL, DHID);
        transpose_split<<<dim3(DMODEL / 32, DHID / 32), dim3(32, 8)>>>(
            w2 + (size_t)i * DHID * DMODEL, w2T_hi, w2T_lo, DHID, DMODEL);

        // 1) ctx = x @ qkv_w + qkv_b  -> bf16 hi/lo   (12x32 = 384 CTAs)
        gemm_mma<false, false, false, true><<<dim3(CTXW / 128, ROWS / 128), 256>>>(
            x_hi, x_lo, qkvT_hi, qkvT_lo, qkv_b + (size_t)i * CTXW,
            nullptr, nullptr, ctx_hi, ctx_lo, CTXW, DMODEL);

        // 2) attention -> bf16 hi/lo
        attn_kernel<<<dim3(SEQ / 64, BATCH * NH), 256, ATTN_SMEM_BYTES>>>(
            ctx_hi, ctx_lo, attn_hi, attn_lo);

        // 3) x1 = attn @ fc_w + fc_b + xcur (fp32)
        gemm_mma<false, true, true, false><<<dim3(DMODEL / 128, ROWS / 128), 256>>>(
            attn_hi, attn_lo, fcT_hi, fcT_lo, fc_b + (size_t)i * DMODEL,
            xcur_f, x1, nullptr, nullptr, DMODEL, DMODEL);

        // 4) xn = LN1(x1) -> hi/lo only
        ln_kernel<<<ROWS, 128>>>(x1, ln1_g + (size_t)i * DMODEL,
                                 ln1_b + (size_t)i * DMODEL, nullptr, xn_hi, xn_lo);

        // 5) h = relu(xn @ w1 + b1) -> hi/lo
        gemm_mma<true, false, false, true><<<dim3(DHID / 128, ROWS / 128), 256>>>(
            xn_hi, xn_lo, w1T_hi, w1T_lo, b1 + (size_t)i * DHID,
            nullptr, nullptr, h_hi, h_lo, DHID, DMODEL);

        // 6) x2 = h @ w2 + b2 + x1 (fp32)
        gemm_mma<false, true, true, false><<<dim3(DMODEL / 128, ROWS / 128), 256>>>(
            h_hi, h_lo, w2T_hi, w2T_lo, b2 + (size_t)i * DMODEL,
            x1, x2, nullptr, nullptr, DMODEL, DHID);

        // 7) carry = LN2(x2): fp32 (+ hi/lo for next layer's GEMM input)
        float* dstf = (i == NB - 1) ? out : x;
        __nv_bfloat16* nh = (i == NB - 1) ? nullptr : x_hi;
        __nv_bfloat16* nl = (i == NB - 1) ? nullptr : x_lo;
        ln_kernel<<<ROWS, 128>>>(x2, ln2_g + (size_t)i * DMODEL,
                                 ln2_b + (size_t)i * DMODEL, dstf, nh, nl);
        xcur_f = dstf;
    }
}

// round 5
// speedup vs baseline: 2.3688x; 1.0682x over previous
#include <cuda_runtime.h>
#include <cuda_bf16.h>
#include <cstdint>
#include <cstddef>

// ---------------------------------------------------------------------------
// Encoder: 12 x (QKV -> MHA -> proj+res -> LN1 -> MLP(relu) -> +res -> LN2)
// B=2, S=2048, D=512, H=8, DH=64, DHID=1024, fp32 in/out.
// All matmuls mma.sync bf16 (HMMA) hi/lo split (3 MMAs) ~ fp32 accuracy.
// Attention: register-resident flash (S/P never leave registers).
// ---------------------------------------------------------------------------

#define NB     12
#define DMODEL 512
#define NH     8
#define DHEAD  64
#define DHID   1024
#define BATCH  2
#define SEQ    2048
#define ROWS   (BATCH * SEQ)     // 4096
#define CTXW   (3 * DMODEL)      // 1536
#define LN_EPS 1e-5f
#define ATTN_SCALE 0.044194173824159216f  // 1/sqrt(512)

// ----------------------------- PTX helpers ---------------------------------
__device__ __forceinline__ uint32_t smem_u32(const void* p) {
    uint32_t a;
    asm("{ .reg .u64 t; cvta.to.shared.u64 t, %1; cvt.u32.u64 %0, t; }"
        : "=r"(a) : "l"(p));
    return a;
}
__device__ __forceinline__ void ldsm_x4(uint32_t* r, uint32_t a) {
    asm volatile("ldmatrix.sync.aligned.m8n8.x4.shared.b16 {%0,%1,%2,%3}, [%4];"
        : "=r"(r[0]), "=r"(r[1]), "=r"(r[2]), "=r"(r[3]) : "r"(a));
}
__device__ __forceinline__ void ldsm_x2t(uint32_t* r, uint32_t a) {
    asm volatile("ldmatrix.sync.aligned.m8n8.x2.trans.shared.b16 {%0,%1}, [%2];"
        : "=r"(r[0]), "=r"(r[1]) : "r"(a));
}
__device__ __forceinline__ void mma_bf16(float* c, const uint32_t* a, const uint32_t* b) {
    asm volatile("mma.sync.aligned.m16n8k16.row.col.f32.bf16.bf16.f32 "
        "{%0,%1,%2,%3}, {%4,%5,%6,%7}, {%8,%9}, {%0,%1,%2,%3};"
        : "+f"(c[0]), "+f"(c[1]), "+f"(c[2]), "+f"(c[3])
        : "r"(a[0]), "r"(a[1]), "r"(a[2]), "r"(a[3]), "r"(b[0]), "r"(b[1]));
}
__device__ __forceinline__ void split2(float v, __nv_bfloat16& h, __nv_bfloat16& l) {
    h = __float2bfloat16(v);
    l = __float2bfloat16(v - __bfloat162float(h));
}

// ------------------------- scratch (no allocation) -------------------------
__device__ __nv_bfloat16 g_ctx_hi[ROWS * CTXW];
__device__ __nv_bfloat16 g_ctx_lo[ROWS * CTXW];
__device__ __nv_bfloat16 g_attn_hi[ROWS * DMODEL];
__device__ __nv_bfloat16 g_attn_lo[ROWS * DMODEL];
__device__ float         g_x   [ROWS * DMODEL];
__device__ __nv_bfloat16 g_x_hi[ROWS * DMODEL];
__device__ __nv_bfloat16 g_x_lo[ROWS * DMODEL];
__device__ float         g_x1  [ROWS * DMODEL];
__device__ __nv_bfloat16 g_xn_hi[ROWS * DMODEL];
__device__ __nv_bfloat16 g_xn_lo[ROWS * DMODEL];
__device__ __nv_bfloat16 g_h_hi[ROWS * DHID];
__device__ __nv_bfloat16 g_h_lo[ROWS * DHID];
__device__ float         g_x2  [ROWS * DMODEL];
// transposed+split weights, ALL layers (done once up front, 4 launches)
__device__ __nv_bfloat16 g_qkvT_hi[NB * CTXW * DMODEL],  g_qkvT_lo[NB * CTXW * DMODEL];
__device__ __nv_bfloat16 g_fcT_hi [NB * DMODEL * DMODEL], g_fcT_lo[NB * DMODEL * DMODEL];
__device__ __nv_bfloat16 g_w1T_hi [NB * DHID * DMODEL],   g_w1T_lo[NB * DHID * DMODEL];
__device__ __nv_bfloat16 g_w2T_hi [NB * DMODEL * DHID],   g_w2T_lo[NB * DMODEL * DHID];

// ---------------------------------------------------------------------------
// mma GEMM: C[M,N] = A[M,K] @ W[K,N] (+bias)(+res)(relu)  (unchanged from R4)
// ---------------------------------------------------------------------------
#define GS 40   // smem row stride in bf16

template <bool RELU, bool RES, bool WF32, bool WHILO>
__global__ void __launch_bounds__(256)
gemm_mma(const __nv_bfloat16* __restrict__ Ahi, const __nv_bfloat16* __restrict__ Alo,
         const __nv_bfloat16* __restrict__ Bhi, const __nv_bfloat16* __restrict__ Blo,
         const float* __restrict__ bias, const float* __restrict__ res,
         float* __restrict__ Cf, __nv_bfloat16* __restrict__ Chi,
         __nv_bfloat16* __restrict__ Clo, int N, int K)
{
    __shared__ __nv_bfloat16 sAh[128 * GS], sAl[128 * GS];
    __shared__ __nv_bfloat16 sBh[128 * GS], sBl[128 * GS];

    const int tid  = threadIdx.x;
    const int lane = tid & 31, wid = tid >> 5;
    const int g = lane >> 3, rq = lane & 7;
    const int brow = blockIdx.y * 128, bcol = blockIdx.x * 128;
    const int m0 = (wid & 3) * 32, n0 = (wid >> 2) * 64;

    const uint32_t bAh = smem_u32(sAh), bAl = smem_u32(sAl);
    const uint32_t bBh = smem_u32(sBh), bBl = smem_u32(sBl);

    float acc[2][8][4];
#pragma unroll
    for (int mt = 0; mt < 2; mt++)
#pragma unroll
        for (int nt = 0; nt < 8; nt++)
#pragma unroll
            for (int e = 0; e < 4; e++) acc[mt][nt][e] = 0.f;

    const int NC = K >> 5;
    for (int c = 0; c < NC; c++) {
        uint4 rAh[2], rAl[2], rBh[2], rBl[2];
#pragma unroll
        for (int t = 0; t < 2; t++) {
            int idx = tid + t * 256;
            int row = idx >> 2, seg = idx & 3;
            size_t ga = (size_t)(brow + row) * K + c * 32 + seg * 8;
            size_t gb = (size_t)(bcol + row) * K + c * 32 + seg * 8;
            rAh[t] = *(const uint4*)(Ahi + ga);
            rAl[t] = *(const uint4*)(Alo + ga);
            rBh[t] = *(const uint4*)(Bhi + gb);
            rBl[t] = *(const uint4*)(Blo + gb);
        }
        __syncthreads();
#pragma unroll
        for (int t = 0; t < 2; t++) {
            int idx = tid + t * 256;
            int row = idx >> 2, seg = idx & 3;
            int so = row * GS + seg * 8;
            *(uint4*)(sAh + so) = rAh[t];
            *(uint4*)(sAl + so) = rAl[t];
            *(uint4*)(sBh + so) = rBh[t];
            *(uint4*)(sBl + so) = rBl[t];
        }
        __syncthreads();
#pragma unroll
        for (int ks = 0; ks < 2; ks++) {
            const int k0 = ks * 16;
            uint32_t ah[2][4], al[2][4];
#pragma unroll
            for (int mt = 0; mt < 2; mt++) {
                uint32_t off = (uint32_t)(m0 + mt * 16 + (g & 1) * 8 + rq) * (GS * 2)
                             + (k0 + (g >> 1) * 8) * 2;
                ldsm_x4(ah[mt], bAh + off);
                ldsm_x4(al[mt], bAl + off);
            }
            uint32_t bh[8][2], bl[8][2];
#pragma unroll
            for (int np = 0; np < 4; np++) {
                uint32_t off = (uint32_t)(n0 + np * 16 + (g >> 1) * 8 + rq) * (GS * 2)
                             + (k0 + (g & 1) * 8) * 2;
                uint32_t tmp[4];
                ldsm_x4(tmp, bBh + off);
                bh[2 * np][0] = tmp[0]; bh[2 * np][1] = tmp[1];
                bh[2 * np + 1][0] = tmp[2]; bh[2 * np + 1][1] = tmp[3];
                ldsm_x4(tmp, bBl + off);
                bl[2 * np][0] = tmp[0]; bl[2 * np][1] = tmp[1];
                bl[2 * np + 1][0] = tmp[2]; bl[2 * np + 1][1] = tmp[3];
            }
#pragma unroll
            for (int mt = 0; mt < 2; mt++)
#pragma unroll
                for (int nt = 0; nt < 8; nt++) {
                    mma_bf16(acc[mt][nt], ah[mt], bh[nt]);
                    mma_bf16(acc[mt][nt], ah[mt], bl[nt]);
                    mma_bf16(acc[mt][nt], al[mt], bh[nt]);
                }
        }
    }

#pragma unroll
    for (int mt = 0; mt < 2; mt++)
#pragma unroll
        for (int nt = 0; nt < 8; nt++) {
            const int row0 = brow + m0 + mt * 16 + (lane >> 2);
            const int col  = bcol + n0 + nt * 8 + (lane & 3) * 2;
            float2 bv = *(const float2*)(bias + col);
#pragma unroll
            for (int hh = 0; hh < 2; hh++) {
                const int row = row0 + hh * 8;
                float v0 = acc[mt][nt][2 * hh]     + bv.x;
                float v1 = acc[mt][nt][2 * hh + 1] + bv.y;
                if (RES) {
                    float2 rv = *(const float2*)(res + (size_t)row * N + col);
                    v0 += rv.x; v1 += rv.y;
                }
                if (RELU) { v0 = fmaxf(v0, 0.f); v1 = fmaxf(v1, 0.f); }
                if (WF32) {
                    float2 o = {v0, v1};
                    *(float2*)(Cf + (size_t)row * N + col) = o;
                }
                if (WHILO) {
                    __nv_bfloat162 hp, lp;
                    split2(v0, hp.x, lp.x);
                    split2(v1, hp.y, lp.y);
                    *(__nv_bfloat162*)(Chi + (size_t)row * N + col) = hp;
                    *(__nv_bfloat162*)(Clo + (size_t)row * N + col) = lp;
                }
            }
        }
}

// ---------------------------------------------------------------------------
// Weight transpose+split for ALL layers at once (blockIdx.z = layer).
// in[z][K][N] fp32 -> out_hi/lo [z][N][K] bf16
// ---------------------------------------------------------------------------
__global__ void __launch_bounds__(256)
transpose_split_l(const float* __restrict__ in, __nv_bfloat16* __restrict__ oh,
                  __nv_bfloat16* __restrict__ ol, int K, int N)
{
    __shared__ float t[32][33];
    const size_t zoff = (size_t)blockIdx.z * K * N;
    const float* src = in + zoff;
    const int n0 = blockIdx.x * 32, k0 = blockIdx.y * 32;
    const int tx = threadIdx.x, ty = threadIdx.y;   // 32 x 8
#pragma unroll
    for (int i = 0; i < 32; i += 8)
        t[ty + i][tx] = src[(size_t)(k0 + ty + i) * N + n0 + tx];
    __syncthreads();
#pragma unroll
    for (int i = 0; i < 32; i += 8) {
        float v = t[tx][ty + i];
        size_t o = zoff + (size_t)(n0 + ty + i) * K + k0 + tx;
        __nv_bfloat16 h, l;
        split2(v, h, l);
        oh[o] = h; ol[o] = l;
    }
}

__global__ void __launch_bounds__(256)
split_hilo(const float* __restrict__ x, __nv_bfloat16* __restrict__ h,
           __nv_bfloat16* __restrict__ l, int n)
{
    int i = blockIdx.x * 256 + threadIdx.x;
    if (i < n) {
        __nv_bfloat16 hv, lv;
        split2(x[i], hv, lv);
        h[i] = hv; l[i] = lv;
    }
}

// ---------------------------------------------------------------------------
// Attention, register-resident flash: CTA = 128 q-rows x one (b,h);
// 8 warps, warp w owns q rows [w*16, w*16+16) x ALL 64 keys per tile.
// S and P stay in registers; softmax via shfl; P(C-frag) == PV A-frag layout.
// ---------------------------------------------------------------------------
#define AST 72                    // bf16 smem row stride
#define ATTN_SMEM_BYTES ((2 * 128 + 4 * 64) * AST * 2)   // 73728

__global__ void __launch_bounds__(256)
attn_kernel(const __nv_bfloat16* __restrict__ cxh, const __nv_bfloat16* __restrict__ cxl,
            __nv_bfloat16* __restrict__ ohi, __nv_bfloat16* __restrict__ olo)
{
    extern __shared__ char smc[];
    __nv_bfloat16* Qh = (__nv_bfloat16*)smc;        // 128 x AST
    __nv_bfloat16* Ql = Qh + 128 * AST;
    __nv_bfloat16* Kh = Ql + 128 * AST;             // 64 x AST each
    __nv_bfloat16* Kl = Kh + 64 * AST;
    __nv_bfloat16* Vh = Kl + 64 * AST;
    __nv_bfloat16* Vl = Vh + 64 * AST;

    const int tid  = threadIdx.x;
    const int lane = tid & 31, wid = tid >> 5;
    const int g = lane >> 3, rq = lane & 7;
    const int b = blockIdx.y >> 3, h = blockIdx.y & 7;
    const int qrow0 = b * SEQ + blockIdx.x * 128;
    const int krowb = b * SEQ;
    const int qc = h * 192, kc = qc + 64, vc = qc + 128;

    const uint32_t bQh = smem_u32(Qh), bQl = smem_u32(Ql);
    const uint32_t bKh = smem_u32(Kh), bKl = smem_u32(Kl);
    const uint32_t bVh = smem_u32(Vh), bVl = smem_u32(Vl);

    const int m0 = wid * 16;      // warp's q rows within the 128-row tile

    // ---- load Q tile 128x64 hi/lo, extract fragments once ----
#pragma unroll
    for (int t = 0; t < 4; t++) {
        int idx = tid + t * 256;
        int row = idx >> 3, seg = idx & 7;
        size_t go = (size_t)(qrow0 + row) * CTXW + qc + seg * 8;
        int so = row * AST + seg * 8;
        *(uint4*)(Qh + so) = *(const uint4*)(cxh + go);
        *(uint4*)(Ql + so) = *(const uint4*)(cxl + go);
    }
    __syncthreads();
    uint32_t qf_h[4][4], qf_l[4][4];
#pragma unroll
    for (int ks = 0; ks < 4; ks++) {
        uint32_t offA = (uint32_t)(m0 + (g & 1) * 8 + rq) * (AST * 2)
                      + (ks * 16 + (g >> 1) * 8) * 2;
        ldsm_x4(qf_h[ks], bQh + offA);
        ldsm_x4(qf_l[ks], bQl + offA);
    }

    float m_r0 = -1e30f, m_r1 = -1e30f, l_r0 = 0.f, l_r1 = 0.f;
    float oacc[8][4];
#pragma unroll
    for (int nt = 0; nt < 8; nt++)
#pragma unroll
        for (int e = 0; e < 4; e++) oacc[nt][e] = 0.f;

    for (int kt = 0; kt < 32; kt++) {
        const int krow0 = krowb + kt * 64;
        // stage K/V (64 rows x 8 segs = 512 units / 256 threads)
        uint4 rkh[2], rkl[2], rvh[2], rvl[2];
#pragma unroll
        for (int t = 0; t < 2; t++) {
            int idx = tid + t * 256;
            int row = idx >> 3, seg = idx & 7;
            size_t gk = (size_t)(krow0 + row) * CTXW + kc + seg * 8;
            size_t gv = (size_t)(krow0 + row) * CTXW + vc + seg * 8;
            rkh[t] = *(const uint4*)(cxh + gk);
            rkl[t] = *(const uint4*)(cxl + gk);
            rvh[t] = *(const uint4*)(cxh + gv);
            rvl[t] = *(const uint4*)(cxl + gv);
        }
        __syncthreads();   // prev tile's V ldsm done (and Q ldsm on kt=0)
#pragma unroll
        for (int t = 0; t < 2; t++) {
            int idx = tid + t * 256;
            int row = idx >> 3, seg = idx & 7;
            int so = row * AST + seg * 8;
            *(uint4*)(Kh + so) = rkh[t];
            *(uint4*)(Kl + so) = rkl[t];
            *(uint4*)(Vh + so) = rvh[t];
            *(uint4*)(Vl + so) = rvl[t];
        }
        __syncthreads();

        // ---- S = Q @ K^T (hi/lo, 3 mma), registers only ----
        float sacc[8][4];
#pragma unroll
        for (int nt = 0; nt < 8; nt++)
#pragma unroll
            for (int e = 0; e < 4; e++) sacc[nt][e] = 0.f;
#pragma unroll
        for (int ks = 0; ks < 4; ks++) {
#pragma unroll
            for (int np = 0; np < 4; np++) {
                uint32_t offB = (uint32_t)(np * 16 + (g >> 1) * 8 + rq) * (AST * 2)
                              + (ks * 16 + (g & 1) * 8) * 2;
                uint32_t th[4], tl[4];
                ldsm_x4(th, bKh + offB);
                ldsm_x4(tl, bKl + offB);
                mma_bf16(sacc[2 * np],     qf_h[ks], th);
                mma_bf16(sacc[2 * np],     qf_h[ks], tl);
                mma_bf16(sacc[2 * np],     qf_l[ks], th);
                mma_bf16(sacc[2 * np + 1], qf_h[ks], th + 2);
                mma_bf16(sacc[2 * np + 1], qf_h[ks], tl + 2);
                mma_bf16(sacc[2 * np + 1], qf_l[ks], th + 2);
            }
        }
        // scale
#pragma unroll
        for (int nt = 0; nt < 8; nt++)
#pragma unroll
            for (int e = 0; e < 4; e++) sacc[nt][e] *= ATTN_SCALE;

        // ---- register softmax (rows r0 = lane>>2, r1 = r0+8) ----
        float mx0 = -1e30f, mx1 = -1e30f;
#pragma unroll
        for (int nt = 0; nt < 8; nt++) {
            mx0 = fmaxf(mx0, fmaxf(sacc[nt][0], sacc[nt][1]));
            mx1 = fmaxf(mx1, fmaxf(sacc[nt][2], sacc[nt][3]));
        }
        mx0 = fmaxf(mx0, __shfl_xor_sync(0xffffffffu, mx0, 1));
        mx0 = fmaxf(mx0, __shfl_xor_sync(0xffffffffu, mx0, 2));
        mx1 = fmaxf(mx1, __shfl_xor_sync(0xffffffffu, mx1, 1));
        mx1 = fmaxf(mx1, __shfl_xor_sync(0xffffffffu, mx1, 2));
        const float mn0 = fmaxf(m_r0, mx0), mn1 = fmaxf(m_r1, mx1);
        const float cf0 = __expf(m_r0 - mn0), cf1 = __expf(m_r1 - mn1);
        float sum0 = 0.f, sum1 = 0.f;
#pragma unroll
        for (int nt = 0; nt < 8; nt++) {
            sacc[nt][0] = __expf(sacc[nt][0] - mn0);
            sacc[nt][1] = __expf(sacc[nt][1] - mn0);
            sacc[nt][2] = __expf(sacc[nt][2] - mn1);
            sacc[nt][3] = __expf(sacc[nt][3] - mn1);
            sum0 += sacc[nt][0] + sacc[nt][1];
            sum1 += sacc[nt][2] + sacc[nt][3];
        }
        sum0 += __shfl_xor_sync(0xffffffffu, sum0, 1);
        sum0 += __shfl_xor_sync(0xffffffffu, sum0, 2);
        sum1 += __shfl_xor_sync(0xffffffffu, sum1, 1);
        sum1 += __shfl_xor_sync(0xffffffffu, sum1, 2);
        l_r0 = l_r0 * cf0 + sum0;  m_r0 = mn0;
        l_r1 = l_r1 * cf1 + sum1;  m_r1 = mn1;

        // rescale O
#pragma unroll
        for (int nt = 0; nt < 8; nt++) {
            oacc[nt][0] *= cf0; oacc[nt][1] *= cf0;
            oacc[nt][2] *= cf1; oacc[nt][3] *= cf1;
        }

        // ---- O += P @ V : P packed from sacc (C-frag == A-frag layout) ----
#pragma unroll
        for (int ks = 0; ks < 4; ks++) {
            uint32_t ap_h[4], ap_l[4];
            {
                __nv_bfloat162 h0, l0;
                split2(sacc[2 * ks][0], h0.x, l0.x);
                split2(sacc[2 * ks][1], h0.y, l0.y);
                ap_h[0] = *(uint32_t*)&h0; ap_l[0] = *(uint32_t*)&l0;
                split2(sacc[2 * ks][2], h0.x, l0.x);
                split2(sacc[2 * ks][3], h0.y, l0.y);
                ap_h[1] = *(uint32_t*)&h0; ap_l[1] = *(uint32_t*)&l0;
                split2(sacc[2 * ks + 1][0], h0.x, l0.x);
                split2(sacc[2 * ks + 1][1], h0.y, l0.y);
                ap_h[2] = *(uint32_t*)&h0; ap_l[2] = *(uint32_t*)&l0;
                split2(sacc[2 * ks + 1][2], h0.x, l0.x);
                split2(sacc[2 * ks + 1][3], h0.y, l0.y);
                ap_h[3] = *(uint32_t*)&h0; ap_l[3] = *(uint32_t*)&l0;
            }
            const uint32_t rowv = (uint32_t)(ks * 16 + (lane & 15)) * (AST * 2);
#pragma unroll
            for (int nt = 0; nt < 8; nt++) {
                uint32_t bvh[2], bvl[2];
                uint32_t offB = rowv + nt * 16;   // (nt*8 cols)*2 bytes
                ldsm_x2t(bvh, bVh + offB);
                ldsm_x2t(bvl, bVl + offB);
                mma_bf16(oacc[nt], ap_h, bvh);
                mma_bf16(oacc[nt], ap_h, bvl);
                mma_bf16(oacc[nt], ap_l, bvh);
            }
        }
    }

    // ---- epilogue: O /= l, write bf16 hi/lo ----
    const float inv0 = 1.f / l_r0, inv1 = 1.f / l_r1;
#pragma unroll
    for (int nt = 0; nt < 8; nt++) {
#pragma unroll
        for (int hh = 0; hh < 2; hh++) {
            const int rloc = m0 + hh * 8 + (lane >> 2);
            const float inv = hh ? inv1 : inv0;
            float v0 = oacc[nt][2 * hh] * inv;
            float v1 = oacc[nt][2 * hh + 1] * inv;
            size_t base = (size_t)(qrow0 + rloc) * DMODEL + h * 64
                        + nt * 8 + (lane & 3) * 2;
            __nv_bfloat162 hp, lp;
            split2(v0, hp.x, lp.x);
            split2(v1, hp.y, lp.y);
            *(__nv_bfloat162*)(ohi + base) = hp;
            *(__nv_bfloat162*)(olo + base) = lp;
        }
    }
}

// ---------------------------------------------------------------------------
// LayerNorm (rows of 512). Optional fp32 out, optional bf16 hi/lo out.
// ---------------------------------------------------------------------------
__global__ void __launch_bounds__(128)
ln_kernel(const float* __restrict__ x, const float* __restrict__ g,
          const float* __restrict__ bta, float* __restrict__ yf,
          __nv_bfloat16* __restrict__ yh, __nv_bfloat16* __restrict__ yl)
{
    __shared__ float sbuf[4];
    const int row = blockIdx.x;
    const int tid = threadIdx.x;
    const float* xr = x + (size_t)row * DMODEL;
    float4 v = *(const float4*)(xr + tid * 4);

    float s = v.x + v.y + v.z + v.w;
#pragma unroll
    for (int off = 16; off > 0; off >>= 1) s += __shfl_xor_sync(0xffffffffu, s, off);
    if ((tid & 31) == 0) sbuf[tid >> 5] = s;
    __syncthreads();
    float mean = (sbuf[0] + sbuf[1] + sbuf[2] + sbuf[3]) * (1.f / 512.f);

    float dx = v.x - mean, dy = v.y - mean, dz = v.z - mean, dw = v.w - mean;
    float s2 = dx * dx + dy * dy + dz * dz + dw * dw;
#pragma unroll
    for (int off = 16; off > 0; off >>= 1) s2 += __shfl_xor_sync(0xffffffffu, s2, off);
    __syncthreads();
    if ((tid & 31) == 0) sbuf[tid >> 5] = s2;
    __syncthreads();
    float var = (sbuf[0] + sbuf[1] + sbuf[2] + sbuf[3]) * (1.f / 512.f);
    float inv = rsqrtf(var + LN_EPS);

    float4 gg = *(const float4*)(g + tid * 4);
    float4 bb = *(const float4*)(bta + tid * 4);
    float o0 = dx * inv * gg.x + bb.x;
    float o1 = dy * inv * gg.y + bb.y;
    float o2 = dz * inv * gg.z + bb.z;
    float o3 = dw * inv * gg.w + bb.w;
    size_t base = (size_t)row * DMODEL + tid * 4;
    if (yf) {
        float4 o = {o0, o1, o2, o3};
        *(float4*)(yf + base) = o;
    }
    if (yh) {
        __nv_bfloat162 h01, h23, l01, l23;
        split2(o0, h01.x, l01.x); split2(o1, h01.y, l01.y);
        split2(o2, h23.x, l23.x); split2(o3, h23.y, l23.y);
        *(__nv_bfloat162*)(yh + base)     = h01;
        *(__nv_bfloat162*)(yh + base + 2) = h23;
        *(__nv_bfloat162*)(yl + base)     = l01;
        *(__nv_bfloat162*)(yl + base + 2) = l23;
    }
}

// ---------------------------------------------------------------------------
extern "C" void kernel_launch(void* const* d_in, const int* in_sizes, int n_in,
                              void* d_out, int out_size)
{
    const float* X     = (const float*)d_in[0];
    const float* qkv_w = (const float*)d_in[1];
    const float* qkv_b = (const float*)d_in[2];
    const float* fc_w  = (const float*)d_in[3];
    const float* fc_b  = (const float*)d_in[4];
    const float* ln1_g = (const float*)d_in[5];
    const float* ln1_b = (const float*)d_in[6];
    const float* w1    = (const float*)d_in[7];
    const float* b1    = (const float*)d_in[8];
    const float* w2    = (const float*)d_in[9];
    const float* b2    = (const float*)d_in[10];
    const float* ln2_g = (const float*)d_in[11];
    const float* ln2_b = (const float*)d_in[12];
    float* out = (float*)d_out;

    float *x, *x1, *x2;
    __nv_bfloat16 *ctx_hi, *ctx_lo, *attn_hi, *attn_lo, *x_hi, *x_lo;
    __nv_bfloat16 *xn_hi, *xn_lo, *h_hi, *h_lo;
    __nv_bfloat16 *qkvT_hi, *qkvT_lo, *fcT_hi, *fcT_lo, *w1T_hi, *w1T_lo, *w2T_hi, *w2T_lo;
    cudaGetSymbolAddress((void**)&ctx_hi,  g_ctx_hi);
    cudaGetSymbolAddress((void**)&ctx_lo,  g_ctx_lo);
    cudaGetSymbolAddress((void**)&attn_hi, g_attn_hi);
    cudaGetSymbolAddress((void**)&attn_lo, g_attn_lo);
    cudaGetSymbolAddress((void**)&x,       g_x);
    cudaGetSymbolAddress((void**)&x1,      g_x1);
    cudaGetSymbolAddress((void**)&x2,      g_x2);
    cudaGetSymbolAddress((void**)&x_hi,    g_x_hi);
    cudaGetSymbolAddress((void**)&x_lo,    g_x_lo);
    cudaGetSymbolAddress((void**)&xn_hi,   g_xn_hi);
    cudaGetSymbolAddress((void**)&xn_lo,   g_xn_lo);
    cudaGetSymbolAddress((void**)&h_hi,    g_h_hi);
    cudaGetSymbolAddress((void**)&h_lo,    g_h_lo);
    cudaGetSymbolAddress((void**)&qkvT_hi, g_qkvT_hi);
    cudaGetSymbolAddress((void**)&qkvT_lo, g_qkvT_lo);
    cudaGetSymbolAddress((void**)&fcT_hi,  g_fcT_hi);
    cudaGetSymbolAddress((void**)&fcT_lo,  g_fcT_lo);
    cudaGetSymbolAddress((void**)&w1T_hi,  g_w1T_hi);
    cudaGetSymbolAddress((void**)&w1T_lo,  g_w1T_lo);
    cudaGetSymbolAddress((void**)&w2T_hi,  g_w2T_hi);
    cudaGetSymbolAddress((void**)&w2T_lo,  g_w2T_lo);

    cudaFuncSetAttribute(attn_kernel, cudaFuncAttributeMaxDynamicSharedMemorySize,
                         ATTN_SMEM_BYTES);

    // all weight transposes up front (4 launches, z = layer)
    transpose_split_l<<<dim3(CTXW / 32, DMODEL / 32, NB), dim3(32, 8)>>>(
        qkv_w, qkvT_hi, qkvT_lo, DMODEL, CTXW);
    transpose_split_l<<<dim3(DMODEL / 32, DMODEL / 32, NB), dim3(32, 8)>>>(
        fc_w, fcT_hi, fcT_lo, DMODEL, DMODEL);
    transpose_split_l<<<dim3(DHID / 32, DMODEL / 32, NB), dim3(32, 8)>>>(
        w1, w1T_hi, w1T_lo, DMODEL, DHID);
    transpose_split_l<<<dim3(DMODEL / 32, DHID / 32, NB), dim3(32, 8)>>>(
        w2, w2T_hi, w2T_lo, DHID, DMODEL);

    split_hilo<<<(ROWS * DMODEL + 255) / 256, 256>>>(X, x_hi, x_lo, ROWS * DMODEL);

    const float* xcur_f = X;

    for (int i = 0; i < NB; i++) {
        const size_t oq = (size_t)i * CTXW * DMODEL;
        const size_t of = (size_t)i * DMODEL * DMODEL;
        const size_t o1 = (size_t)i * DHID * DMODEL;
        const size_t o2 = (size_t)i * DMODEL * DHID;

        // 1) ctx = x @ qkv_w + qkv_b -> bf16 hi/lo
        gemm_mma<false, false, false, true><<<dim3(CTXW / 128, ROWS / 128), 256>>>(
            x_hi, x_lo, qkvT_hi + oq, qkvT_lo + oq, qkv_b + (size_t)i * CTXW,
            nullptr, nullptr, ctx_hi, ctx_lo, CTXW, DMODEL);

        // 2) attention -> bf16 hi/lo
        attn_kernel<<<dim3(SEQ / 128, BATCH * NH), 256, ATTN_SMEM_BYTES>>>(
            ctx_hi, ctx_lo, attn_hi, attn_lo);

        // 3) x1 = attn @ fc_w + fc_b + xcur (fp32)
        gemm_mma<false, true, true, false><<<dim3(DMODEL / 128, ROWS / 128), 256>>>(
            attn_hi, attn_lo, fcT_hi + of, fcT_lo + of, fc_b + (size_t)i * DMODEL,
            xcur_f, x1, nullptr, nullptr, DMODEL, DMODEL);

        // 4) xn = LN1(x1) -> hi/lo only
        ln_kernel<<<ROWS, 128>>>(x1, ln1_g + (size_t)i * DMODEL,
                                 ln1_b + (size_t)i * DMODEL, nullptr, xn_hi, xn_lo);

        // 5) h = relu(xn @ w1 + b1) -> hi/lo
        gemm_mma<true, false, false, true><<<dim3(DHID / 128, ROWS / 128), 256>>>(
            xn_hi, xn_lo, w1T_hi + o1, w1T_lo + o1, b1 + (size_t)i * DHID,
            nullptr, nullptr, h_hi, h_lo, DHID, DMODEL);

        // 6) x2 = h @ w2 + b2 + x1 (fp32)
        gemm_mma<false, true, true, false><<<dim3(DMODEL / 128, ROWS / 128), 256>>>(
            h_hi, h_lo, w2T_hi + o2, w2T_lo + o2, b2 + (size_t)i * DMODEL,
            x1, x2, nullptr, nullptr, DMODEL, DHID);

        // 7) carry = LN2(x2): fp32 (+ hi/lo for next layer's GEMM input)
        float* dstf = (i == NB - 1) ? out : x;
        __nv_bfloat16* nh = (i == NB - 1) ? nullptr : x_hi;
        __nv_bfloat16* nl = (i == NB - 1) ? nullptr : x_lo;
        ln_kernel<<<ROWS, 128>>>(x2, ln2_g + (size_t)i * DMODEL,
                                 ln2_b + (size_t)i * DMODEL, dstf, nh, nl);
        xcur_f = dstf;
    }
}

// round 7
// speedup vs baseline: 2.8988x; 1.2238x over previous
#include <cuda_runtime.h>
#include <cuda_bf16.h>
#include <cstdint>
#include <cstddef>

// ---------------------------------------------------------------------------
// Encoder: 12 x (QKV -> MHA -> proj+res -> LN1 -> MLP(relu) -> +res -> LN2)
// B=2, S=2048, D=512, H=8, DH=64, DHID=1024, fp32 in/out.
// All matmuls mma.sync bf16 (HMMA) hi/lo split (3 MMAs) ~ fp32 accuracy.
// R7 = R6 resubmit: cp.async 2-stage pipelines in GEMM and attention.
// ---------------------------------------------------------------------------

#define NB     12
#define DMODEL 512
#define NH     8
#define DHEAD  64
#define DHID   1024
#define BATCH  2
#define SEQ    2048
#define ROWS   (BATCH * SEQ)     // 4096
#define CTXW   (3 * DMODEL)      // 1536
#define LN_EPS 1e-5f
#define ATTN_SCALE 0.044194173824159216f  // 1/sqrt(512)

// ----------------------------- PTX helpers ---------------------------------
__device__ __forceinline__ uint32_t smem_u32(const void* p) {
    uint32_t a;
    asm("{ .reg .u64 t; cvta.to.shared.u64 t, %1; cvt.u32.u64 %0, t; }"
        : "=r"(a) : "l"(p));
    return a;
}
__device__ __forceinline__ void ldsm_x4(uint32_t* r, uint32_t a) {
    asm volatile("ldmatrix.sync.aligned.m8n8.x4.shared.b16 {%0,%1,%2,%3}, [%4];"
        : "=r"(r[0]), "=r"(r[1]), "=r"(r[2]), "=r"(r[3]) : "r"(a));
}
__device__ __forceinline__ void ldsm_x2t(uint32_t* r, uint32_t a) {
    asm volatile("ldmatrix.sync.aligned.m8n8.x2.trans.shared.b16 {%0,%1}, [%2];"
        : "=r"(r[0]), "=r"(r[1]) : "r"(a));
}
__device__ __forceinline__ void mma_bf16(float* c, const uint32_t* a, const uint32_t* b) {
    asm volatile("mma.sync.aligned.m16n8k16.row.col.f32.bf16.bf16.f32 "
        "{%0,%1,%2,%3}, {%4,%5,%6,%7}, {%8,%9}, {%0,%1,%2,%3};"
        : "+f"(c[0]), "+f"(c[1]), "+f"(c[2]), "+f"(c[3])
        : "r"(a[0]), "r"(a[1]), "r"(a[2]), "r"(a[3]), "r"(b[0]), "r"(b[1]));
}
__device__ __forceinline__ void split2(float v, __nv_bfloat16& h, __nv_bfloat16& l) {
    h = __float2bfloat16(v);
    l = __float2bfloat16(v - __bfloat162float(h));
}
__device__ __forceinline__ void cp16(uint32_t dst, const void* src) {
    asm volatile("cp.async.cg.shared.global [%0], [%1], 16;"
                 :: "r"(dst), "l"(src) : "memory");
}
#define CP_COMMIT() asm volatile("cp.async.commit_group;" ::: "memory")
#define CP_WAIT1()  asm volatile("cp.async.wait_group 1;"  ::: "memory")

// ------------------------- scratch (no allocation) -------------------------
__device__ __nv_bfloat16 g_ctx_hi[ROWS * CTXW];
__device__ __nv_bfloat16 g_ctx_lo[ROWS * CTXW];
__device__ __nv_bfloat16 g_attn_hi[ROWS * DMODEL];
__device__ __nv_bfloat16 g_attn_lo[ROWS * DMODEL];
__device__ float         g_x   [ROWS * DMODEL];
__device__ __nv_bfloat16 g_x_hi[ROWS * DMODEL];
__device__ __nv_bfloat16 g_x_lo[ROWS * DMODEL];
__device__ float         g_x1  [ROWS * DMODEL];
__device__ __nv_bfloat16 g_xn_hi[ROWS * DMODEL];
__device__ __nv_bfloat16 g_xn_lo[ROWS * DMODEL];
__device__ __nv_bfloat16 g_h_hi[ROWS * DHID];
__device__ __nv_bfloat16 g_h_lo[ROWS * DHID];
__device__ float         g_x2  [ROWS * DMODEL];
__device__ __nv_bfloat16 g_qkvT_hi[NB * CTXW * DMODEL],  g_qkvT_lo[NB * CTXW * DMODEL];
__device__ __nv_bfloat16 g_fcT_hi [NB * DMODEL * DMODEL], g_fcT_lo[NB * DMODEL * DMODEL];
__device__ __nv_bfloat16 g_w1T_hi [NB * DHID * DMODEL],   g_w1T_lo[NB * DHID * DMODEL];
__device__ __nv_bfloat16 g_w2T_hi [NB * DMODEL * DHID],   g_w2T_lo[NB * DMODEL * DHID];

// ---------------------------------------------------------------------------
// mma GEMM with cp.async 2-stage pipeline.
// C[M,N] = A[M,K] @ W[K,N] (+bias)(+res)(relu); A hi/lo [M][K], W^T hi/lo [N][K].
// 128x128 tile, BK=32, 8 warps (warp tile 32x64).
// Stage layout (bytes): Ah 0, Al 10240, Bh 20480, Bl 30720; STG=40960.
// ---------------------------------------------------------------------------
#define GS 40                       // smem row stride in bf16
#define G_STG 40960
#define G_SMEM (2 * G_STG)          // 81920

template <bool RELU, bool RES, bool WF32, bool WHILO>
__global__ void __launch_bounds__(256)
gemm_mma(const __nv_bfloat16* __restrict__ Ahi, const __nv_bfloat16* __restrict__ Alo,
         const __nv_bfloat16* __restrict__ Bhi, const __nv_bfloat16* __restrict__ Blo,
         const float* __restrict__ bias, const float* __restrict__ res,
         float* __restrict__ Cf, __nv_bfloat16* __restrict__ Chi,
         __nv_bfloat16* __restrict__ Clo, int N, int K)
{
    extern __shared__ char dsm[];
    const uint32_t sb = smem_u32(dsm);

    const int tid  = threadIdx.x;
    const int lane = tid & 31, wid = tid >> 5;
    const int g = lane >> 3, rq = lane & 7;
    const int brow = blockIdx.y * 128, bcol = blockIdx.x * 128;
    const int m0 = (wid & 3) * 32, n0 = (wid >> 2) * 64;

    // loader indices: 2 iters x 256 threads cover 128 rows x 4 segs
    const int lrow0 = tid >> 2, lseg = (tid & 3) * 8;       // seg in bf16

    float acc[2][8][4];
#pragma unroll
    for (int mt = 0; mt < 2; mt++)
#pragma unroll
        for (int nt = 0; nt < 8; nt++)
#pragma unroll
            for (int e = 0; e < 4; e++) acc[mt][nt][e] = 0.f;

    const int NT = K >> 5;

    // stage loader: chunk c -> buffer buf
    auto issue = [&](int c, int buf) {
        const uint32_t st = sb + buf * G_STG;
        const size_t kb = (size_t)c * 32 + lseg;
#pragma unroll
        for (int t = 0; t < 2; t++) {
            const int row = lrow0 + t * 64;
            const uint32_t so = (uint32_t)(row * GS + lseg) * 2;
            const size_t ga = (size_t)(brow + row) * K + kb;
            const size_t gb = (size_t)(bcol + row) * K + kb;
            cp16(st + so,         Ahi + ga);
            cp16(st + 10240 + so, Alo + ga);
            cp16(st + 20480 + so, Bhi + gb);
            cp16(st + 30720 + so, Blo + gb);
        }
    };

    issue(0, 0); CP_COMMIT();
    issue(1, 1); CP_COMMIT();

    for (int c = 0; c < NT; c++) {
        CP_WAIT1();
        __syncthreads();
        const uint32_t st = sb + (c & 1) * G_STG;
        const uint32_t bAh = st, bAl = st + 10240, bBh = st + 20480, bBl = st + 30720;
#pragma unroll
        for (int ks = 0; ks < 2; ks++) {
            const int k0 = ks * 16;
            uint32_t ah[2][4], al[2][4];
#pragma unroll
            for (int mt = 0; mt < 2; mt++) {
                uint32_t off = (uint32_t)(m0 + mt * 16 + (g & 1) * 8 + rq) * (GS * 2)
                             + (k0 + (g >> 1) * 8) * 2;
                ldsm_x4(ah[mt], bAh + off);
                ldsm_x4(al[mt], bAl + off);
            }
            uint32_t bh[8][2], bl[8][2];
#pragma unroll
            for (int np = 0; np < 4; np++) {
                uint32_t off = (uint32_t)(n0 + np * 16 + (g >> 1) * 8 + rq) * (GS * 2)
                             + (k0 + (g & 1) * 8) * 2;
                uint32_t tmp[4];
                ldsm_x4(tmp, bBh + off);
                bh[2 * np][0] = tmp[0]; bh[2 * np][1] = tmp[1];
                bh[2 * np + 1][0] = tmp[2]; bh[2 * np + 1][1] = tmp[3];
                ldsm_x4(tmp, bBl + off);
                bl[2 * np][0] = tmp[0]; bl[2 * np][1] = tmp[1];
                bl[2 * np + 1][0] = tmp[2]; bl[2 * np + 1][1] = tmp[3];
            }
#pragma unroll
            for (int mt = 0; mt < 2; mt++)
#pragma unroll
                for (int nt = 0; nt < 8; nt++) {
                    mma_bf16(acc[mt][nt], ah[mt], bh[nt]);
                    mma_bf16(acc[mt][nt], ah[mt], bl[nt]);
                    mma_bf16(acc[mt][nt], al[mt], bh[nt]);
                }
        }
        __syncthreads();
        if (c + 2 < NT) issue(c + 2, c & 1);
        CP_COMMIT();
    }

#pragma unroll
    for (int mt = 0; mt < 2; mt++)
#pragma unroll
        for (int nt = 0; nt < 8; nt++) {
            const int row0 = brow + m0 + mt * 16 + (lane >> 2);
            const int col  = bcol + n0 + nt * 8 + (lane & 3) * 2;
            float2 bv = *(const float2*)(bias + col);
#pragma unroll
            for (int hh = 0; hh < 2; hh++) {
                const int row = row0 + hh * 8;
                float v0 = acc[mt][nt][2 * hh]     + bv.x;
                float v1 = acc[mt][nt][2 * hh + 1] + bv.y;
                if (RES) {
                    float2 rv = *(const float2*)(res + (size_t)row * N + col);
                    v0 += rv.x; v1 += rv.y;
                }
                if (RELU) { v0 = fmaxf(v0, 0.f); v1 = fmaxf(v1, 0.f); }
                if (WF32) {
                    float2 o = {v0, v1};
                    *(float2*)(Cf + (size_t)row * N + col) = o;
                }
                if (WHILO) {
                    __nv_bfloat162 hp, lp;
                    split2(v0, hp.x, lp.x);
                    split2(v1, hp.y, lp.y);
                    *(__nv_bfloat162*)(Chi + (size_t)row * N + col) = hp;
                    *(__nv_bfloat162*)(Clo + (size_t)row * N + col) = lp;
                }
            }
        }
}

// ---------------------------------------------------------------------------
// Weight transpose+split for ALL layers (blockIdx.z = layer).
// ---------------------------------------------------------------------------
__global__ void __launch_bounds__(256)
transpose_split_l(const float* __restrict__ in, __nv_bfloat16* __restrict__ oh,
                  __nv_bfloat16* __restrict__ ol, int K, int N)
{
    __shared__ float t[32][33];
    const size_t zoff = (size_t)blockIdx.z * K * N;
    const float* src = in + zoff;
    const int n0 = blockIdx.x * 32, k0 = blockIdx.y * 32;
    const int tx = threadIdx.x, ty = threadIdx.y;   // 32 x 8
#pragma unroll
    for (int i = 0; i < 32; i += 8)
        t[ty + i][tx] = src[(size_t)(k0 + ty + i) * N + n0 + tx];
    __syncthreads();
#pragma unroll
    for (int i = 0; i < 32; i += 8) {
        float v = t[tx][ty + i];
        size_t o = zoff + (size_t)(n0 + ty + i) * K + k0 + tx;
        __nv_bfloat16 h, l;
        split2(v, h, l);
        oh[o] = h; ol[o] = l;
    }
}

__global__ void __launch_bounds__(256)
split_hilo(const float* __restrict__ x, __nv_bfloat16* __restrict__ h,
           __nv_bfloat16* __restrict__ l, int n)
{
    int i = blockIdx.x * 256 + threadIdx.x;
    if (i < n) {
        __nv_bfloat16 hv, lv;
        split2(x[i], hv, lv);
        h[i] = hv; l[i] = lv;
    }
}

// ---------------------------------------------------------------------------
// Attention, register-resident flash + cp.async 2-stage KV pipeline.
// CTA = 128 q-rows x one (b,h); warp w owns q rows [w*16,w*16+16) x all 64 keys.
// Dynamic smem: Qh 0, Ql 18432; stage s at 36864+s*36864
//   within stage: Kh 0, Kl 9216, Vh 18432, Vl 27648.
// ---------------------------------------------------------------------------
#define AST 72
#define A_QB  18432                 // one Q matrix bytes (128 x 72 x 2)
#define A_KVB 9216                  // one K/V matrix bytes (64 x 72 x 2)
#define A_STG (4 * A_KVB)           // 36864
#define ATTN_SMEM_BYTES (2 * A_QB + 2 * A_STG)   // 110592

__global__ void __launch_bounds__(256)
attn_kernel(const __nv_bfloat16* __restrict__ cxh, const __nv_bfloat16* __restrict__ cxl,
            __nv_bfloat16* __restrict__ ohi, __nv_bfloat16* __restrict__ olo)
{
    extern __shared__ char smc[];
    const uint32_t sb = smem_u32(smc);
    __nv_bfloat16* Qh = (__nv_bfloat16*)smc;
    __nv_bfloat16* Ql = Qh + 128 * AST;

    const int tid  = threadIdx.x;
    const int lane = tid & 31, wid = tid >> 5;
    const int g = lane >> 3, rq = lane & 7;
    const int b = blockIdx.y >> 3, h = blockIdx.y & 7;
    const int qrow0 = b * SEQ + blockIdx.x * 128;
    const int krowb = b * SEQ;
    const int qc = h * 192, kc = qc + 64, vc = qc + 128;

    const int m0 = wid * 16;
    const int lrow = tid >> 3, lseg = (tid & 7) * 8;   // KV loader

    auto issueKV = [&](int kt, int buf) {
        const int krow0 = krowb + kt * 64;
        const uint32_t st = sb + 2 * A_QB + buf * A_STG;
#pragma unroll
        for (int t = 0; t < 2; t++) {
            const int row = lrow + t * 32;
            const uint32_t so = (uint32_t)(row * AST + lseg) * 2;
            const size_t gk = (size_t)(krow0 + row) * CTXW + kc + lseg;
            const size_t gv = (size_t)(krow0 + row) * CTXW + vc + lseg;
            cp16(st + so,             cxh + gk);
            cp16(st + A_KVB + so,     cxl + gk);
            cp16(st + 2 * A_KVB + so, cxh + gv);
            cp16(st + 3 * A_KVB + so, cxl + gv);
        }
    };

    issueKV(0, 0); CP_COMMIT();
    issueKV(1, 1); CP_COMMIT();

#pragma unroll
    for (int t = 0; t < 4; t++) {
        int idx = tid + t * 256;
        int row = idx >> 3, seg = idx & 7;
        size_t go = (size_t)(qrow0 + row) * CTXW + qc + seg * 8;
        int so = row * AST + seg * 8;
        *(uint4*)(Qh + so) = *(const uint4*)(cxh + go);
        *(uint4*)(Ql + so) = *(const uint4*)(cxl + go);
    }
    __syncthreads();
    uint32_t qf_h[4][4], qf_l[4][4];
#pragma unroll
    for (int ks = 0; ks < 4; ks++) {
        uint32_t offA = (uint32_t)(m0 + (g & 1) * 8 + rq) * (AST * 2)
                      + (ks * 16 + (g >> 1) * 8) * 2;
        ldsm_x4(qf_h[ks], sb + offA);
        ldsm_x4(qf_l[ks], sb + A_QB + offA);
    }

    float m_r0 = -1e30f, m_r1 = -1e30f, l_r0 = 0.f, l_r1 = 0.f;
    float oacc[8][4];
#pragma unroll
    for (int nt = 0; nt < 8; nt++)
#pragma unroll
        for (int e = 0; e < 4; e++) oacc[nt][e] = 0.f;

    for (int kt = 0; kt < 32; kt++) {
        CP_WAIT1();
        __syncthreads();
        const uint32_t st = sb + 2 * A_QB + (kt & 1) * A_STG;
        const uint32_t bKh = st, bKl = st + A_KVB;
        const uint32_t bVh = st + 2 * A_KVB, bVl = st + 3 * A_KVB;

        // ---- S = Q @ K^T ----
        float sacc[8][4];
#pragma unroll
        for (int nt = 0; nt < 8; nt++)
#pragma unroll
            for (int e = 0; e < 4; e++) sacc[nt][e] = 0.f;
#pragma unroll
        for (int ks = 0; ks < 4; ks++) {
#pragma unroll
            for (int np = 0; np < 4; np++) {
                uint32_t offB = (uint32_t)(np * 16 + (g >> 1) * 8 + rq) * (AST * 2)
                              + (ks * 16 + (g & 1) * 8) * 2;
                uint32_t th[4], tl[4];
                ldsm_x4(th, bKh + offB);
                ldsm_x4(tl, bKl + offB);
                mma_bf16(sacc[2 * np],     qf_h[ks], th);
                mma_bf16(sacc[2 * np],     qf_h[ks], tl);
                mma_bf16(sacc[2 * np],     qf_l[ks], th);
                mma_bf16(sacc[2 * np + 1], qf_h[ks], th + 2);
                mma_bf16(sacc[2 * np + 1], qf_h[ks], tl + 2);
                mma_bf16(sacc[2 * np + 1], qf_l[ks], th + 2);
            }
        }
#pragma unroll
        for (int nt = 0; nt < 8; nt++)
#pragma unroll
            for (int e = 0; e < 4; e++) sacc[nt][e] *= ATTN_SCALE;

        // ---- register softmax ----
        float mx0 = -1e30f, mx1 = -1e30f;
#pragma unroll
        for (int nt = 0; nt < 8; nt++) {
            mx0 = fmaxf(mx0, fmaxf(sacc[nt][0], sacc[nt][1]));
            mx1 = fmaxf(mx1, fmaxf(sacc[nt][2], sacc[nt][3]));
        }
        mx0 = fmaxf(mx0, __shfl_xor_sync(0xffffffffu, mx0, 1));
        mx0 = fmaxf(mx0, __shfl_xor_sync(0xffffffffu, mx0, 2));
        mx1 = fmaxf(mx1, __shfl_xor_sync(0xffffffffu, mx1, 1));
        mx1 = fmaxf(mx1, __shfl_xor_sync(0xffffffffu, mx1, 2));
        const float mn0 = fmaxf(m_r0, mx0), mn1 = fmaxf(m_r1, mx1);
        const float cf0 = __expf(m_r0 - mn0), cf1 = __expf(m_r1 - mn1);
        float sum0 = 0.f, sum1 = 0.f;
#pragma unroll
        for (int nt = 0; nt < 8; nt++) {
            sacc[nt][0] = __expf(sacc[nt][0] - mn0);
            sacc[nt][1] = __expf(sacc[nt][1] - mn0);
            sacc[nt][2] = __expf(sacc[nt][2] - mn1);
            sacc[nt][3] = __expf(sacc[nt][3] - mn1);
            sum0 += sacc[nt][0] + sacc[nt][1];
            sum1 += sacc[nt][2] + sacc[nt][3];
        }
        sum0 += __shfl_xor_sync(0xffffffffu, sum0, 1);
        sum0 += __shfl_xor_sync(0xffffffffu, sum0, 2);
        sum1 += __shfl_xor_sync(0xffffffffu, sum1, 1);
        sum1 += __shfl_xor_sync(0xffffffffu, sum1, 2);
        l_r0 = l_r0 * cf0 + sum0;  m_r0 = mn0;
        l_r1 = l_r1 * cf1 + sum1;  m_r1 = mn1;

#pragma unroll
        for (int nt = 0; nt < 8; nt++) {
            oacc[nt][0] *= cf0; oacc[nt][1] *= cf0;
            oacc[nt][2] *= cf1; oacc[nt][3] *= cf1;
        }

        // ---- O += P @ V (P packed from sacc; C-frag == A-frag layout) ----
#pragma unroll
        for (int ks = 0; ks < 4; ks++) {
            uint32_t ap_h[4], ap_l[4];
            {
                __nv_bfloat162 h0, l0;
                split2(sacc[2 * ks][0], h0.x, l0.x);
                split2(sacc[2 * ks][1], h0.y, l0.y);
                ap_h[0] = *(uint32_t*)&h0; ap_l[0] = *(uint32_t*)&l0;
                split2(sacc[2 * ks][2], h0.x, l0.x);
                split2(sacc[2 * ks][3], h0.y, l0.y);
                ap_h[1] = *(uint32_t*)&h0; ap_l[1] = *(uint32_t*)&l0;
                split2(sacc[2 * ks + 1][0], h0.x, l0.x);
                split2(sacc[2 * ks + 1][1], h0.y, l0.y);
                ap_h[2] = *(uint32_t*)&h0; ap_l[2] = *(uint32_t*)&l0;
                split2(sacc[2 * ks + 1][2], h0.x, l0.x);
                split2(sacc[2 * ks + 1][3], h0.y, l0.y);
                ap_h[3] = *(uint32_t*)&h0; ap_l[3] = *(uint32_t*)&l0;
            }
            const uint32_t rowv = (uint32_t)(ks * 16 + (lane & 15)) * (AST * 2);
#pragma unroll
            for (int nt = 0; nt < 8; nt++) {
                uint32_t bvh[2], bvl[2];
                uint32_t offB = rowv + nt * 16;
                ldsm_x2t(bvh, bVh + offB);
                ldsm_x2t(bvl, bVl + offB);
                mma_bf16(oacc[nt], ap_h, bvh);
                mma_bf16(oacc[nt], ap_h, bvl);
                mma_bf16(oacc[nt], ap_l, bvh);
            }
        }
        __syncthreads();
        if (kt + 2 < 32) issueKV(kt + 2, kt & 1);
        CP_COMMIT();
    }

    // ---- epilogue ----
    const float inv0 = 1.f / l_r0, inv1 = 1.f / l_r1;
#pragma unroll
    for (int nt = 0; nt < 8; nt++) {
#pragma unroll
        for (int hh = 0; hh < 2; hh++) {
            const int rloc = m0 + hh * 8 + (lane >> 2);
            const float inv = hh ? inv1 : inv0;
            float v0 = oacc[nt][2 * hh] * inv;
            float v1 = oacc[nt][2 * hh + 1] * inv;
            size_t base = (size_t)(qrow0 + rloc) * DMODEL + h * 64
                        + nt * 8 + (lane & 3) * 2;
            __nv_bfloat162 hp, lp;
            split2(v0, hp.x, lp.x);
            split2(v1, hp.y, lp.y);
            *(__nv_bfloat162*)(ohi + base) = hp;
            *(__nv_bfloat162*)(olo + base) = lp;
        }
    }
}

// ---------------------------------------------------------------------------
// LayerNorm (rows of 512).
// ---------------------------------------------------------------------------
__global__ void __launch_bounds__(128)
ln_kernel(const float* __restrict__ x, const float* __restrict__ g,
          const float* __restrict__ bta, float* __restrict__ yf,
          __nv_bfloat16* __restrict__ yh, __nv_bfloat16* __restrict__ yl)
{
    __shared__ float sbuf[4];
    const int row = blockIdx.x;
    const int tid = threadIdx.x;
    const float* xr = x + (size_t)row * DMODEL;
    float4 v = *(const float4*)(xr + tid * 4);

    float s = v.x + v.y + v.z + v.w;
#pragma unroll
    for (int off = 16; off > 0; off >>= 1) s += __shfl_xor_sync(0xffffffffu, s, off);
    if ((tid & 31) == 0) sbuf[tid >> 5] = s;
    __syncthreads();
    float mean = (sbuf[0] + sbuf[1] + sbuf[2] + sbuf[3]) * (1.f / 512.f);

    float dx = v.x - mean, dy = v.y - mean, dz = v.z - mean, dw = v.w - mean;
    float s2 = dx * dx + dy * dy + dz * dz + dw * dw;
#pragma unroll
    for (int off = 16; off > 0; off >>= 1) s2 += __shfl_xor_sync(0xffffffffu, s2, off);
    __syncthreads();
    if ((tid & 31) == 0) sbuf[tid >> 5] = s2;
    __syncthreads();
    float var = (sbuf[0] + sbuf[1] + sbuf[2] + sbuf[3]) * (1.f / 512.f);
    float inv = rsqrtf(var + LN_EPS);

    float4 gg = *(const float4*)(g + tid * 4);
    float4 bb = *(const float4*)(bta + tid * 4);
    float o0 = dx * inv * gg.x + bb.x;
    float o1 = dy * inv * gg.y + bb.y;
    float o2 = dz * inv * gg.z + bb.z;
    float o3 = dw * inv * gg.w + bb.w;
    size_t base = (size_t)row * DMODEL + tid * 4;
    if (yf) {
        float4 o = {o0, o1, o2, o3};
        *(float4*)(yf + base) = o;
    }
    if (yh) {
        __nv_bfloat162 h01, h23, l01, l23;
        split2(o0, h01.x, l01.x); split2(o1, h01.y, l01.y);
        split2(o2, h23.x, l23.x); split2(o3, h23.y, l23.y);
        *(__nv_bfloat162*)(yh + base)     = h01;
        *(__nv_bfloat162*)(yh + base + 2) = h23;
        *(__nv_bfloat162*)(yl + base)     = l01;
        *(__nv_bfloat162*)(yl + base + 2) = l23;
    }
}

// ---------------------------------------------------------------------------
extern "C" void kernel_launch(void* const* d_in, const int* in_sizes, int n_in,
                              void* d_out, int out_size)
{
    const float* X     = (const float*)d_in[0];
    const float* qkv_w = (const float*)d_in[1];
    const float* qkv_b = (const float*)d_in[2];
    const float* fc_w  = (const float*)d_in[3];
    const float* fc_b  = (const float*)d_in[4];
    const float* ln1_g = (const float*)d_in[5];
    const float* ln1_b = (const float*)d_in[6];
    const float* w1    = (const float*)d_in[7];
    const float* b1    = (const float*)d_in[8];
    const float* w2    = (const float*)d_in[9];
    const float* b2    = (const float*)d_in[10];
    const float* ln2_g = (const float*)d_in[11];
    const float* ln2_b = (const float*)d_in[12];
    float* out = (float*)d_out;

    float *x, *x1, *x2;
    __nv_bfloat16 *ctx_hi, *ctx_lo, *attn_hi, *attn_lo, *x_hi, *x_lo;
    __nv_bfloat16 *xn_hi, *xn_lo, *h_hi, *h_lo;
    __nv_bfloat16 *qkvT_hi, *qkvT_lo, *fcT_hi, *fcT_lo, *w1T_hi, *w1T_lo, *w2T_hi, *w2T_lo;
    cudaGetSymbolAddress((void**)&ctx_hi,  g_ctx_hi);
    cudaGetSymbolAddress((void**)&ctx_lo,  g_ctx_lo);
    cudaGetSymbolAddress((void**)&attn_hi, g_attn_hi);
    cudaGetSymbolAddress((void**)&attn_lo, g_attn_lo);
    cudaGetSymbolAddress((void**)&x,       g_x);
    cudaGetSymbolAddress((void**)&x1,      g_x1);
    cudaGetSymbolAddress((void**)&x2,      g_x2);
    cudaGetSymbolAddress((void**)&x_hi,    g_x_hi);
    cudaGetSymbolAddress((void**)&x_lo,    g_x_lo);
    cudaGetSymbolAddress((void**)&xn_hi,   g_xn_hi);
    cudaGetSymbolAddress((void**)&xn_lo,   g_xn_lo);
    cudaGetSymbolAddress((void**)&h_hi,    g_h_hi);
    cudaGetSymbolAddress((void**)&h_lo,    g_h_lo);
    cudaGetSymbolAddress((void**)&qkvT_hi, g_qkvT_hi);
    cudaGetSymbolAddress((void**)&qkvT_lo, g_qkvT_lo);
    cudaGetSymbolAddress((void**)&fcT_hi,  g_fcT_hi);
    cudaGetSymbolAddress((void**)&fcT_lo,  g_fcT_lo);
    cudaGetSymbolAddress((void**)&w1T_hi,  g_w1T_hi);
    cudaGetSymbolAddress((void**)&w1T_lo,  g_w1T_lo);
    cudaGetSymbolAddress((void**)&w2T_hi,  g_w2T_hi);
    cudaGetSymbolAddress((void**)&w2T_lo,  g_w2T_lo);

    cudaFuncSetAttribute(attn_kernel, cudaFuncAttributeMaxDynamicSharedMemorySize,
                         ATTN_SMEM_BYTES);
    cudaFuncSetAttribute(gemm_mma<false, false, false, true>,
                         cudaFuncAttributeMaxDynamicSharedMemorySize, G_SMEM);
    cudaFuncSetAttribute(gemm_mma<false, true, true, false>,
                         cudaFuncAttributeMaxDynamicSharedMemorySize, G_SMEM);
    cudaFuncSetAttribute(gemm_mma<true, false, false, true>,
                         cudaFuncAttributeMaxDynamicSharedMemorySize, G_SMEM);

    transpose_split_l<<<dim3(CTXW / 32, DMODEL / 32, NB), dim3(32, 8)>>>(
        qkv_w, qkvT_hi, qkvT_lo, DMODEL, CTXW);
    transpose_split_l<<<dim3(DMODEL / 32, DMODEL / 32, NB), dim3(32, 8)>>>(
        fc_w, fcT_hi, fcT_lo, DMODEL, DMODEL);
    transpose_split_l<<<dim3(DHID / 32, DMODEL / 32, NB), dim3(32, 8)>>>(
        w1, w1T_hi, w1T_lo, DMODEL, DHID);
    transpose_split_l<<<dim3(DMODEL / 32, DHID / 32, NB), dim3(32, 8)>>>(
        w2, w2T_hi, w2T_lo, DHID, DMODEL);

    split_hilo<<<(ROWS * DMODEL + 255) / 256, 256>>>(X, x_hi, x_lo, ROWS * DMODEL);

    const float* xcur_f = X;

    for (int i = 0; i < NB; i++) {
        const size_t oq = (size_t)i * CTXW * DMODEL;
        const size_t of = (size_t)i * DMODEL * DMODEL;
        const size_t o1 = (size_t)i * DHID * DMODEL;
        const size_t o2 = (size_t)i * DMODEL * DHID;

        // 1) ctx = x @ qkv_w + qkv_b -> bf16 hi/lo
        gemm_mma<false, false, false, true>
            <<<dim3(CTXW / 128, ROWS / 128), 256, G_SMEM>>>(
            x_hi, x_lo, qkvT_hi + oq, qkvT_lo + oq, qkv_b + (size_t)i * CTXW,
            nullptr, nullptr, ctx_hi, ctx_lo, CTXW, DMODEL);

        // 2) attention -> bf16 hi/lo
        attn_kernel<<<dim3(SEQ / 128, BATCH * NH), 256, ATTN_SMEM_BYTES>>>(
            ctx_hi, ctx_lo, attn_hi, attn_lo);

        // 3) x1 = attn @ fc_w + fc_b + xcur (fp32)
        gemm_mma<false, true, true, false>
            <<<dim3(DMODEL / 128, ROWS / 128), 256, G_SMEM>>>(
            attn_hi, attn_lo, fcT_hi + of, fcT_lo + of, fc_b + (size_t)i * DMODEL,
            xcur_f, x1, nullptr, nullptr, DMODEL, DMODEL);

        // 4) xn = LN1(x1) -> hi/lo only
        ln_kernel<<<ROWS, 128>>>(x1, ln1_g + (size_t)i * DMODEL,
                                 ln1_b + (size_t)i * DMODEL, nullptr, xn_hi, xn_lo);

        // 5) h = relu(xn @ w1 + b1) -> hi/lo
        gemm_mma<true, false, false, true>
            <<<dim3(DHID / 128, ROWS / 128), 256, G_SMEM>>>(
            xn_hi, xn_lo, w1T_hi + o1, w1T_lo + o1, b1 + (size_t)i * DHID,
            nullptr, nullptr, h_hi, h_lo, DHID, DMODEL);

        // 6) x2 = h @ w2 + b2 + x1 (fp32)
        gemm_mma<false, true, true, false>
            <<<dim3(DMODEL / 128, ROWS / 128), 256, G_SMEM>>>(
            h_hi, h_lo, w2T_hi + o2, w2T_lo + o2, b2 + (size_t)i * DMODEL,
            x1, x2, nullptr, nullptr, DMODEL, DHID);

        // 7) carry = LN2(x2)
        float* dstf = (i == NB - 1) ? out : x;
        __nv_bfloat16* nh = (i == NB - 1) ? nullptr : x_hi;
        __nv_bfloat16* nl = (i == NB - 1) ? nullptr : x_lo;
        ln_kernel<<<ROWS, 128>>>(x2, ln2_g + (size_t)i * DMODEL,
                                 ln2_b + (size_t)i * DMODEL, dstf, nh, nl);
        xcur_f = dstf;
    }
}

// round 8
// speedup vs baseline: 3.0982x; 1.0688x over previous
#include <cuda_runtime.h>
#include <cuda_bf16.h>
#include <cstdint>
#include <cstddef>

// ---------------------------------------------------------------------------
// Encoder: 12 x (QKV -> MHA -> proj+res -> LN1 -> MLP(relu) -> +res -> LN2)
// B=2, S=2048, D=512, H=8, DH=64, DHID=1024, fp32 in/out.
// All matmuls mma.sync bf16 (HMMA) hi/lo split (3 MMAs) ~ fp32 accuracy.
// R8: attention occupancy push — no Q smem (direct-fragment LDG),
//     2 CTAs/SM (launch_bounds 256,2; smem 72KB), V loads via ldmatrix.x4.trans.
// ---------------------------------------------------------------------------

#define NB     12
#define DMODEL 512
#define NH     8
#define DHEAD  64
#define DHID   1024
#define BATCH  2
#define SEQ    2048
#define ROWS   (BATCH * SEQ)     // 4096
#define CTXW   (3 * DMODEL)      // 1536
#define LN_EPS 1e-5f
#define ATTN_SCALE 0.044194173824159216f  // 1/sqrt(512)

// ----------------------------- PTX helpers ---------------------------------
__device__ __forceinline__ uint32_t smem_u32(const void* p) {
    uint32_t a;
    asm("{ .reg .u64 t; cvta.to.shared.u64 t, %1; cvt.u32.u64 %0, t; }"
        : "=r"(a) : "l"(p));
    return a;
}
__device__ __forceinline__ void ldsm_x4(uint32_t* r, uint32_t a) {
    asm volatile("ldmatrix.sync.aligned.m8n8.x4.shared.b16 {%0,%1,%2,%3}, [%4];"
        : "=r"(r[0]), "=r"(r[1]), "=r"(r[2]), "=r"(r[3]) : "r"(a));
}
__device__ __forceinline__ void ldsm_x4t(uint32_t* r, uint32_t a) {
    asm volatile("ldmatrix.sync.aligned.m8n8.x4.trans.shared.b16 {%0,%1,%2,%3}, [%4];"
        : "=r"(r[0]), "=r"(r[1]), "=r"(r[2]), "=r"(r[3]) : "r"(a));
}
__device__ __forceinline__ void mma_bf16(float* c, const uint32_t* a, const uint32_t* b) {
    asm volatile("mma.sync.aligned.m16n8k16.row.col.f32.bf16.bf16.f32 "
        "{%0,%1,%2,%3}, {%4,%5,%6,%7}, {%8,%9}, {%0,%1,%2,%3};"
        : "+f"(c[0]), "+f"(c[1]), "+f"(c[2]), "+f"(c[3])
        : "r"(a[0]), "r"(a[1]), "r"(a[2]), "r"(a[3]), "r"(b[0]), "r"(b[1]));
}
__device__ __forceinline__ void split2(float v, __nv_bfloat16& h, __nv_bfloat16& l) {
    h = __float2bfloat16(v);
    l = __float2bfloat16(v - __bfloat162float(h));
}
__device__ __forceinline__ void cp16(uint32_t dst, const void* src) {
    asm volatile("cp.async.cg.shared.global [%0], [%1], 16;"
                 :: "r"(dst), "l"(src) : "memory");
}
#define CP_COMMIT() asm volatile("cp.async.commit_group;" ::: "memory")
#define CP_WAIT1()  asm volatile("cp.async.wait_group 1;"  ::: "memory")

// ------------------------- scratch (no allocation) -------------------------
__device__ __nv_bfloat16 g_ctx_hi[ROWS * CTXW];
__device__ __nv_bfloat16 g_ctx_lo[ROWS * CTXW];
__device__ __nv_bfloat16 g_attn_hi[ROWS * DMODEL];
__device__ __nv_bfloat16 g_attn_lo[ROWS * DMODEL];
__device__ float         g_x   [ROWS * DMODEL];
__device__ __nv_bfloat16 g_x_hi[ROWS * DMODEL];
__device__ __nv_bfloat16 g_x_lo[ROWS * DMODEL];
__device__ float         g_x1  [ROWS * DMODEL];
__device__ __nv_bfloat16 g_xn_hi[ROWS * DMODEL];
__device__ __nv_bfloat16 g_xn_lo[ROWS * DMODEL];
__device__ __nv_bfloat16 g_h_hi[ROWS * DHID];
__device__ __nv_bfloat16 g_h_lo[ROWS * DHID];
__device__ float         g_x2  [ROWS * DMODEL];
__device__ __nv_bfloat16 g_qkvT_hi[NB * CTXW * DMODEL],  g_qkvT_lo[NB * CTXW * DMODEL];
__device__ __nv_bfloat16 g_fcT_hi [NB * DMODEL * DMODEL], g_fcT_lo[NB * DMODEL * DMODEL];
__device__ __nv_bfloat16 g_w1T_hi [NB * DHID * DMODEL],   g_w1T_lo[NB * DHID * DMODEL];
__device__ __nv_bfloat16 g_w2T_hi [NB * DMODEL * DHID],   g_w2T_lo[NB * DMODEL * DHID];

// ---------------------------------------------------------------------------
// mma GEMM with cp.async 2-stage pipeline (unchanged from R7).
// ---------------------------------------------------------------------------
#define GS 40                       // smem row stride in bf16
#define G_STG 40960
#define G_SMEM (2 * G_STG)          // 81920

template <bool RELU, bool RES, bool WF32, bool WHILO>
__global__ void __launch_bounds__(256)
gemm_mma(const __nv_bfloat16* __restrict__ Ahi, const __nv_bfloat16* __restrict__ Alo,
         const __nv_bfloat16* __restrict__ Bhi, const __nv_bfloat16* __restrict__ Blo,
         const float* __restrict__ bias, const float* __restrict__ res,
         float* __restrict__ Cf, __nv_bfloat16* __restrict__ Chi,
         __nv_bfloat16* __restrict__ Clo, int N, int K)
{
    extern __shared__ char dsm[];
    const uint32_t sb = smem_u32(dsm);

    const int tid  = threadIdx.x;
    const int lane = tid & 31, wid = tid >> 5;
    const int g = lane >> 3, rq = lane & 7;
    const int brow = blockIdx.y * 128, bcol = blockIdx.x * 128;
    const int m0 = (wid & 3) * 32, n0 = (wid >> 2) * 64;

    const int lrow0 = tid >> 2, lseg = (tid & 3) * 8;

    float acc[2][8][4];
#pragma unroll
    for (int mt = 0; mt < 2; mt++)
#pragma unroll
        for (int nt = 0; nt < 8; nt++)
#pragma unroll
            for (int e = 0; e < 4; e++) acc[mt][nt][e] = 0.f;

    const int NT = K >> 5;

    auto issue = [&](int c, int buf) {
        const uint32_t st = sb + buf * G_STG;
        const size_t kb = (size_t)c * 32 + lseg;
#pragma unroll
        for (int t = 0; t < 2; t++) {
            const int row = lrow0 + t * 64;
            const uint32_t so = (uint32_t)(row * GS + lseg) * 2;
            const size_t ga = (size_t)(brow + row) * K + kb;
            const size_t gb = (size_t)(bcol + row) * K + kb;
            cp16(st + so,         Ahi + ga);
            cp16(st + 10240 + so, Alo + ga);
            cp16(st + 20480 + so, Bhi + gb);
            cp16(st + 30720 + so, Blo + gb);
        }
    };

    issue(0, 0); CP_COMMIT();
    issue(1, 1); CP_COMMIT();

    for (int c = 0; c < NT; c++) {
        CP_WAIT1();
        __syncthreads();
        const uint32_t st = sb + (c & 1) * G_STG;
        const uint32_t bAh = st, bAl = st + 10240, bBh = st + 20480, bBl = st + 30720;
#pragma unroll
        for (int ks = 0; ks < 2; ks++) {
            const int k0 = ks * 16;
            uint32_t ah[2][4], al[2][4];
#pragma unroll
            for (int mt = 0; mt < 2; mt++) {
                uint32_t off = (uint32_t)(m0 + mt * 16 + (g & 1) * 8 + rq) * (GS * 2)
                             + (k0 + (g >> 1) * 8) * 2;
                ldsm_x4(ah[mt], bAh + off);
                ldsm_x4(al[mt], bAl + off);
            }
            uint32_t bh[8][2], bl[8][2];
#pragma unroll
            for (int np = 0; np < 4; np++) {
                uint32_t off = (uint32_t)(n0 + np * 16 + (g >> 1) * 8 + rq) * (GS * 2)
                             + (k0 + (g & 1) * 8) * 2;
                uint32_t tmp[4];
                ldsm_x4(tmp, bBh + off);
                bh[2 * np][0] = tmp[0]; bh[2 * np][1] = tmp[1];
                bh[2 * np + 1][0] = tmp[2]; bh[2 * np + 1][1] = tmp[3];
                ldsm_x4(tmp, bBl + off);
                bl[2 * np][0] = tmp[0]; bl[2 * np][1] = tmp[1];
                bl[2 * np + 1][0] = tmp[2]; bl[2 * np + 1][1] = tmp[3];
            }
#pragma unroll
            for (int mt = 0; mt < 2; mt++)
#pragma unroll
                for (int nt = 0; nt < 8; nt++) {
                    mma_bf16(acc[mt][nt], ah[mt], bh[nt]);
                    mma_bf16(acc[mt][nt], ah[mt], bl[nt]);
                    mma_bf16(acc[mt][nt], al[mt], bh[nt]);
                }
        }
        __syncthreads();
        if (c + 2 < NT) issue(c + 2, c & 1);
        CP_COMMIT();
    }

#pragma unroll
    for (int mt = 0; mt < 2; mt++)
#pragma unroll
        for (int nt = 0; nt < 8; nt++) {
            const int row0 = brow + m0 + mt * 16 + (lane >> 2);
            const int col  = bcol + n0 + nt * 8 + (lane & 3) * 2;
            float2 bv = *(const float2*)(bias + col);
#pragma unroll
            for (int hh = 0; hh < 2; hh++) {
                const int row = row0 + hh * 8;
                float v0 = acc[mt][nt][2 * hh]     + bv.x;
                float v1 = acc[mt][nt][2 * hh + 1] + bv.y;
                if (RES) {
                    float2 rv = *(const float2*)(res + (size_t)row * N + col);
                    v0 += rv.x; v1 += rv.y;
                }
                if (RELU) { v0 = fmaxf(v0, 0.f); v1 = fmaxf(v1, 0.f); }
                if (WF32) {
                    float2 o = {v0, v1};
                    *(float2*)(Cf + (size_t)row * N + col) = o;
                }
                if (WHILO) {
                    __nv_bfloat162 hp, lp;
                    split2(v0, hp.x, lp.x);
                    split2(v1, hp.y, lp.y);
                    *(__nv_bfloat162*)(Chi + (size_t)row * N + col) = hp;
                    *(__nv_bfloat162*)(Clo + (size_t)row * N + col) = lp;
                }
            }
        }
}

// ---------------------------------------------------------------------------
// Weight transpose+split for ALL layers (blockIdx.z = layer).
// ---------------------------------------------------------------------------
__global__ void __launch_bounds__(256)
transpose_split_l(const float* __restrict__ in, __nv_bfloat16* __restrict__ oh,
                  __nv_bfloat16* __restrict__ ol, int K, int N)
{
    __shared__ float t[32][33];
    const size_t zoff = (size_t)blockIdx.z * K * N;
    const float* src = in + zoff;
    const int n0 = blockIdx.x * 32, k0 = blockIdx.y * 32;
    const int tx = threadIdx.x, ty = threadIdx.y;   // 32 x 8
#pragma unroll
    for (int i = 0; i < 32; i += 8)
        t[ty + i][tx] = src[(size_t)(k0 + ty + i) * N + n0 + tx];
    __syncthreads();
#pragma unroll
    for (int i = 0; i < 32; i += 8) {
        float v = t[tx][ty + i];
        size_t o = zoff + (size_t)(n0 + ty + i) * K + k0 + tx;
        __nv_bfloat16 h, l;
        split2(v, h, l);
        oh[o] = h; ol[o] = l;
    }
}

__global__ void __launch_bounds__(256)
split_hilo(const float* __restrict__ x, __nv_bfloat16* __restrict__ h,
           __nv_bfloat16* __restrict__ l, int n)
{
    int i = blockIdx.x * 256 + threadIdx.x;
    if (i < n) {
        __nv_bfloat16 hv, lv;
        split2(x[i], hv, lv);
        h[i] = hv; l[i] = lv;
    }
}

// ---------------------------------------------------------------------------
// Attention, register-resident flash, cp.async 2-stage KV pipeline.
// R8: no Q smem (fragments LDG'd directly), smem = 2 KV stages = 72KB,
//     2 CTAs/SM target, V fragments via ldmatrix.x4.trans.
// CTA = 128 q-rows x one (b,h); warp w owns q rows [w*16,w*16+16) x all 64 keys.
// ---------------------------------------------------------------------------
#define AST 72
#define A_KVB 9216                  // one K/V matrix bytes (64 x 72 x 2)
#define A_STG (4 * A_KVB)           // 36864
#define ATTN_SMEM_BYTES (2 * A_STG) // 73728

__global__ void __launch_bounds__(256, 2)
attn_kernel(const __nv_bfloat16* __restrict__ cxh, const __nv_bfloat16* __restrict__ cxl,
            __nv_bfloat16* __restrict__ ohi, __nv_bfloat16* __restrict__ olo)
{
    extern __shared__ char smc[];
    const uint32_t sb = smem_u32(smc);

    const int tid  = threadIdx.x;
    const int lane = tid & 31, wid = tid >> 5;
    const int g = lane >> 3, rq = lane & 7;
    const int b = blockIdx.y >> 3, h = blockIdx.y & 7;
    const int qrow0 = b * SEQ + blockIdx.x * 128;
    const int krowb = b * SEQ;
    const int qc = h * 192, kc = qc + 64, vc = qc + 128;

    const int m0 = wid * 16;
    const int lrow = tid >> 3, lseg = (tid & 7) * 8;   // KV loader

    auto issueKV = [&](int kt, int buf) {
        const int krow0 = krowb + kt * 64;
        const uint32_t st = sb + buf * A_STG;
#pragma unroll
        for (int t = 0; t < 2; t++) {
            const int row = lrow + t * 32;
            const uint32_t so = (uint32_t)(row * AST + lseg) * 2;
            const size_t gk = (size_t)(krow0 + row) * CTXW + kc + lseg;
            const size_t gv = (size_t)(krow0 + row) * CTXW + vc + lseg;
            cp16(st + so,             cxh + gk);
            cp16(st + A_KVB + so,     cxl + gk);
            cp16(st + 2 * A_KVB + so, cxh + gv);
            cp16(st + 3 * A_KVB + so, cxl + gv);
        }
    };

    issueKV(0, 0); CP_COMMIT();
    issueKV(1, 1); CP_COMMIT();

    // ---- Q fragments directly from gmem (canonical m16n8k16 A layout) ----
    uint32_t qf_h[4][4], qf_l[4][4];
    {
        const size_t r0 = (size_t)(qrow0 + m0 + (lane >> 2)) * CTXW;
        const size_t r1 = r0 + (size_t)8 * CTXW;
        const int c0 = qc + (lane & 3) * 2;
#pragma unroll
        for (int ks = 0; ks < 4; ks++) {
            const int c = c0 + ks * 16;
            qf_h[ks][0] = *(const uint32_t*)(cxh + r0 + c);
            qf_h[ks][1] = *(const uint32_t*)(cxh + r1 + c);
            qf_h[ks][2] = *(const uint32_t*)(cxh + r0 + c + 8);
            qf_h[ks][3] = *(const uint32_t*)(cxh + r1 + c + 8);
            qf_l[ks][0] = *(const uint32_t*)(cxl + r0 + c);
            qf_l[ks][1] = *(const uint32_t*)(cxl + r1 + c);
            qf_l[ks][2] = *(const uint32_t*)(cxl + r0 + c + 8);
            qf_l[ks][3] = *(const uint32_t*)(cxl + r1 + c + 8);
        }
    }

    float m_r0 = -1e30f, m_r1 = -1e30f, l_r0 = 0.f, l_r1 = 0.f;
    float oacc[8][4];
#pragma unroll
    for (int nt = 0; nt < 8; nt++)
#pragma unroll
        for (int e = 0; e < 4; e++) oacc[nt][e] = 0.f;

    for (int kt = 0; kt < 32; kt++) {
        CP_WAIT1();
        __syncthreads();
        const uint32_t st = sb + (kt & 1) * A_STG;
        const uint32_t bKh = st, bKl = st + A_KVB;
        const uint32_t bVh = st + 2 * A_KVB, bVl = st + 3 * A_KVB;

        // ---- S = Q @ K^T ----
        float sacc[8][4];
#pragma unroll
        for (int nt = 0; nt < 8; nt++)
#pragma unroll
            for (int e = 0; e < 4; e++) sacc[nt][e] = 0.f;
#pragma unroll
        for (int ks = 0; ks < 4; ks++) {
#pragma unroll
            for (int np = 0; np < 4; np++) {
                uint32_t offB = (uint32_t)(np * 16 + (g >> 1) * 8 + rq) * (AST * 2)
                              + (ks * 16 + (g & 1) * 8) * 2;
                uint32_t th[4], tl[4];
                ldsm_x4(th, bKh + offB);
                ldsm_x4(tl, bKl + offB);
                mma_bf16(sacc[2 * np],     qf_h[ks], th);
                mma_bf16(sacc[2 * np],     qf_h[ks], tl);
                mma_bf16(sacc[2 * np],     qf_l[ks], th);
                mma_bf16(sacc[2 * np + 1], qf_h[ks], th + 2);
                mma_bf16(sacc[2 * np + 1], qf_h[ks], tl + 2);
                mma_bf16(sacc[2 * np + 1], qf_l[ks], th + 2);
            }
        }
#pragma unroll
        for (int nt = 0; nt < 8; nt++)
#pragma unroll
            for (int e = 0; e < 4; e++) sacc[nt][e] *= ATTN_SCALE;

        // ---- register softmax (rows r0 = lane>>2, r1 = r0+8) ----
        float mx0 = -1e30f, mx1 = -1e30f;
#pragma unroll
        for (int nt = 0; nt < 8; nt++) {
            mx0 = fmaxf(mx0, fmaxf(sacc[nt][0], sacc[nt][1]));
            mx1 = fmaxf(mx1, fmaxf(sacc[nt][2], sacc[nt][3]));
        }
        mx0 = fmaxf(mx0, __shfl_xor_sync(0xffffffffu, mx0, 1));
        mx0 = fmaxf(mx0, __shfl_xor_sync(0xffffffffu, mx0, 2));
        mx1 = fmaxf(mx1, __shfl_xor_sync(0xffffffffu, mx1, 1));
        mx1 = fmaxf(mx1, __shfl_xor_sync(0xffffffffu, mx1, 2));
        const float mn0 = fmaxf(m_r0, mx0), mn1 = fmaxf(m_r1, mx1);
        const float cf0 = __expf(m_r0 - mn0), cf1 = __expf(m_r1 - mn1);
        float sum0 = 0.f, sum1 = 0.f;
#pragma unroll
        for (int nt = 0; nt < 8; nt++) {
            sacc[nt][0] = __expf(sacc[nt][0] - mn0);
            sacc[nt][1] = __expf(sacc[nt][1] - mn0);
            sacc[nt][2] = __expf(sacc[nt][2] - mn1);
            sacc[nt][3] = __expf(sacc[nt][3] - mn1);
            sum0 += sacc[nt][0] + sacc[nt][1];
            sum1 += sacc[nt][2] + sacc[nt][3];
        }
        sum0 += __shfl_xor_sync(0xffffffffu, sum0, 1);
        sum0 += __shfl_xor_sync(0xffffffffu, sum0, 2);
        sum1 += __shfl_xor_sync(0xffffffffu, sum1, 1);
        sum1 += __shfl_xor_sync(0xffffffffu, sum1, 2);
        l_r0 = l_r0 * cf0 + sum0;  m_r0 = mn0;
        l_r1 = l_r1 * cf1 + sum1;  m_r1 = mn1;

#pragma unroll
        for (int nt = 0; nt < 8; nt++) {
            oacc[nt][0] *= cf0; oacc[nt][1] *= cf0;
            oacc[nt][2] *= cf1; oacc[nt][3] *= cf1;
        }

        // ---- O += P @ V (P from sacc; V frags via ldmatrix.x4.trans) ----
#pragma unroll
        for (int ks = 0; ks < 4; ks++) {
            uint32_t ap_h[4], ap_l[4];
            {
                __nv_bfloat162 h0, l0;
                split2(sacc[2 * ks][0], h0.x, l0.x);
                split2(sacc[2 * ks][1], h0.y, l0.y);
                ap_h[0] = *(uint32_t*)&h0; ap_l[0] = *(uint32_t*)&l0;
                split2(sacc[2 * ks][2], h0.x, l0.x);
                split2(sacc[2 * ks][3], h0.y, l0.y);
                ap_h[1] = *(uint32_t*)&h0; ap_l[1] = *(uint32_t*)&l0;
                split2(sacc[2 * ks + 1][0], h0.x, l0.x);
                split2(sacc[2 * ks + 1][1], h0.y, l0.y);
                ap_h[2] = *(uint32_t*)&h0; ap_l[2] = *(uint32_t*)&l0;
                split2(sacc[2 * ks + 1][2], h0.x, l0.x);
                split2(sacc[2 * ks + 1][3], h0.y, l0.y);
                ap_h[3] = *(uint32_t*)&h0; ap_l[3] = *(uint32_t*)&l0;
            }
            // x4.trans: lanes 0-15 cover rows k0..k0+15 at col base, lanes 16-31
            // the same rows at col base+8 -> r0,r1 = B-frag(nt=2*ntp), r2,r3 = nt+1
            const uint32_t rowv = (uint32_t)(ks * 16 + (lane & 15)) * (AST * 2)
                                + ((lane >> 4) << 4);
#pragma unroll
            for (int ntp = 0; ntp < 4; ntp++) {
                uint32_t vh[4], vl[4];
                const uint32_t offB = rowv + ntp * 32;
                ldsm_x4t(vh, bVh + offB);
                ldsm_x4t(vl, bVl + offB);
                mma_bf16(oacc[2 * ntp],     ap_h, vh);
                mma_bf16(oacc[2 * ntp],     ap_h, vl);
                mma_bf16(oacc[2 * ntp],     ap_l, vh);
                mma_bf16(oacc[2 * ntp + 1], ap_h, vh + 2);
                mma_bf16(oacc[2 * ntp + 1], ap_h, vl + 2);
                mma_bf16(oacc[2 * ntp + 1], ap_l, vh + 2);
            }
        }
        __syncthreads();
        if (kt + 2 < 32) issueKV(kt + 2, kt & 1);
        CP_COMMIT();
    }

    // ---- epilogue ----
    const float inv0 = 1.f / l_r0, inv1 = 1.f / l_r1;
#pragma unroll
    for (int nt = 0; nt < 8; nt++) {
#pragma unroll
        for (int hh = 0; hh < 2; hh++) {
            const int rloc = m0 + hh * 8 + (lane >> 2);
            const float inv = hh ? inv1 : inv0;
            float v0 = oacc[nt][2 * hh] * inv;
            float v1 = oacc[nt][2 * hh + 1] * inv;
            size_t base = (size_t)(qrow0 + rloc) * DMODEL + h * 64
                        + nt * 8 + (lane & 3) * 2;
            __nv_bfloat162 hp, lp;
            split2(v0, hp.x, lp.x);
            split2(v1, hp.y, lp.y);
            *(__nv_bfloat162*)(ohi + base) = hp;
            *(__nv_bfloat162*)(olo + base) = lp;
        }
    }
}

// ---------------------------------------------------------------------------
// LayerNorm (rows of 512).
// ---------------------------------------------------------------------------
__global__ void __launch_bounds__(128)
ln_kernel(const float* __restrict__ x, const float* __restrict__ g,
          const float* __restrict__ bta, float* __restrict__ yf,
          __nv_bfloat16* __restrict__ yh, __nv_bfloat16* __restrict__ yl)
{
    __shared__ float sbuf[4];
    const int row = blockIdx.x;
    const int tid = threadIdx.x;
    const float* xr = x + (size_t)row * DMODEL;
    float4 v = *(const float4*)(xr + tid * 4);

    float s = v.x + v.y + v.z + v.w;
#pragma unroll
    for (int off = 16; off > 0; off >>= 1) s += __shfl_xor_sync(0xffffffffu, s, off);
    if ((tid & 31) == 0) sbuf[tid >> 5] = s;
    __syncthreads();
    float mean = (sbuf[0] + sbuf[1] + sbuf[2] + sbuf[3]) * (1.f / 512.f);

    float dx = v.x - mean, dy = v.y - mean, dz = v.z - mean, dw = v.w - mean;
    float s2 = dx * dx + dy * dy + dz * dz + dw * dw;
#pragma unroll
    for (int off = 16; off > 0; off >>= 1) s2 += __shfl_xor_sync(0xffffffffu, s2, off);
    __syncthreads();
    if ((tid & 31) == 0) sbuf[tid >> 5] = s2;
    __syncthreads();
    float var = (sbuf[0] + sbuf[1] + sbuf[2] + sbuf[3]) * (1.f / 512.f);
    float inv = rsqrtf(var + LN_EPS);

    float4 gg = *(const float4*)(g + tid * 4);
    float4 bb = *(const float4*)(bta + tid * 4);
    float o0 = dx * inv * gg.x + bb.x;
    float o1 = dy * inv * gg.y + bb.y;
    float o2 = dz * inv * gg.z + bb.z;
    float o3 = dw * inv * gg.w + bb.w;
    size_t base = (size_t)row * DMODEL + tid * 4;
    if (yf) {
        float4 o = {o0, o1, o2, o3};
        *(float4*)(yf + base) = o;
    }
    if (yh) {
        __nv_bfloat162 h01, h23, l01, l23;
        split2(o0, h01.x, l01.x); split2(o1, h01.y, l01.y);
        split2(o2, h23.x, l23.x); split2(o3, h23.y, l23.y);
        *(__nv_bfloat162*)(yh + base)     = h01;
        *(__nv_bfloat162*)(yh + base + 2) = h23;
        *(__nv_bfloat162*)(yl + base)     = l01;
        *(__nv_bfloat162*)(yl + base + 2) = l23;
    }
}

// ---------------------------------------------------------------------------
extern "C" void kernel_launch(void* const* d_in, const int* in_sizes, int n_in,
                              void* d_out, int out_size)
{
    const float* X     = (const float*)d_in[0];
    const float* qkv_w = (const float*)d_in[1];
    const float* qkv_b = (const float*)d_in[2];
    const float* fc_w  = (const float*)d_in[3];
    const float* fc_b  = (const float*)d_in[4];
    const float* ln1_g = (const float*)d_in[5];
    const float* ln1_b = (const float*)d_in[6];
    const float* w1    = (const float*)d_in[7];
    const float* b1    = (const float*)d_in[8];
    const float* w2    = (const float*)d_in[9];
    const float* b2    = (const float*)d_in[10];
    const float* ln2_g = (const float*)d_in[11];
    const float* ln2_b = (const float*)d_in[12];
    float* out = (float*)d_out;

    float *x, *x1, *x2;
    __nv_bfloat16 *ctx_hi, *ctx_lo, *attn_hi, *attn_lo, *x_hi, *x_lo;
    __nv_bfloat16 *xn_hi, *xn_lo, *h_hi, *h_lo;
    __nv_bfloat16 *qkvT_hi, *qkvT_lo, *fcT_hi, *fcT_lo, *w1T_hi, *w1T_lo, *w2T_hi, *w2T_lo;
    cudaGetSymbolAddress((void**)&ctx_hi,  g_ctx_hi);
    cudaGetSymbolAddress((void**)&ctx_lo,  g_ctx_lo);
    cudaGetSymbolAddress((void**)&attn_hi, g_attn_hi);
    cudaGetSymbolAddress((void**)&attn_lo, g_attn_lo);
    cudaGetSymbolAddress((void**)&x,       g_x);
    cudaGetSymbolAddress((void**)&x1,      g_x1);
    cudaGetSymbolAddress((void**)&x2,      g_x2);
    cudaGetSymbolAddress((void**)&x_hi,    g_x_hi);
    cudaGetSymbolAddress((void**)&x_lo,    g_x_lo);
    cudaGetSymbolAddress((void**)&xn_hi,   g_xn_hi);
    cudaGetSymbolAddress((void**)&xn_lo,   g_xn_lo);
    cudaGetSymbolAddress((void**)&h_hi,    g_h_hi);
    cudaGetSymbolAddress((void**)&h_lo,    g_h_lo);
    cudaGetSymbolAddress((void**)&qkvT_hi, g_qkvT_hi);
    cudaGetSymbolAddress((void**)&qkvT_lo, g_qkvT_lo);
    cudaGetSymbolAddress((void**)&fcT_hi,  g_fcT_hi);
    cudaGetSymbolAddress((void**)&fcT_lo,  g_fcT_lo);
    cudaGetSymbolAddress((void**)&w1T_hi,  g_w1T_hi);
    cudaGetSymbolAddress((void**)&w1T_lo,  g_w1T_lo);
    cudaGetSymbolAddress((void**)&w2T_hi,  g_w2T_hi);
    cudaGetSymbolAddress((void**)&w2T_lo,  g_w2T_lo);

    cudaFuncSetAttribute(attn_kernel, cudaFuncAttributeMaxDynamicSharedMemorySize,
                         ATTN_SMEM_BYTES);
    cudaFuncSetAttribute(gemm_mma<false, false, false, true>,
                         cudaFuncAttributeMaxDynamicSharedMemorySize, G_SMEM);
    cudaFuncSetAttribute(gemm_mma<false, true, true, false>,
                         cudaFuncAttributeMaxDynamicSharedMemorySize, G_SMEM);
    cudaFuncSetAttribute(gemm_mma<true, false, false, true>,
                         cudaFuncAttributeMaxDynamicSharedMemorySize, G_SMEM);

    transpose_split_l<<<dim3(CTXW / 32, DMODEL / 32, NB), dim3(32, 8)>>>(
        qkv_w, qkvT_hi, qkvT_lo, DMODEL, CTXW);
    transpose_split_l<<<dim3(DMODEL / 32, DMODEL / 32, NB), dim3(32, 8)>>>(
        fc_w, fcT_hi, fcT_lo, DMODEL, DMODEL);
    transpose_split_l<<<dim3(DHID / 32, DMODEL / 32, NB), dim3(32, 8)>>>(
        w1, w1T_hi, w1T_lo, DMODEL, DHID);
    transpose_split_l<<<dim3(DMODEL / 32, DHID / 32, NB), dim3(32, 8)>>>(
        w2, w2T_hi, w2T_lo, DHID, DMODEL);

    split_hilo<<<(ROWS * DMODEL + 255) / 256, 256>>>(X, x_hi, x_lo, ROWS * DMODEL);

    const float* xcur_f = X;

    for (int i = 0; i < NB; i++) {
        const size_t oq = (size_t)i * CTXW * DMODEL;
        const size_t of = (size_t)i * DMODEL * DMODEL;
        const size_t o1 = (size_t)i * DHID * DMODEL;
        const size_t o2 = (size_t)i * DMODEL * DHID;

        // 1) ctx = x @ qkv_w + qkv_b -> bf16 hi/lo
        gemm_mma<false, false, false, true>
            <<<dim3(CTXW / 128, ROWS / 128), 256, G_SMEM>>>(
            x_hi, x_lo, qkvT_hi + oq, qkvT_lo + oq, qkv_b + (size_t)i * CTXW,
            nullptr, nullptr, ctx_hi, ctx_lo, CTXW, DMODEL);

        // 2) attention -> bf16 hi/lo
        attn_kernel<<<dim3(SEQ / 128, BATCH * NH), 256, ATTN_SMEM_BYTES>>>(
            ctx_hi, ctx_lo, attn_hi, attn_lo);

        // 3) x1 = attn @ fc_w + fc_b + xcur (fp32)
        gemm_mma<false, true, true, false>
            <<<dim3(DMODEL / 128, ROWS / 128), 256, G_SMEM>>>(
            attn_hi, attn_lo, fcT_hi + of, fcT_lo + of, fc_b + (size_t)i * DMODEL,
            xcur_f, x1, nullptr, nullptr, DMODEL, DMODEL);

        // 4) xn = LN1(x1) -> hi/lo only
        ln_kernel<<<ROWS, 128>>>(x1, ln1_g + (size_t)i * DMODEL,
                                 ln1_b + (size_t)i * DMODEL, nullptr, xn_hi, xn_lo);

        // 5) h = relu(xn @ w1 + b1) -> hi/lo
        gemm_mma<true, false, false, true>
            <<<dim3(DHID / 128, ROWS / 128), 256, G_SMEM>>>(
            xn_hi, xn_lo, w1T_hi + o1, w1T_lo + o1, b1 + (size_t)i * DHID,
            nullptr, nullptr, h_hi, h_lo, DHID, DMODEL);

        // 6) x2 = h @ w2 + b2 + x1 (fp32)
        gemm_mma<false, true, true, false>
            <<<dim3(DMODEL / 128, ROWS / 128), 256, G_SMEM>>>(
            h_hi, h_lo, w2T_hi + o2, w2T_lo + o2, b2 + (size_t)i * DMODEL,
            x1, x2, nullptr, nullptr, DMODEL, DHID);

        // 7) carry = LN2(x2)
        float* dstf = (i == NB - 1) ? out : x;
        __nv_bfloat16* nh = (i == NB - 1) ? nullptr : x_hi;
        __nv_bfloat16* nl = (i == NB - 1) ? nullptr : x_lo;
        ln_kernel<<<ROWS, 128>>>(x2, ln2_g + (size_t)i * DMODEL,
                                 ln2_b + (size_t)i * DMODEL, dstf, nh, nl);
        xcur_f = dstf;
    }
}

// round 9
// speedup vs baseline: 3.1160x; 1.0057x over previous
#include <cuda_runtime.h>
#include <cuda_bf16.h>
#include <cstdint>
#include <cstddef>

// ---------------------------------------------------------------------------
// Encoder: 12 x (QKV -> MHA -> proj+res -> LN1 -> MLP(relu) -> +res -> LN2)
// B=2, S=2048, D=512, H=8, DH=64, DHID=1024, fp32 in/out.
// All matmuls mma.sync bf16 (HMMA) hi/lo split (3 MMAs) ~ fp32 accuracy.
// R9: GEMM BK=64 2-stage (800cyc lead, half the syncs);
//     attention 3-stage KV pipeline (2-iteration lead).
// ---------------------------------------------------------------------------

#define NB     12
#define DMODEL 512
#define NH     8
#define DHEAD  64
#define DHID   1024
#define BATCH  2
#define SEQ    2048
#define ROWS   (BATCH * SEQ)     // 4096
#define CTXW   (3 * DMODEL)      // 1536
#define LN_EPS 1e-5f
#define ATTN_SCALE 0.044194173824159216f  // 1/sqrt(512)

// ----------------------------- PTX helpers ---------------------------------
__device__ __forceinline__ uint32_t smem_u32(const void* p) {
    uint32_t a;
    asm("{ .reg .u64 t; cvta.to.shared.u64 t, %1; cvt.u32.u64 %0, t; }"
        : "=r"(a) : "l"(p));
    return a;
}
__device__ __forceinline__ void ldsm_x4(uint32_t* r, uint32_t a) {
    asm volatile("ldmatrix.sync.aligned.m8n8.x4.shared.b16 {%0,%1,%2,%3}, [%4];"
        : "=r"(r[0]), "=r"(r[1]), "=r"(r[2]), "=r"(r[3]) : "r"(a));
}
__device__ __forceinline__ void ldsm_x4t(uint32_t* r, uint32_t a) {
    asm volatile("ldmatrix.sync.aligned.m8n8.x4.trans.shared.b16 {%0,%1,%2,%3}, [%4];"
        : "=r"(r[0]), "=r"(r[1]), "=r"(r[2]), "=r"(r[3]) : "r"(a));
}
__device__ __forceinline__ void mma_bf16(float* c, const uint32_t* a, const uint32_t* b) {
    asm volatile("mma.sync.aligned.m16n8k16.row.col.f32.bf16.bf16.f32 "
        "{%0,%1,%2,%3}, {%4,%5,%6,%7}, {%8,%9}, {%0,%1,%2,%3};"
        : "+f"(c[0]), "+f"(c[1]), "+f"(c[2]), "+f"(c[3])
        : "r"(a[0]), "r"(a[1]), "r"(a[2]), "r"(a[3]), "r"(b[0]), "r"(b[1]));
}
__device__ __forceinline__ void split2(float v, __nv_bfloat16& h, __nv_bfloat16& l) {
    h = __float2bfloat16(v);
    l = __float2bfloat16(v - __bfloat162float(h));
}
__device__ __forceinline__ void cp16(uint32_t dst, const void* src) {
    asm volatile("cp.async.cg.shared.global [%0], [%1], 16;"
                 :: "r"(dst), "l"(src) : "memory");
}
#define CP_COMMIT() asm volatile("cp.async.commit_group;" ::: "memory")
#define CP_WAIT1()  asm volatile("cp.async.wait_group 1;"  ::: "memory")
#define CP_WAIT2()  asm volatile("cp.async.wait_group 2;"  ::: "memory")

// ------------------------- scratch (no allocation) -------------------------
__device__ __nv_bfloat16 g_ctx_hi[ROWS * CTXW];
__device__ __nv_bfloat16 g_ctx_lo[ROWS * CTXW];
__device__ __nv_bfloat16 g_attn_hi[ROWS * DMODEL];
__device__ __nv_bfloat16 g_attn_lo[ROWS * DMODEL];
__device__ float         g_x   [ROWS * DMODEL];
__device__ __nv_bfloat16 g_x_hi[ROWS * DMODEL];
__device__ __nv_bfloat16 g_x_lo[ROWS * DMODEL];
__device__ float         g_x1  [ROWS * DMODEL];
__device__ __nv_bfloat16 g_xn_hi[ROWS * DMODEL];
__device__ __nv_bfloat16 g_xn_lo[ROWS * DMODEL];
__device__ __nv_bfloat16 g_h_hi[ROWS * DHID];
__device__ __nv_bfloat16 g_h_lo[ROWS * DHID];
__device__ float         g_x2  [ROWS * DMODEL];
__device__ __nv_bfloat16 g_qkvT_hi[NB * CTXW * DMODEL],  g_qkvT_lo[NB * CTXW * DMODEL];
__device__ __nv_bfloat16 g_fcT_hi [NB * DMODEL * DMODEL], g_fcT_lo[NB * DMODEL * DMODEL];
__device__ __nv_bfloat16 g_w1T_hi [NB * DHID * DMODEL],   g_w1T_lo[NB * DHID * DMODEL];
__device__ __nv_bfloat16 g_w2T_hi [NB * DMODEL * DHID],   g_w2T_lo[NB * DMODEL * DHID];

// ---------------------------------------------------------------------------
// mma GEMM, cp.async 2-stage pipeline, BK=64.
// C[M,N] = A[M,K] @ W[K,N] (+bias)(+res)(relu); A hi/lo [M][K], W^T hi/lo [N][K].
// 128x128 tile, 8 warps (warp tile 32x64). Stage: Ah|Al|Bh|Bl, 18432B each.
// ---------------------------------------------------------------------------
#define GS2   72                    // smem row stride in bf16 (144B)
#define G_MAT 18432                 // one matrix: 128 rows x 144B
#define G_STG (4 * G_MAT)           // 73728
#define G_SMEM (2 * G_STG)          // 147456

template <bool RELU, bool RES, bool WF32, bool WHILO>
__global__ void __launch_bounds__(256)
gemm_mma(const __nv_bfloat16* __restrict__ Ahi, const __nv_bfloat16* __restrict__ Alo,
         const __nv_bfloat16* __restrict__ Bhi, const __nv_bfloat16* __restrict__ Blo,
         const float* __restrict__ bias, const float* __restrict__ res,
         float* __restrict__ Cf, __nv_bfloat16* __restrict__ Chi,
         __nv_bfloat16* __restrict__ Clo, int N, int K)
{
    extern __shared__ char dsm[];
    const uint32_t sb = smem_u32(dsm);

    const int tid  = threadIdx.x;
    const int lane = tid & 31, wid = tid >> 5;
    const int g = lane >> 3, rq = lane & 7;
    const int brow = blockIdx.y * 128, bcol = blockIdx.x * 128;
    const int m0 = (wid & 3) * 32, n0 = (wid >> 2) * 64;

    float acc[2][8][4];
#pragma unroll
    for (int mt = 0; mt < 2; mt++)
#pragma unroll
        for (int nt = 0; nt < 8; nt++)
#pragma unroll
            for (int e = 0; e < 4; e++) acc[mt][nt][e] = 0.f;

    const int NT = K >> 6;

    // chunk c (64 k) -> buffer buf; 128 rows x 8 segs per matrix, 4 iters
    auto issue = [&](int c, int buf) {
        const uint32_t st = sb + buf * G_STG;
#pragma unroll
        for (int t = 0; t < 4; t++) {
            const int idx = tid + t * 256;
            const int row = idx >> 3, seg = (idx & 7) * 8;
            const uint32_t so = (uint32_t)(row * GS2 + seg) * 2;
            const size_t ga = (size_t)(brow + row) * K + c * 64 + seg;
            const size_t gb = (size_t)(bcol + row) * K + c * 64 + seg;
            cp16(st + so,             Ahi + ga);
            cp16(st + G_MAT + so,     Alo + ga);
            cp16(st + 2 * G_MAT + so, Bhi + gb);
            cp16(st + 3 * G_MAT + so, Blo + gb);
        }
    };

    issue(0, 0); CP_COMMIT();
    issue(1, 1); CP_COMMIT();

    for (int c = 0; c < NT; c++) {
        CP_WAIT1();
        __syncthreads();
        const uint32_t st = sb + (c & 1) * G_STG;
        const uint32_t bAh = st, bAl = st + G_MAT;
        const uint32_t bBh = st + 2 * G_MAT, bBl = st + 3 * G_MAT;
#pragma unroll
        for (int ks = 0; ks < 4; ks++) {
            const int k0 = ks * 16;
            uint32_t ah[2][4], al[2][4];
#pragma unroll
            for (int mt = 0; mt < 2; mt++) {
                uint32_t off = (uint32_t)(m0 + mt * 16 + (g & 1) * 8 + rq) * (GS2 * 2)
                             + (k0 + (g >> 1) * 8) * 2;
                ldsm_x4(ah[mt], bAh + off);
                ldsm_x4(al[mt], bAl + off);
            }
            uint32_t bh[8][2], bl[8][2];
#pragma unroll
            for (int np = 0; np < 4; np++) {
                uint32_t off = (uint32_t)(n0 + np * 16 + (g >> 1) * 8 + rq) * (GS2 * 2)
                             + (k0 + (g & 1) * 8) * 2;
                uint32_t tmp[4];
                ldsm_x4(tmp, bBh + off);
                bh[2 * np][0] = tmp[0]; bh[2 * np][1] = tmp[1];
                bh[2 * np + 1][0] = tmp[2]; bh[2 * np + 1][1] = tmp[3];
                ldsm_x4(tmp, bBl + off);
                bl[2 * np][0] = tmp[0]; bl[2 * np][1] = tmp[1];
                bl[2 * np + 1][0] = tmp[2]; bl[2 * np + 1][1] = tmp[3];
            }
#pragma unroll
            for (int mt = 0; mt < 2; mt++)
#pragma unroll
                for (int nt = 0; nt < 8; nt++) {
                    mma_bf16(acc[mt][nt], ah[mt], bh[nt]);
                    mma_bf16(acc[mt][nt], ah[mt], bl[nt]);
                    mma_bf16(acc[mt][nt], al[mt], bh[nt]);
                }
        }
        __syncthreads();
        if (c + 2 < NT) issue(c + 2, c & 1);
        CP_COMMIT();
    }

#pragma unroll
    for (int mt = 0; mt < 2; mt++)
#pragma unroll
        for (int nt = 0; nt < 8; nt++) {
            const int row0 = brow + m0 + mt * 16 + (lane >> 2);
            const int col  = bcol + n0 + nt * 8 + (lane & 3) * 2;
            float2 bv = *(const float2*)(bias + col);
#pragma unroll
            for (int hh = 0; hh < 2; hh++) {
                const int row = row0 + hh * 8;
                float v0 = acc[mt][nt][2 * hh]     + bv.x;
                float v1 = acc[mt][nt][2 * hh + 1] + bv.y;
                if (RES) {
                    float2 rv = *(const float2*)(res + (size_t)row * N + col);
                    v0 += rv.x; v1 += rv.y;
                }
                if (RELU) { v0 = fmaxf(v0, 0.f); v1 = fmaxf(v1, 0.f); }
                if (WF32) {
                    float2 o = {v0, v1};
                    *(float2*)(Cf + (size_t)row * N + col) = o;
                }
                if (WHILO) {
                    __nv_bfloat162 hp, lp;
                    split2(v0, hp.x, lp.x);
                    split2(v1, hp.y, lp.y);
                    *(__nv_bfloat162*)(Chi + (size_t)row * N + col) = hp;
                    *(__nv_bfloat162*)(Clo + (size_t)row * N + col) = lp;
                }
            }
        }
}

// ---------------------------------------------------------------------------
// Weight transpose+split for ALL layers (blockIdx.z = layer).
// ---------------------------------------------------------------------------
__global__ void __launch_bounds__(256)
transpose_split_l(const float* __restrict__ in, __nv_bfloat16* __restrict__ oh,
                  __nv_bfloat16* __restrict__ ol, int K, int N)
{
    __shared__ float t[32][33];
    const size_t zoff = (size_t)blockIdx.z * K * N;
    const float* src = in + zoff;
    const int n0 = blockIdx.x * 32, k0 = blockIdx.y * 32;
    const int tx = threadIdx.x, ty = threadIdx.y;   // 32 x 8
#pragma unroll
    for (int i = 0; i < 32; i += 8)
        t[ty + i][tx] = src[(size_t)(k0 + ty + i) * N + n0 + tx];
    __syncthreads();
#pragma unroll
    for (int i = 0; i < 32; i += 8) {
        float v = t[tx][ty + i];
        size_t o = zoff + (size_t)(n0 + ty + i) * K + k0 + tx;
        __nv_bfloat16 h, l;
        split2(v, h, l);
        oh[o] = h; ol[o] = l;
    }
}

__global__ void __launch_bounds__(256)
split_hilo(const float* __restrict__ x, __nv_bfloat16* __restrict__ h,
           __nv_bfloat16* __restrict__ l, int n)
{
    int i = blockIdx.x * 256 + threadIdx.x;
    if (i < n) {
        __nv_bfloat16 hv, lv;
        split2(x[i], hv, lv);
        h[i] = hv; l[i] = lv;
    }
}

// ---------------------------------------------------------------------------
// Attention, register-resident flash, cp.async 3-stage KV pipeline.
// No Q smem (direct-fragment LDG); smem = 3 KV stages = 108KB; 2 CTAs/SM goal.
// CTA = 128 q-rows x one (b,h); warp w owns q rows [w*16,w*16+16) x all 64 keys.
// ---------------------------------------------------------------------------
#define AST 72
#define A_KVB 9216                  // one K/V matrix (64 x 144B)
#define A_STG (4 * A_KVB)           // 36864
#define ATTN_SMEM_BYTES (3 * A_STG) // 110592

__global__ void __launch_bounds__(256, 2)
attn_kernel(const __nv_bfloat16* __restrict__ cxh, const __nv_bfloat16* __restrict__ cxl,
            __nv_bfloat16* __restrict__ ohi, __nv_bfloat16* __restrict__ olo)
{
    extern __shared__ char smc[];
    const uint32_t sb = smem_u32(smc);

    const int tid  = threadIdx.x;
    const int lane = tid & 31, wid = tid >> 5;
    const int g = lane >> 3, rq = lane & 7;
    const int b = blockIdx.y >> 3, h = blockIdx.y & 7;
    const int qrow0 = b * SEQ + blockIdx.x * 128;
    const int krowb = b * SEQ;
    const int qc = h * 192, kc = qc + 64, vc = qc + 128;

    const int m0 = wid * 16;
    const int lrow = tid >> 3, lseg = (tid & 7) * 8;   // KV loader

    auto issueKV = [&](int kt, int buf) {
        const int krow0 = krowb + kt * 64;
        const uint32_t st = sb + buf * A_STG;
#pragma unroll
        for (int t = 0; t < 2; t++) {
            const int row = lrow + t * 32;
            const uint32_t so = (uint32_t)(row * AST + lseg) * 2;
            const size_t gk = (size_t)(krow0 + row) * CTXW + kc + lseg;
            const size_t gv = (size_t)(krow0 + row) * CTXW + vc + lseg;
            cp16(st + so,             cxh + gk);
            cp16(st + A_KVB + so,     cxl + gk);
            cp16(st + 2 * A_KVB + so, cxh + gv);
            cp16(st + 3 * A_KVB + so, cxl + gv);
        }
    };

    issueKV(0, 0); CP_COMMIT();
    issueKV(1, 1); CP_COMMIT();
    issueKV(2, 2); CP_COMMIT();

    // ---- Q fragments directly from gmem (canonical m16n8k16 A layout) ----
    uint32_t qf_h[4][4], qf_l[4][4];
    {
        const size_t r0 = (size_t)(qrow0 + m0 + (lane >> 2)) * CTXW;
        const size_t r1 = r0 + (size_t)8 * CTXW;
        const int c0 = qc + (lane & 3) * 2;
#pragma unroll
        for (int ks = 0; ks < 4; ks++) {
            const int c = c0 + ks * 16;
            qf_h[ks][0] = *(const uint32_t*)(cxh + r0 + c);
            qf_h[ks][1] = *(const uint32_t*)(cxh + r1 + c);
            qf_h[ks][2] = *(const uint32_t*)(cxh + r0 + c + 8);
            qf_h[ks][3] = *(const uint32_t*)(cxh + r1 + c + 8);
            qf_l[ks][0] = *(const uint32_t*)(cxl + r0 + c);
            qf_l[ks][1] = *(const uint32_t*)(cxl + r1 + c);
            qf_l[ks][2] = *(const uint32_t*)(cxl + r0 + c + 8);
            qf_l[ks][3] = *(const uint32_t*)(cxl + r1 + c + 8);
        }
    }

    float m_r0 = -1e30f, m_r1 = -1e30f, l_r0 = 0.f, l_r1 = 0.f;
    float oacc[8][4];
#pragma unroll
    for (int nt = 0; nt < 8; nt++)
#pragma unroll
        for (int e = 0; e < 4; e++) oacc[nt][e] = 0.f;

    int buf = 0;
    for (int kt = 0; kt < 32; kt++) {
        CP_WAIT2();
        __syncthreads();
        const uint32_t st = sb + buf * A_STG;
        const uint32_t bKh = st, bKl = st + A_KVB;
        const uint32_t bVh = st + 2 * A_KVB, bVl = st + 3 * A_KVB;

        // ---- S = Q @ K^T ----
        float sacc[8][4];
#pragma unroll
        for (int nt = 0; nt < 8; nt++)
#pragma unroll
            for (int e = 0; e < 4; e++) sacc[nt][e] = 0.f;
#pragma unroll
        for (int ks = 0; ks < 4; ks++) {
#pragma unroll
            for (int np = 0; np < 4; np++) {
                uint32_t offB = (uint32_t)(np * 16 + (g >> 1) * 8 + rq) * (AST * 2)
                              + (ks * 16 + (g & 1) * 8) * 2;
                uint32_t th[4], tl[4];
                ldsm_x4(th, bKh + offB);
                ldsm_x4(tl, bKl + offB);
                mma_bf16(sacc[2 * np],     qf_h[ks], th);
                mma_bf16(sacc[2 * np],     qf_h[ks], tl);
                mma_bf16(sacc[2 * np],     qf_l[ks], th);
                mma_bf16(sacc[2 * np + 1], qf_h[ks], th + 2);
                mma_bf16(sacc[2 * np + 1], qf_h[ks], tl + 2);
                mma_bf16(sacc[2 * np + 1], qf_l[ks], th + 2);
            }
        }
#pragma unroll
        for (int nt = 0; nt < 8; nt++)
#pragma unroll
            for (int e = 0; e < 4; e++) sacc[nt][e] *= ATTN_SCALE;

        // ---- register softmax (rows r0 = lane>>2, r1 = r0+8) ----
        float mx0 = -1e30f, mx1 = -1e30f;
#pragma unroll
        for (int nt = 0; nt < 8; nt++) {
            mx0 = fmaxf(mx0, fmaxf(sacc[nt][0], sacc[nt][1]));
            mx1 = fmaxf(mx1, fmaxf(sacc[nt][2], sacc[nt][3]));
        }
        mx0 = fmaxf(mx0, __shfl_xor_sync(0xffffffffu, mx0, 1));
        mx0 = fmaxf(mx0, __shfl_xor_sync(0xffffffffu, mx0, 2));
        mx1 = fmaxf(mx1, __shfl_xor_sync(0xffffffffu, mx1, 1));
        mx1 = fmaxf(mx1, __shfl_xor_sync(0xffffffffu, mx1, 2));
        const float mn0 = fmaxf(m_r0, mx0), mn1 = fmaxf(m_r1, mx1);
        const float cf0 = __expf(m_r0 - mn0), cf1 = __expf(m_r1 - mn1);
        float sum0 = 0.f, sum1 = 0.f;
#pragma unroll
        for (int nt = 0; nt < 8; nt++) {
            sacc[nt][0] = __expf(sacc[nt][0] - mn0);
            sacc[nt][1] = __expf(sacc[nt][1] - mn0);
            sacc[nt][2] = __expf(sacc[nt][2] - mn1);
            sacc[nt][3] = __expf(sacc[nt][3] - mn1);
            sum0 += sacc[nt][0] + sacc[nt][1];
            sum1 += sacc[nt][2] + sacc[nt][3];
        }
        sum0 += __shfl_xor_sync(0xffffffffu, sum0, 1);
        sum0 += __shfl_xor_sync(0xffffffffu, sum0, 2);
        sum1 += __shfl_xor_sync(0xffffffffu, sum1, 1);
        sum1 += __shfl_xor_sync(0xffffffffu, sum1, 2);
        l_r0 = l_r0 * cf0 + sum0;  m_r0 = mn0;
        l_r1 = l_r1 * cf1 + sum1;  m_r1 = mn1;

#pragma unroll
        for (int nt = 0; nt < 8; nt++) {
            oacc[nt][0] *= cf0; oacc[nt][1] *= cf0;
            oacc[nt][2] *= cf1; oacc[nt][3] *= cf1;
        }

        // ---- O += P @ V (P from sacc; V frags via ldmatrix.x4.trans) ----
#pragma unroll
        for (int ks = 0; ks < 4; ks++) {
            uint32_t ap_h[4], ap_l[4];
            {
                __nv_bfloat162 h0, l0;
                split2(sacc[2 * ks][0], h0.x, l0.x);
                split2(sacc[2 * ks][1], h0.y, l0.y);
                ap_h[0] = *(uint32_t*)&h0; ap_l[0] = *(uint32_t*)&l0;
                split2(sacc[2 * ks][2], h0.x, l0.x);
                split2(sacc[2 * ks][3], h0.y, l0.y);
                ap_h[1] = *(uint32_t*)&h0; ap_l[1] = *(uint32_t*)&l0;
                split2(sacc[2 * ks + 1][0], h0.x, l0.x);
                split2(sacc[2 * ks + 1][1], h0.y, l0.y);
                ap_h[2] = *(uint32_t*)&h0; ap_l[2] = *(uint32_t*)&l0;
                split2(sacc[2 * ks + 1][2], h0.x, l0.x);
                split2(sacc[2 * ks + 1][3], h0.y, l0.y);
                ap_h[3] = *(uint32_t*)&h0; ap_l[3] = *(uint32_t*)&l0;
            }
            const uint32_t rowv = (uint32_t)(ks * 16 + (lane & 15)) * (AST * 2)
                                + ((lane >> 4) << 4);
#pragma unroll
            for (int ntp = 0; ntp < 4; ntp++) {
                uint32_t vh[4], vl[4];
                const uint32_t offB = rowv + ntp * 32;
                ldsm_x4t(vh, bVh + offB);
                ldsm_x4t(vl, bVl + offB);
                mma_bf16(oacc[2 * ntp],     ap_h, vh);
                mma_bf16(oacc[2 * ntp],     ap_h, vl);
                mma_bf16(oacc[2 * ntp],     ap_l, vh);
                mma_bf16(oacc[2 * ntp + 1], ap_h, vh + 2);
                mma_bf16(oacc[2 * ntp + 1], ap_h, vl + 2);
                mma_bf16(oacc[2 * ntp + 1], ap_l, vh + 2);
            }
        }
        __syncthreads();
        if (kt + 3 < 32) issueKV(kt + 3, buf);
        CP_COMMIT();
        buf = (buf == 2) ? 0 : buf + 1;
    }

    // ---- epilogue ----
    const float inv0 = 1.f / l_r0, inv1 = 1.f / l_r1;
#pragma unroll
    for (int nt = 0; nt < 8; nt++) {
#pragma unroll
        for (int hh = 0; hh < 2; hh++) {
            const int rloc = m0 + hh * 8 + (lane >> 2);
            const float inv = hh ? inv1 : inv0;
            float v0 = oacc[nt][2 * hh] * inv;
            float v1 = oacc[nt][2 * hh + 1] * inv;
            size_t base = (size_t)(qrow0 + rloc) * DMODEL + h * 64
                        + nt * 8 + (lane & 3) * 2;
            __nv_bfloat162 hp, lp;
            split2(v0, hp.x, lp.x);
            split2(v1, hp.y, lp.y);
            *(__nv_bfloat162*)(ohi + base) = hp;
            *(__nv_bfloat162*)(olo + base) = lp;
        }
    }
}

// ---------------------------------------------------------------------------
// LayerNorm (rows of 512).
// ---------------------------------------------------------------------------
__global__ void __launch_bounds__(128)
ln_kernel(const float* __restrict__ x, const float* __restrict__ g,
          const float* __restrict__ bta, float* __restrict__ yf,
          __nv_bfloat16* __restrict__ yh, __nv_bfloat16* __restrict__ yl)
{
    __shared__ float sbuf[4];
    const int row = blockIdx.x;
    const int tid = threadIdx.x;
    const float* xr = x + (size_t)row * DMODEL;
    float4 v = *(const float4*)(xr + tid * 4);

    float s = v.x + v.y + v.z + v.w;
#pragma unroll
    for (int off = 16; off > 0; off >>= 1) s += __shfl_xor_sync(0xffffffffu, s, off);
    if ((tid & 31) == 0) sbuf[tid >> 5] = s;
    __syncthreads();
    float mean = (sbuf[0] + sbuf[1] + sbuf[2] + sbuf[3]) * (1.f / 512.f);

    float dx = v.x - mean, dy = v.y - mean, dz = v.z - mean, dw = v.w - mean;
    float s2 = dx * dx + dy * dy + dz * dz + dw * dw;
#pragma unroll
    for (int off = 16; off > 0; off >>= 1) s2 += __shfl_xor_sync(0xffffffffu, s2, off);
    __syncthreads();
    if ((tid & 31) == 0) sbuf[tid >> 5] = s2;
    __syncthreads();
    float var = (sbuf[0] + sbuf[1] + sbuf[2] + sbuf[3]) * (1.f / 512.f);
    float inv = rsqrtf(var + LN_EPS);

    float4 gg = *(const float4*)(g + tid * 4);
    float4 bb = *(const float4*)(bta + tid * 4);
    float o0 = dx * inv * gg.x + bb.x;
    float o1 = dy * inv * gg.y + bb.y;
    float o2 = dz * inv * gg.z + bb.z;
    float o3 = dw * inv * gg.w + bb.w;
    size_t base = (size_t)row * DMODEL + tid * 4;
    if (yf) {
        float4 o = {o0, o1, o2, o3};
        *(float4*)(yf + base) = o;
    }
    if (yh) {
        __nv_bfloat162 h01, h23, l01, l23;
        split2(o0, h01.x, l01.x); split2(o1, h01.y, l01.y);
        split2(o2, h23.x, l23.x); split2(o3, h23.y, l23.y);
        *(__nv_bfloat162*)(yh + base)     = h01;
        *(__nv_bfloat162*)(yh + base + 2) = h23;
        *(__nv_bfloat162*)(yl + base)     = l01;
        *(__nv_bfloat162*)(yl + base + 2) = l23;
    }
}

// ---------------------------------------------------------------------------
extern "C" void kernel_launch(void* const* d_in, const int* in_sizes, int n_in,
                              void* d_out, int out_size)
{
    const float* X     = (const float*)d_in[0];
    const float* qkv_w = (const float*)d_in[1];
    const float* qkv_b = (const float*)d_in[2];
    const float* fc_w  = (const float*)d_in[3];
    const float* fc_b  = (const float*)d_in[4];
    const float* ln1_g = (const float*)d_in[5];
    const float* ln1_b = (const float*)d_in[6];
    const float* w1    = (const float*)d_in[7];
    const float* b1    = (const float*)d_in[8];
    const float* w2    = (const float*)d_in[9];
    const float* b2    = (const float*)d_in[10];
    const float* ln2_g = (const float*)d_in[11];
    const float* ln2_b = (const float*)d_in[12];
    float* out = (float*)d_out;

    float *x, *x1, *x2;
    __nv_bfloat16 *ctx_hi, *ctx_lo, *attn_hi, *attn_lo, *x_hi, *x_lo;
    __nv_bfloat16 *xn_hi, *xn_lo, *h_hi, *h_lo;
    __nv_bfloat16 *qkvT_hi, *qkvT_lo, *fcT_hi, *fcT_lo, *w1T_hi, *w1T_lo, *w2T_hi, *w2T_lo;
    cudaGetSymbolAddress((void**)&ctx_hi,  g_ctx_hi);
    cudaGetSymbolAddress((void**)&ctx_lo,  g_ctx_lo);
    cudaGetSymbolAddress((void**)&attn_hi, g_attn_hi);
    cudaGetSymbolAddress((void**)&attn_lo, g_attn_lo);
    cudaGetSymbolAddress((void**)&x,       g_x);
    cudaGetSymbolAddress((void**)&x1,      g_x1);
    cudaGetSymbolAddress((void**)&x2,      g_x2);
    cudaGetSymbolAddress((void**)&x_hi,    g_x_hi);
    cudaGetSymbolAddress((void**)&x_lo,    g_x_lo);
    cudaGetSymbolAddress((void**)&xn_hi,   g_xn_hi);
    cudaGetSymbolAddress((void**)&xn_lo,   g_xn_lo);
    cudaGetSymbolAddress((void**)&h_hi,    g_h_hi);
    cudaGetSymbolAddress((void**)&h_lo,    g_h_lo);
    cudaGetSymbolAddress((void**)&qkvT_hi, g_qkvT_hi);
    cudaGetSymbolAddress((void**)&qkvT_lo, g_qkvT_lo);
    cudaGetSymbolAddress((void**)&fcT_hi,  g_fcT_hi);
    cudaGetSymbolAddress((void**)&fcT_lo,  g_fcT_lo);
    cudaGetSymbolAddress((void**)&w1T_hi,  g_w1T_hi);
    cudaGetSymbolAddress((void**)&w1T_lo,  g_w1T_lo);
    cudaGetSymbolAddress((void**)&w2T_hi,  g_w2T_hi);
    cudaGetSymbolAddress((void**)&w2T_lo,  g_w2T_lo);

    cudaFuncSetAttribute(attn_kernel, cudaFuncAttributeMaxDynamicSharedMemorySize,
                         ATTN_SMEM_BYTES);
    cudaFuncSetAttribute(gemm_mma<false, false, false, true>,
                         cudaFuncAttributeMaxDynamicSharedMemorySize, G_SMEM);
    cudaFuncSetAttribute(gemm_mma<false, true, true, false>,
                         cudaFuncAttributeMaxDynamicSharedMemorySize, G_SMEM);
    cudaFuncSetAttribute(gemm_mma<true, false, false, true>,
                         cudaFuncAttributeMaxDynamicSharedMemorySize, G_SMEM);

    transpose_split_l<<<dim3(CTXW / 32, DMODEL / 32, NB), dim3(32, 8)>>>(
        qkv_w, qkvT_hi, qkvT_lo, DMODEL, CTXW);
    transpose_split_l<<<dim3(DMODEL / 32, DMODEL / 32, NB), dim3(32, 8)>>>(
        fc_w, fcT_hi, fcT_lo, DMODEL, DMODEL);
    transpose_split_l<<<dim3(DHID / 32, DMODEL / 32, NB), dim3(32, 8)>>>(
        w1, w1T_hi, w1T_lo, DMODEL, DHID);
    transpose_split_l<<<dim3(DMODEL / 32, DHID / 32, NB), dim3(32, 8)>>>(
        w2, w2T_hi, w2T_lo, DHID, DMODEL);

    split_hilo<<<(ROWS * DMODEL + 255) / 256, 256>>>(X, x_hi, x_lo, ROWS * DMODEL);

    const float* xcur_f = X;

    for (int i = 0; i < NB; i++) {
        const size_t oq = (size_t)i * CTXW * DMODEL;
        const size_t of = (size_t)i * DMODEL * DMODEL;
        const size_t o1 = (size_t)i * DHID * DMODEL;
        const size_t o2 = (size_t)i * DMODEL * DHID;

        // 1) ctx = x @ qkv_w + qkv_b -> bf16 hi/lo
        gemm_mma<false, false, false, true>
            <<<dim3(CTXW / 128, ROWS / 128), 256, G_SMEM>>>(
            x_hi, x_lo, qkvT_hi + oq, qkvT_lo + oq, qkv_b + (size_t)i * CTXW,
            nullptr, nullptr, ctx_hi, ctx_lo, CTXW, DMODEL);

        // 2) attention -> bf16 hi/lo
        attn_kernel<<<dim3(SEQ / 128, BATCH * NH), 256, ATTN_SMEM_BYTES>>>(
            ctx_hi, ctx_lo, attn_hi, attn_lo);

        // 3) x1 = attn @ fc_w + fc_b + xcur (fp32)
        gemm_mma<false, true, true, false>
            <<<dim3(DMODEL / 128, ROWS / 128), 256, G_SMEM>>>(
            attn_hi, attn_lo, fcT_hi + of, fcT_lo + of, fc_b + (size_t)i * DMODEL,
            xcur_f, x1, nullptr, nullptr, DMODEL, DMODEL);

        // 4) xn = LN1(x1) -> hi/lo only
        ln_kernel<<<ROWS, 128>>>(x1, ln1_g + (size_t)i * DMODEL,
                                 ln1_b + (size_t)i * DMODEL, nullptr, xn_hi, xn_lo);

        // 5) h = relu(xn @ w1 + b1) -> hi/lo
        gemm_mma<true, false, false, true>
            <<<dim3(DHID / 128, ROWS / 128), 256, G_SMEM>>>(
            xn_hi, xn_lo, w1T_hi + o1, w1T_lo + o1, b1 + (size_t)i * DHID,
            nullptr, nullptr, h_hi, h_lo, DHID, DMODEL);

        // 6) x2 = h @ w2 + b2 + x1 (fp32)
        gemm_mma<false, true, true, false>
            <<<dim3(DMODEL / 128, ROWS / 128), 256, G_SMEM>>>(
            h_hi, h_lo, w2T_hi + o2, w2T_lo + o2, b2 + (size_t)i * DMODEL,
            x1, x2, nullptr, nullptr, DMODEL, DHID);

        // 7) carry = LN2(x2)
        float* dstf = (i == NB - 1) ? out : x;
        __nv_bfloat16* nh = (i == NB - 1) ? nullptr : x_hi;
        __nv_bfloat16* nl = (i == NB - 1) ? nullptr : x_lo;
        ln_kernel<<<ROWS, 128>>>(x2, ln2_g + (size_t)i * DMODEL,
                                 ln2_b + (size_t)i * DMODEL, dstf, nh, nl);
        xcur_f = dstf;
    }
}

// round 11
// speedup vs baseline: 4.4347x; 1.4232x over previous
#include <cuda_runtime.h>
#include <cuda_fp16.h>
#include <cstdint>
#include <cstddef>

// ---------------------------------------------------------------------------
// Encoder: 12 x (QKV -> MHA -> proj+res -> LN1 -> MLP(relu) -> +res -> LN2)
// B=2, S=2048, D=512, H=8, DH=64, DHID=1024, fp32 in/out.
// R11 = R10 resubmit (broker flake): fp16 hi/lo, 2-term MMA (Afull x Bhi).
// B-side lo eliminated: weights hi-only, attention K/V hi-only. -33% MMAs.
// ---------------------------------------------------------------------------

#define NB     12
#define DMODEL 512
#define NH     8
#define DHEAD  64
#define DHID   1024
#define BATCH  2
#define SEQ    2048
#define ROWS   (BATCH * SEQ)     // 4096
#define CTXW   (3 * DMODEL)      // 1536
#define LN_EPS 1e-5f
#define ATTN_SCALE 0.044194173824159216f  // 1/sqrt(512)

// ----------------------------- PTX helpers ---------------------------------
__device__ __forceinline__ uint32_t smem_u32(const void* p) {
    uint32_t a;
    asm("{ .reg .u64 t; cvta.to.shared.u64 t, %1; cvt.u32.u64 %0, t; }"
        : "=r"(a) : "l"(p));
    return a;
}
__device__ __forceinline__ void ldsm_x4(uint32_t* r, uint32_t a) {
    asm volatile("ldmatrix.sync.aligned.m8n8.x4.shared.b16 {%0,%1,%2,%3}, [%4];"
        : "=r"(r[0]), "=r"(r[1]), "=r"(r[2]), "=r"(r[3]) : "r"(a));
}
__device__ __forceinline__ void ldsm_x4t(uint32_t* r, uint32_t a) {
    asm volatile("ldmatrix.sync.aligned.m8n8.x4.trans.shared.b16 {%0,%1,%2,%3}, [%4];"
        : "=r"(r[0]), "=r"(r[1]), "=r"(r[2]), "=r"(r[3]) : "r"(a));
}
__device__ __forceinline__ void mma_f16(float* c, const uint32_t* a, const uint32_t* b) {
    asm volatile("mma.sync.aligned.m16n8k16.row.col.f32.f16.f16.f32 "
        "{%0,%1,%2,%3}, {%4,%5,%6,%7}, {%8,%9}, {%0,%1,%2,%3};"
        : "+f"(c[0]), "+f"(c[1]), "+f"(c[2]), "+f"(c[3])
        : "r"(a[0]), "r"(a[1]), "r"(a[2]), "r"(a[3]), "r"(b[0]), "r"(b[1]));
}
__device__ __forceinline__ void split2(float v, __half& h, __half& l) {
    h = __float2half(v);
    l = __float2half(v - __half2float(h));
}
__device__ __forceinline__ void cp16(uint32_t dst, const void* src) {
    asm volatile("cp.async.cg.shared.global [%0], [%1], 16;"
                 :: "r"(dst), "l"(src) : "memory");
}
#define CP_COMMIT() asm volatile("cp.async.commit_group;" ::: "memory")
#define CP_WAIT1()  asm volatile("cp.async.wait_group 1;"  ::: "memory")
#define CP_WAIT2()  asm volatile("cp.async.wait_group 2;"  ::: "memory")

// ------------------------- scratch (no allocation) -------------------------
__device__ __half g_ctx_hi[ROWS * CTXW];
__device__ __half g_ctx_lo[ROWS * CTXW];
__device__ __half g_attn_hi[ROWS * DMODEL];
__device__ __half g_attn_lo[ROWS * DMODEL];
__device__ float  g_x   [ROWS * DMODEL];
__device__ __half g_x_hi[ROWS * DMODEL];
__device__ __half g_x_lo[ROWS * DMODEL];
__device__ float  g_x1  [ROWS * DMODEL];
__device__ __half g_xn_hi[ROWS * DMODEL];
__device__ __half g_xn_lo[ROWS * DMODEL];
__device__ __half g_h_hi[ROWS * DHID];
__device__ __half g_h_lo[ROWS * DHID];
__device__ float  g_x2  [ROWS * DMODEL];
// transposed weights, hi ONLY (2-term scheme), all layers
__device__ __half g_qkvT_hi[NB * CTXW * DMODEL];
__device__ __half g_fcT_hi [NB * DMODEL * DMODEL];
__device__ __half g_w1T_hi [NB * DHID * DMODEL];
__device__ __half g_w2T_hi [NB * DMODEL * DHID];

// ---------------------------------------------------------------------------
// mma GEMM, cp.async 2-stage pipeline, BK=64, fp16 2-term.
// C[M,N] = A[M,K] @ W[K,N] (+bias)(+res)(relu); A hi/lo [M][K], W^T hi [N][K].
// 128x128 tile, 8 warps (warp tile 32x64). Stage: Ah|Al|Bh, 18432B each.
// ---------------------------------------------------------------------------
#define GS2   72                    // smem row stride in halves (144B)
#define G_MAT 18432                 // one matrix: 128 rows x 144B
#define G_STG (3 * G_MAT)           // 55296
#define G_SMEM (2 * G_STG)          // 110592

template <bool RELU, bool RES, bool WF32, bool WHILO>
__global__ void __launch_bounds__(256)
gemm_mma(const __half* __restrict__ Ahi, const __half* __restrict__ Alo,
         const __half* __restrict__ Bhi,
         const float* __restrict__ bias, const float* __restrict__ res,
         float* __restrict__ Cf, __half* __restrict__ Chi,
         __half* __restrict__ Clo, int N, int K)
{
    extern __shared__ char dsm[];
    const uint32_t sb = smem_u32(dsm);

    const int tid  = threadIdx.x;
    const int lane = tid & 31, wid = tid >> 5;
    const int g = lane >> 3, rq = lane & 7;
    const int brow = blockIdx.y * 128, bcol = blockIdx.x * 128;
    const int m0 = (wid & 3) * 32, n0 = (wid >> 2) * 64;

    float acc[2][8][4];
#pragma unroll
    for (int mt = 0; mt < 2; mt++)
#pragma unroll
        for (int nt = 0; nt < 8; nt++)
#pragma unroll
            for (int e = 0; e < 4; e++) acc[mt][nt][e] = 0.f;

    const int NT = K >> 6;

    auto issue = [&](int c, int buf) {
        const uint32_t st = sb + buf * G_STG;
#pragma unroll
        for (int t = 0; t < 4; t++) {
            const int idx = tid + t * 256;
            const int row = idx >> 3, seg = (idx & 7) * 8;
            const uint32_t so = (uint32_t)(row * GS2 + seg) * 2;
            const size_t ga = (size_t)(brow + row) * K + c * 64 + seg;
            const size_t gb = (size_t)(bcol + row) * K + c * 64 + seg;
            cp16(st + so,             Ahi + ga);
            cp16(st + G_MAT + so,     Alo + ga);
            cp16(st + 2 * G_MAT + so, Bhi + gb);
        }
    };

    issue(0, 0); CP_COMMIT();
    issue(1, 1); CP_COMMIT();

    for (int c = 0; c < NT; c++) {
        CP_WAIT1();
        __syncthreads();
        const uint32_t st = sb + (c & 1) * G_STG;
        const uint32_t bAh = st, bAl = st + G_MAT, bBh = st + 2 * G_MAT;
#pragma unroll
        for (int ks = 0; ks < 4; ks++) {
            const int k0 = ks * 16;
            uint32_t ah[2][4], al[2][4];
#pragma unroll
            for (int mt = 0; mt < 2; mt++) {
                uint32_t off = (uint32_t)(m0 + mt * 16 + (g & 1) * 8 + rq) * (GS2 * 2)
                             + (k0 + (g >> 1) * 8) * 2;
                ldsm_x4(ah[mt], bAh + off);
                ldsm_x4(al[mt], bAl + off);
            }
            uint32_t bh[8][2];
#pragma unroll
            for (int np = 0; np < 4; np++) {
                uint32_t off = (uint32_t)(n0 + np * 16 + (g >> 1) * 8 + rq) * (GS2 * 2)
                             + (k0 + (g & 1) * 8) * 2;
                uint32_t tmp[4];
                ldsm_x4(tmp, bBh + off);
                bh[2 * np][0] = tmp[0]; bh[2 * np][1] = tmp[1];
                bh[2 * np + 1][0] = tmp[2]; bh[2 * np + 1][1] = tmp[3];
            }
#pragma unroll
            for (int mt = 0; mt < 2; mt++)
#pragma unroll
                for (int nt = 0; nt < 8; nt++) {
                    mma_f16(acc[mt][nt], ah[mt], bh[nt]);
                    mma_f16(acc[mt][nt], al[mt], bh[nt]);
                }
        }
        __syncthreads();
        if (c + 2 < NT) issue(c + 2, c & 1);
        CP_COMMIT();
    }

#pragma unroll
    for (int mt = 0; mt < 2; mt++)
#pragma unroll
        for (int nt = 0; nt < 8; nt++) {
            const int row0 = brow + m0 + mt * 16 + (lane >> 2);
            const int col  = bcol + n0 + nt * 8 + (lane & 3) * 2;
            float2 bv = *(const float2*)(bias + col);
#pragma unroll
            for (int hh = 0; hh < 2; hh++) {
                const int row = row0 + hh * 8;
                float v0 = acc[mt][nt][2 * hh]     + bv.x;
                float v1 = acc[mt][nt][2 * hh + 1] + bv.y;
                if (RES) {
                    float2 rv = *(const float2*)(res + (size_t)row * N + col);
                    v0 += rv.x; v1 += rv.y;
                }
                if (RELU) { v0 = fmaxf(v0, 0.f); v1 = fmaxf(v1, 0.f); }
                if (WF32) {
                    float2 o = {v0, v1};
                    *(float2*)(Cf + (size_t)row * N + col) = o;
                }
                if (WHILO) {
                    __half2 hp, lp;
                    split2(v0, hp.x, lp.x);
                    split2(v1, hp.y, lp.y);
                    *(__half2*)(Chi + (size_t)row * N + col) = hp;
                    *(__half2*)(Clo + (size_t)row * N + col) = lp;
                }
            }
        }
}

// ---------------------------------------------------------------------------
// Weight transpose (hi only) for ALL layers (blockIdx.z = layer).
// in[z][K][N] fp32 -> out_hi [z][N][K] fp16
// ---------------------------------------------------------------------------
__global__ void __launch_bounds__(256)
transpose_split_l(const float* __restrict__ in, __half* __restrict__ oh,
                  int K, int N)
{
    __shared__ float t[32][33];
    const size_t zoff = (size_t)blockIdx.z * K * N;
    const float* src = in + zoff;
    const int n0 = blockIdx.x * 32, k0 = blockIdx.y * 32;
    const int tx = threadIdx.x, ty = threadIdx.y;   // 32 x 8
#pragma unroll
    for (int i = 0; i < 32; i += 8)
        t[ty + i][tx] = src[(size_t)(k0 + ty + i) * N + n0 + tx];
    __syncthreads();
#pragma unroll
    for (int i = 0; i < 32; i += 8) {
        float v = t[tx][ty + i];
        size_t o = zoff + (size_t)(n0 + ty + i) * K + k0 + tx;
        oh[o] = __float2half(v);
    }
}

__global__ void __launch_bounds__(256)
split_hilo(const float* __restrict__ x, __half* __restrict__ h,
           __half* __restrict__ l, int n)
{
    int i = blockIdx.x * 256 + threadIdx.x;
    if (i < n) {
        __half hv, lv;
        split2(x[i], hv, lv);
        h[i] = hv; l[i] = lv;
    }
}

// ---------------------------------------------------------------------------
// Attention, register-resident flash, cp.async 3-stage KV pipeline.
// fp16 2-term: Q full (hi+lo regs), K/V hi-only in smem (stage halved).
// CTA = 128 q-rows x one (b,h); warp w owns q rows [w*16,w*16+16) x all 64 keys.
// ---------------------------------------------------------------------------
#define AST 72
#define A_KVB 9216                  // one K/V matrix (64 x 144B)
#define A_STG (2 * A_KVB)           // Kh + Vh = 18432
#define ATTN_SMEM_BYTES (3 * A_STG) // 55296

__global__ void __launch_bounds__(256, 2)
attn_kernel(const __half* __restrict__ cxh, const __half* __restrict__ cxl,
            __half* __restrict__ ohi, __half* __restrict__ olo)
{
    extern __shared__ char smc[];
    const uint32_t sb = smem_u32(smc);

    const int tid  = threadIdx.x;
    const int lane = tid & 31, wid = tid >> 5;
    const int g = lane >> 3, rq = lane & 7;
    const int b = blockIdx.y >> 3, h = blockIdx.y & 7;
    const int qrow0 = b * SEQ + blockIdx.x * 128;
    const int krowb = b * SEQ;
    const int qc = h * 192, kc = qc + 64, vc = qc + 128;

    const int m0 = wid * 16;
    const int lrow = tid >> 3, lseg = (tid & 7) * 8;   // KV loader

    auto issueKV = [&](int kt, int buf) {
        const int krow0 = krowb + kt * 64;
        const uint32_t st = sb + buf * A_STG;
#pragma unroll
        for (int t = 0; t < 2; t++) {
            const int row = lrow + t * 32;
            const uint32_t so = (uint32_t)(row * AST + lseg) * 2;
            const size_t gk = (size_t)(krow0 + row) * CTXW + kc + lseg;
            const size_t gv = (size_t)(krow0 + row) * CTXW + vc + lseg;
            cp16(st + so,         cxh + gk);
            cp16(st + A_KVB + so, cxh + gv);
        }
    };

    issueKV(0, 0); CP_COMMIT();
    issueKV(1, 1); CP_COMMIT();
    issueKV(2, 2); CP_COMMIT();

    // ---- Q fragments directly from gmem (canonical m16n8k16 A layout) ----
    uint32_t qf_h[4][4], qf_l[4][4];
    {
        const size_t r0 = (size_t)(qrow0 + m0 + (lane >> 2)) * CTXW;
        const size_t r1 = r0 + (size_t)8 * CTXW;
        const int c0 = qc + (lane & 3) * 2;
#pragma unroll
        for (int ks = 0; ks < 4; ks++) {
            const int c = c0 + ks * 16;
            qf_h[ks][0] = *(const uint32_t*)(cxh + r0 + c);
            qf_h[ks][1] = *(const uint32_t*)(cxh + r1 + c);
            qf_h[ks][2] = *(const uint32_t*)(cxh + r0 + c + 8);
            qf_h[ks][3] = *(const uint32_t*)(cxh + r1 + c + 8);
            qf_l[ks][0] = *(const uint32_t*)(cxl + r0 + c);
            qf_l[ks][1] = *(const uint32_t*)(cxl + r1 + c);
            qf_l[ks][2] = *(const uint32_t*)(cxl + r0 + c + 8);
            qf_l[ks][3] = *(const uint32_t*)(cxl + r1 + c + 8);
        }
    }

    float m_r0 = -1e30f, m_r1 = -1e30f, l_r0 = 0.f, l_r1 = 0.f;
    float oacc[8][4];
#pragma unroll
    for (int nt = 0; nt < 8; nt++)
#pragma unroll
        for (int e = 0; e < 4; e++) oacc[nt][e] = 0.f;

    int buf = 0;
    for (int kt = 0; kt < 32; kt++) {
        CP_WAIT2();
        __syncthreads();
        const uint32_t st = sb + buf * A_STG;
        const uint32_t bKh = st, bVh = st + A_KVB;

        // ---- S = Q @ K^T (2-term: qh.kh + ql.kh) ----
        float sacc[8][4];
#pragma unroll
        for (int nt = 0; nt < 8; nt++)
#pragma unroll
            for (int e = 0; e < 4; e++) sacc[nt][e] = 0.f;
#pragma unroll
        for (int ks = 0; ks < 4; ks++) {
#pragma unroll
            for (int np = 0; np < 4; np++) {
                uint32_t offB = (uint32_t)(np * 16 + (g >> 1) * 8 + rq) * (AST * 2)
                              + (ks * 16 + (g & 1) * 8) * 2;
                uint32_t th[4];
                ldsm_x4(th, bKh + offB);
                mma_f16(sacc[2 * np],     qf_h[ks], th);
                mma_f16(sacc[2 * np],     qf_l[ks], th);
                mma_f16(sacc[2 * np + 1], qf_h[ks], th + 2);
                mma_f16(sacc[2 * np + 1], qf_l[ks], th + 2);
            }
        }
#pragma unroll
        for (int nt = 0; nt < 8; nt++)
#pragma unroll
            for (int e = 0; e < 4; e++) sacc[nt][e] *= ATTN_SCALE;

        // ---- register softmax (rows r0 = lane>>2, r1 = r0+8) ----
        float mx0 = -1e30f, mx1 = -1e30f;
#pragma unroll
        for (int nt = 0; nt < 8; nt++) {
            mx0 = fmaxf(mx0, fmaxf(sacc[nt][0], sacc[nt][1]));
            mx1 = fmaxf(mx1, fmaxf(sacc[nt][2], sacc[nt][3]));
        }
        mx0 = fmaxf(mx0, __shfl_xor_sync(0xffffffffu, mx0, 1));
        mx0 = fmaxf(mx0, __shfl_xor_sync(0xffffffffu, mx0, 2));
        mx1 = fmaxf(mx1, __shfl_xor_sync(0xffffffffu, mx1, 1));
        mx1 = fmaxf(mx1, __shfl_xor_sync(0xffffffffu, mx1, 2));
        const float mn0 = fmaxf(m_r0, mx0), mn1 = fmaxf(m_r1, mx1);
        const float cf0 = __expf(m_r0 - mn0), cf1 = __expf(m_r1 - mn1);
        float sum0 = 0.f, sum1 = 0.f;
#pragma unroll
        for (int nt = 0; nt < 8; nt++) {
            sacc[nt][0] = __expf(sacc[nt][0] - mn0);
            sacc[nt][1] = __expf(sacc[nt][1] - mn0);
            sacc[nt][2] = __expf(sacc[nt][2] - mn1);
            sacc[nt][3] = __expf(sacc[nt][3] - mn1);
            sum0 += sacc[nt][0] + sacc[nt][1];
            sum1 += sacc[nt][2] + sacc[nt][3];
        }
        sum0 += __shfl_xor_sync(0xffffffffu, sum0, 1);
        sum0 += __shfl_xor_sync(0xffffffffu, sum0, 2);
        sum1 += __shfl_xor_sync(0xffffffffu, sum1, 1);
        sum1 += __shfl_xor_sync(0xffffffffu, sum1, 2);
        l_r0 = l_r0 * cf0 + sum0;  m_r0 = mn0;
        l_r1 = l_r1 * cf1 + sum1;  m_r1 = mn1;

#pragma unroll
        for (int nt = 0; nt < 8; nt++) {
            oacc[nt][0] *= cf0; oacc[nt][1] *= cf0;
            oacc[nt][2] *= cf1; oacc[nt][3] *= cf1;
        }

        // ---- O += P @ V (2-term: ph.vh + pl.vh; V hi only) ----
#pragma unroll
        for (int ks = 0; ks < 4; ks++) {
            uint32_t ap_h[4], ap_l[4];
            {
                __half2 h0, l0;
                split2(sacc[2 * ks][0], h0.x, l0.x);
                split2(sacc[2 * ks][1], h0.y, l0.y);
                ap_h[0] = *(uint32_t*)&h0; ap_l[0] = *(uint32_t*)&l0;
                split2(sacc[2 * ks][2], h0.x, l0.x);
                split2(sacc[2 * ks][3], h0.y, l0.y);
                ap_h[1] = *(uint32_t*)&h0; ap_l[1] = *(uint32_t*)&l0;
                split2(sacc[2 * ks + 1][0], h0.x, l0.x);
                split2(sacc[2 * ks + 1][1], h0.y, l0.y);
                ap_h[2] = *(uint32_t*)&h0; ap_l[2] = *(uint32_t*)&l0;
                split2(sacc[2 * ks + 1][2], h0.x, l0.x);
                split2(sacc[2 * ks + 1][3], h0.y, l0.y);
                ap_h[3] = *(uint32_t*)&h0; ap_l[3] = *(uint32_t*)&l0;
            }
            const uint32_t rowv = (uint32_t)(ks * 16 + (lane & 15)) * (AST * 2)
                                + ((lane >> 4) << 4);
#pragma unroll
            for (int ntp = 0; ntp < 4; ntp++) {
                uint32_t vh[4];
                const uint32_t offB = rowv + ntp * 32;
                ldsm_x4t(vh, bVh + offB);
                mma_f16(oacc[2 * ntp],     ap_h, vh);
                mma_f16(oacc[2 * ntp],     ap_l, vh);
                mma_f16(oacc[2 * ntp + 1], ap_h, vh + 2);
                mma_f16(oacc[2 * ntp + 1], ap_l, vh + 2);
            }
        }
        __syncthreads();
        if (kt + 3 < 32) issueKV(kt + 3, buf);
        CP_COMMIT();
        buf = (buf == 2) ? 0 : buf + 1;
    }

    // ---- epilogue ----
    const float inv0 = 1.f / l_r0, inv1 = 1.f / l_r1;
#pragma unroll
    for (int nt = 0; nt < 8; nt++) {
#pragma unroll
        for (int hh = 0; hh < 2; hh++) {
            const int rloc = m0 + hh * 8 + (lane >> 2);
            const float inv = hh ? inv1 : inv0;
            float v0 = oacc[nt][2 * hh] * inv;
            float v1 = oacc[nt][2 * hh + 1] * inv;
            size_t base = (size_t)(qrow0 + rloc) * DMODEL + h * 64
                        + nt * 8 + (lane & 3) * 2;
            __half2 hp, lp;
            split2(v0, hp.x, lp.x);
            split2(v1, hp.y, lp.y);
            *(__half2*)(ohi + base) = hp;
            *(__half2*)(olo + base) = lp;
        }
    }
}

// ---------------------------------------------------------------------------
// LayerNorm (rows of 512).
// ---------------------------------------------------------------------------
__global__ void __launch_bounds__(128)
ln_kernel(const float* __restrict__ x, const float* __restrict__ g,
          const float* __restrict__ bta, float* __restrict__ yf,
          __half* __restrict__ yh, __half* __restrict__ yl)
{
    __shared__ float sbuf[4];
    const int row = blockIdx.x;
    const int tid = threadIdx.x;
    const float* xr = x + (size_t)row * DMODEL;
    float4 v = *(const float4*)(xr + tid * 4);

    float s = v.x + v.y + v.z + v.w;
#pragma unroll
    for (int off = 16; off > 0; off >>= 1) s += __shfl_xor_sync(0xffffffffu, s, off);
    if ((tid & 31) == 0) sbuf[tid >> 5] = s;
    __syncthreads();
    float mean = (sbuf[0] + sbuf[1] + sbuf[2] + sbuf[3]) * (1.f / 512.f);

    float dx = v.x - mean, dy = v.y - mean, dz = v.z - mean, dw = v.w - mean;
    float s2 = dx * dx + dy * dy + dz * dz + dw * dw;
#pragma unroll
    for (int off = 16; off > 0; off >>= 1) s2 += __shfl_xor_sync(0xffffffffu, s2, off);
    __syncthreads();
    if ((tid & 31) == 0) sbuf[tid >> 5] = s2;
    __syncthreads();
    float var = (sbuf[0] + sbuf[1] + sbuf[2] + sbuf[3]) * (1.f / 512.f);
    float inv = rsqrtf(var + LN_EPS);

    float4 gg = *(const float4*)(g + tid * 4);
    float4 bb = *(const float4*)(bta + tid * 4);
    float o0 = dx * inv * gg.x + bb.x;
    float o1 = dy * inv * gg.y + bb.y;
    float o2 = dz * inv * gg.z + bb.z;
    float o3 = dw * inv * gg.w + bb.w;
    size_t base = (size_t)row * DMODEL + tid * 4;
    if (yf) {
        float4 o = {o0, o1, o2, o3};
        *(float4*)(yf + base) = o;
    }
    if (yh) {
        __half2 h01, h23, l01, l23;
        split2(o0, h01.x, l01.x); split2(o1, h01.y, l01.y);
        split2(o2, h23.x, l23.x); split2(o3, h23.y, l23.y);
        *(__half2*)(yh + base)     = h01;
        *(__half2*)(yh + base + 2) = h23;
        *(__half2*)(yl + base)     = l01;
        *(__half2*)(yl + base + 2) = l23;
    }
}

// ---------------------------------------------------------------------------
extern "C" void kernel_launch(void* const* d_in, const int* in_sizes, int n_in,
                              void* d_out, int out_size)
{
    const float* X     = (const float*)d_in[0];
    const float* qkv_w = (const float*)d_in[1];
    const float* qkv_b = (const float*)d_in[2];
    const float* fc_w  = (const float*)d_in[3];
    const float* fc_b  = (const float*)d_in[4];
    const float* ln1_g = (const float*)d_in[5];
    const float* ln1_b = (const float*)d_in[6];
    const float* w1    = (const float*)d_in[7];
    const float* b1    = (const float*)d_in[8];
    const float* w2    = (const float*)d_in[9];
    const float* b2    = (const float*)d_in[10];
    const float* ln2_g = (const float*)d_in[11];
    const float* ln2_b = (const float*)d_in[12];
    float* out = (float*)d_out;

    float *x, *x1, *x2;
    __half *ctx_hi, *ctx_lo, *attn_hi, *attn_lo, *x_hi, *x_lo;
    __half *xn_hi, *xn_lo, *h_hi, *h_lo;
    __half *qkvT_hi, *fcT_hi, *w1T_hi, *w2T_hi;
    cudaGetSymbolAddress((void**)&ctx_hi,  g_ctx_hi);
    cudaGetSymbolAddress((void**)&ctx_lo,  g_ctx_lo);
    cudaGetSymbolAddress((void**)&attn_hi, g_attn_hi);
    cudaGetSymbolAddress((void**)&attn_lo, g_attn_lo);
    cudaGetSymbolAddress((void**)&x,       g_x);
    cudaGetSymbolAddress((void**)&x1,      g_x1);
    cudaGetSymbolAddress((void**)&x2,      g_x2);
    cudaGetSymbolAddress((void**)&x_hi,    g_x_hi);
    cudaGetSymbolAddress((void**)&x_lo,    g_x_lo);
    cudaGetSymbolAddress((void**)&xn_hi,   g_xn_hi);
    cudaGetSymbolAddress((void**)&xn_lo,   g_xn_lo);
    cudaGetSymbolAddress((void**)&h_hi,    g_h_hi);
    cudaGetSymbolAddress((void**)&h_lo,    g_h_lo);
    cudaGetSymbolAddress((void**)&qkvT_hi, g_qkvT_hi);
    cudaGetSymbolAddress((void**)&fcT_hi,  g_fcT_hi);
    cudaGetSymbolAddress((void**)&w1T_hi,  g_w1T_hi);
    cudaGetSymbolAddress((void**)&w2T_hi,  g_w2T_hi);

    cudaFuncSetAttribute(attn_kernel, cudaFuncAttributeMaxDynamicSharedMemorySize,
                         ATTN_SMEM_BYTES);
    cudaFuncSetAttribute(gemm_mma<false, false, false, true>,
                         cudaFuncAttributeMaxDynamicSharedMemorySize, G_SMEM);
    cudaFuncSetAttribute(gemm_mma<false, true, true, false>,
                         cudaFuncAttributeMaxDynamicSharedMemorySize, G_SMEM);
    cudaFuncSetAttribute(gemm_mma<true, false, false, true>,
                         cudaFuncAttributeMaxDynamicSharedMemorySize, G_SMEM);

    transpose_split_l<<<dim3(CTXW / 32, DMODEL / 32, NB), dim3(32, 8)>>>(
        qkv_w, qkvT_hi, DMODEL, CTXW);
    transpose_split_l<<<dim3(DMODEL / 32, DMODEL / 32, NB), dim3(32, 8)>>>(
        fc_w, fcT_hi, DMODEL, DMODEL);
    transpose_split_l<<<dim3(DHID / 32, DMODEL / 32, NB), dim3(32, 8)>>>(
        w1, w1T_hi, DMODEL, DHID);
    transpose_split_l<<<dim3(DMODEL / 32, DHID / 32, NB), dim3(32, 8)>>>(
        w2, w2T_hi, DHID, DMODEL);

    split_hilo<<<(ROWS * DMODEL + 255) / 256, 256>>>(X, x_hi, x_lo, ROWS * DMODEL);

    const float* xcur_f = X;

    for (int i = 0; i < NB; i++) {
        const size_t oq = (size_t)i * CTXW * DMODEL;
        const size_t of = (size_t)i * DMODEL * DMODEL;
        const size_t o1 = (size_t)i * DHID * DMODEL;
        const size_t o2 = (size_t)i * DMODEL * DHID;

        // 1) ctx = x @ qkv_w + qkv_b -> fp16 hi/lo
        gemm_mma<false, false, false, true>
            <<<dim3(CTXW / 128, ROWS / 128), 256, G_SMEM>>>(
            x_hi, x_lo, qkvT_hi + oq, qkv_b + (size_t)i * CTXW,
            nullptr, nullptr, ctx_hi, ctx_lo, CTXW, DMODEL);

        // 2) attention -> fp16 hi/lo
        attn_kernel<<<dim3(SEQ / 128, BATCH * NH), 256, ATTN_SMEM_BYTES>>>(
            ctx_hi, ctx_lo, attn_hi, attn_lo);

        // 3) x1 = attn @ fc_w + fc_b + xcur (fp32)
        gemm_mma<false, true, true, false>
            <<<dim3(DMODEL / 128, ROWS / 128), 256, G_SMEM>>>(
            attn_hi, attn_lo, fcT_hi + of, fc_b + (size_t)i * DMODEL,
            xcur_f, x1, nullptr, nullptr, DMODEL, DMODEL);

        // 4) xn = LN1(x1) -> hi/lo only
        ln_kernel<<<ROWS, 128>>>(x1, ln1_g + (size_t)i * DMODEL,
                                 ln1_b + (size_t)i * DMODEL, nullptr, xn_hi, xn_lo);

        // 5) h = relu(xn @ w1 + b1) -> hi/lo
        gemm_mma<true, false, false, true>
            <<<dim3(DHID / 128, ROWS / 128), 256, G_SMEM>>>(
            xn_hi, xn_lo, w1T_hi + o1, b1 + (size_t)i * DHID,
            nullptr, nullptr, h_hi, h_lo, DHID, DMODEL);

        // 6) x2 = h @ w2 + b2 + x1 (fp32)
        gemm_mma<false, true, true, false>
            <<<dim3(DMODEL / 128, ROWS / 128), 256, G_SMEM>>>(
            h_hi, h_lo, w2T_hi + o2, b2 + (size_t)i * DMODEL,
            x1, x2, nullptr, nullptr, DMODEL, DHID);

        // 7) carry = LN2(x2)
        float* dstf = (i == NB - 1) ? out : x;
        __half* nh = (i == NB - 1) ? nullptr : x_hi;
        __half* nl = (i == NB - 1) ? nullptr : x_lo;
        ln_kernel<<<ROWS, 128>>>(x2, ln2_g + (size_t)i * DMODEL,
                                 ln2_b + (size_t)i * DMODEL, dstf, nh, nl);
        xcur_f = dstf;
    }
}